// round 1
// baseline (speedup 1.0000x reference)
#include <cuda_runtime.h>
#include <cuda_bf16.h>
#include <math.h>

// Problem constants
#define BB 4
#define TT 2048
#define CC 1024
#define HH 16
#define DD 64
#define MTOK (BB * TT)          // 8192 tokens
#define N_QKV (3 * CC)          // 3072

// Scratch (allocation-free rule: __device__ globals)
__device__ float g_qkv[(size_t)MTOK * N_QKV];   // 96 MB
__device__ float g_y[(size_t)MTOK * CC];        // 32 MB

// ---------------------------------------------------------------------------
// Tiled SGEMM with bias: C[M,N] = A[M,K] @ W[K,N] + bias[N]
// BM=BN=128, BK=16, 256 threads, 8x8 per-thread microtile.
// ---------------------------------------------------------------------------
__global__ __launch_bounds__(256) void sgemm_bias_kernel(
    const float* __restrict__ A, const float* __restrict__ W,
    const float* __restrict__ bias, float* __restrict__ C,
    int M, int N, int K)
{
    __shared__ float As[16][128];   // transposed A tile: As[k][m]
    __shared__ float Bs[16][128];   // Bs[k][n]

    const int tid = threadIdx.x;
    const int bm = blockIdx.y * 128;
    const int bn = blockIdx.x * 128;
    const int tx = tid & 15;        // n direction
    const int ty = tid >> 4;        // m direction

    // A-tile load mapping: 128 rows x 4 float4; f = tid (+256)
    const int arow = tid >> 2;      // 0..63
    const int ac4  = tid & 3;       // 0..3
    // B-tile load mapping: 16 rows x 32 float4
    const int brow = tid >> 5;      // 0..7
    const int bc4  = tid & 31;      // 0..31

    float acc[8][8];
#pragma unroll
    for (int i = 0; i < 8; i++)
#pragma unroll
        for (int j = 0; j < 8; j++) acc[i][j] = 0.f;

    const float* Aptr0 = A + (size_t)(bm + arow) * K + ac4 * 4;
    const float* Aptr1 = A + (size_t)(bm + arow + 64) * K + ac4 * 4;
    const float* Wptr0 = W + (size_t)brow * N + bn + bc4 * 4;
    const float* Wptr1 = W + (size_t)(brow + 8) * N + bn + bc4 * 4;

    for (int k0 = 0; k0 < K; k0 += 16) {
        float4 a0 = *(const float4*)(Aptr0 + k0);
        float4 a1 = *(const float4*)(Aptr1 + k0);
        float4 b0 = *(const float4*)(Wptr0 + (size_t)k0 * N);
        float4 b1 = *(const float4*)(Wptr1 + (size_t)k0 * N);

        __syncthreads();   // previous iteration's smem reads complete

        As[ac4 * 4 + 0][arow] = a0.x;
        As[ac4 * 4 + 1][arow] = a0.y;
        As[ac4 * 4 + 2][arow] = a0.z;
        As[ac4 * 4 + 3][arow] = a0.w;
        As[ac4 * 4 + 0][arow + 64] = a1.x;
        As[ac4 * 4 + 1][arow + 64] = a1.y;
        As[ac4 * 4 + 2][arow + 64] = a1.z;
        As[ac4 * 4 + 3][arow + 64] = a1.w;
        *(float4*)&Bs[brow][bc4 * 4]     = b0;
        *(float4*)&Bs[brow + 8][bc4 * 4] = b1;

        __syncthreads();

#pragma unroll
        for (int kk = 0; kk < 16; kk++) {
            float ra[8], rb[8];
            *(float4*)&ra[0] = *(const float4*)&As[kk][ty * 8];
            *(float4*)&ra[4] = *(const float4*)&As[kk][ty * 8 + 4];
            *(float4*)&rb[0] = *(const float4*)&Bs[kk][tx * 8];
            *(float4*)&rb[4] = *(const float4*)&Bs[kk][tx * 8 + 4];
#pragma unroll
            for (int i = 0; i < 8; i++)
#pragma unroll
                for (int j = 0; j < 8; j++)
                    acc[i][j] = fmaf(ra[i], rb[j], acc[i][j]);
        }
    }

    // Epilogue: add bias, store
#pragma unroll
    for (int i = 0; i < 8; i++) {
        float* crow = C + (size_t)(bm + ty * 8 + i) * N + bn + tx * 8;
        const float* brow_ = bias + bn + tx * 8;
#pragma unroll
        for (int j4 = 0; j4 < 2; j4++) {
            float4 v;
            v.x = acc[i][j4 * 4 + 0] + brow_[j4 * 4 + 0];
            v.y = acc[i][j4 * 4 + 1] + brow_[j4 * 4 + 1];
            v.z = acc[i][j4 * 4 + 2] + brow_[j4 * 4 + 2];
            v.w = acc[i][j4 * 4 + 3] + brow_[j4 * 4 + 3];
            *(float4*)(crow + j4 * 4) = v;
        }
    }
}

// ---------------------------------------------------------------------------
// Flash causal attention, fp32. One block per (q_tile, head, batch).
// 64 threads, thread i owns q-row (qt*64 + i). K/V tiles 64x64 in smem.
// Scores buffered transposed S[j][i] (conflict-free writes/reads).
// ---------------------------------------------------------------------------
__global__ __launch_bounds__(64) void flash_attn_kernel(
    const float* __restrict__ qkv, float* __restrict__ y)
{
    __shared__ float Ks[64][64];
    __shared__ float Vs[64][64];
    __shared__ float Ss[64][64];   // Ss[j][i]

    const int qt = blockIdx.x;
    const int h  = blockIdx.y;
    const int b  = blockIdx.z;
    const int i  = threadIdx.x;          // q-row within tile
    const int qrow = qt * 64 + i;

    const float* Qp = qkv + ((size_t)b * TT + qrow) * N_QKV + h * DD;
    const float* Kb = qkv + (size_t)b * TT * N_QKV + CC + h * DD;
    const float* Vb = qkv + (size_t)b * TT * N_QKV + 2 * CC + h * DD;

    float q[64];
#pragma unroll
    for (int d = 0; d < 64; d += 4) {
        float4 t = *(const float4*)&Qp[d];
        q[d + 0] = t.x * 0.125f;   // 1/sqrt(64)
        q[d + 1] = t.y * 0.125f;
        q[d + 2] = t.z * 0.125f;
        q[d + 3] = t.w * 0.125f;
    }
    float o[64];
#pragma unroll
    for (int d = 0; d < 64; d++) o[d] = 0.f;
    float mval = -1e30f, l = 0.f;

    for (int kt = 0; kt <= qt; kt++) {
        __syncthreads();   // previous tile's smem consumption complete
        const float* Kt = Kb + (size_t)(kt * 64) * N_QKV;
        const float* Vt = Vb + (size_t)(kt * 64) * N_QKV;
#pragma unroll 8
        for (int r = 0; r < 64; r++) {
            Ks[r][i] = Kt[(size_t)r * N_QKV + i];
            Vs[r][i] = Vt[(size_t)r * N_QKV + i];
        }
        __syncthreads();

        const int jmax = (kt == qt) ? (i + 1) : 64;   // causal: j < jmax valid
        float tmax = -1e30f;
#pragma unroll 2
        for (int j = 0; j < 64; j++) {
            float s;
            if (j < jmax) {
                float a0 = 0.f, a1 = 0.f, a2 = 0.f, a3 = 0.f;
#pragma unroll
                for (int d = 0; d < 64; d += 4) {
                    float4 kv = *(const float4*)&Ks[j][d];
                    a0 = fmaf(q[d + 0], kv.x, a0);
                    a1 = fmaf(q[d + 1], kv.y, a1);
                    a2 = fmaf(q[d + 2], kv.z, a2);
                    a3 = fmaf(q[d + 3], kv.w, a3);
                }
                s = (a0 + a1) + (a2 + a3);
            } else {
                s = -1e30f;
            }
            Ss[j][i] = s;
            tmax = fmaxf(tmax, s);
        }

        const float mnew = fmaxf(mval, tmax);
        const float corr = __expf(mval - mnew);
        l *= corr;
#pragma unroll
        for (int d = 0; d < 64; d++) o[d] *= corr;
        mval = mnew;

#pragma unroll 1
        for (int j = 0; j < 64; j++) {
            if (j >= jmax) break;
            const float p = __expf(Ss[j][i] - mval);
            l += p;
#pragma unroll
            for (int d = 0; d < 64; d += 4) {
                float4 vv = *(const float4*)&Vs[j][d];
                o[d + 0] = fmaf(p, vv.x, o[d + 0]);
                o[d + 1] = fmaf(p, vv.y, o[d + 1]);
                o[d + 2] = fmaf(p, vv.z, o[d + 2]);
                o[d + 3] = fmaf(p, vv.w, o[d + 3]);
            }
        }
    }

    const float inv = 1.f / l;
    float* yo = y + ((size_t)b * TT + qrow) * CC + h * DD;
#pragma unroll
    for (int d = 0; d < 64; d += 4) {
        float4 v;
        v.x = o[d + 0] * inv;
        v.y = o[d + 1] * inv;
        v.z = o[d + 2] * inv;
        v.w = o[d + 3] * inv;
        *(float4*)(yo + d) = v;
    }
}

// ---------------------------------------------------------------------------
// Launch
// ---------------------------------------------------------------------------
extern "C" void kernel_launch(void* const* d_in, const int* in_sizes, int n_in,
                              void* d_out, int out_size)
{
    const float* x     = (const float*)d_in[0];
    const float* Wqkv  = (const float*)d_in[1];
    const float* bqkv  = (const float*)d_in[2];
    const float* Wproj = (const float*)d_in[3];
    const float* bproj = (const float*)d_in[4];
    float* out = (float*)d_out;

    float* qkv_ptr = nullptr;
    float* y_ptr   = nullptr;
    cudaGetSymbolAddress((void**)&qkv_ptr, g_qkv);
    cudaGetSymbolAddress((void**)&y_ptr, g_y);

    // 1) QKV = x @ Wqkv + bqkv   [8192 x 3072]
    {
        dim3 grid(N_QKV / 128, MTOK / 128);
        sgemm_bias_kernel<<<grid, 256>>>(x, Wqkv, bqkv, qkv_ptr, MTOK, N_QKV, CC);
    }
    // 2) Flash causal attention -> y [8192 x 1024]
    {
        dim3 grid(TT / 64, HH, BB);
        flash_attn_kernel<<<grid, 64>>>(qkv_ptr, y_ptr);
    }
    // 3) out = y @ Wproj + bproj   [8192 x 1024]
    {
        dim3 grid(CC / 128, MTOK / 128);
        sgemm_bias_kernel<<<grid, 256>>>(y_ptr, Wproj, bproj, out, MTOK, CC, CC);
    }
}

// round 3
// speedup vs baseline: 1.4638x; 1.4638x over previous
#include <cuda_runtime.h>
#include <cuda_bf16.h>
#include <math.h>
#include <stdint.h>

// Problem constants
#define BB 4
#define TT 2048
#define CC 1024
#define HH 16
#define DD 64
#define MTOK (BB * TT)          // 8192 tokens
#define N_QKV (3 * CC)          // 3072
#define NKC 16                  // K chunks: 1024 / 64

// ---------------------------------------------------------------------------
// Scratch (allocation-free rule: __device__ globals)
// ---------------------------------------------------------------------------
__device__ float g_qkv[(size_t)MTOK * N_QKV];            // 96 MB fp32
__device__ float g_y[(size_t)MTOK * CC];                 // 32 MB fp32
__device__ __nv_bfloat16 g_xh[(size_t)MTOK * CC];
__device__ __nv_bfloat16 g_xl[(size_t)MTOK * CC];
__device__ __nv_bfloat16 g_yh[(size_t)MTOK * CC];
__device__ __nv_bfloat16 g_yl[(size_t)MTOK * CC];
__device__ __nv_bfloat16 g_wqkvh[(size_t)N_QKV * CC];
__device__ __nv_bfloat16 g_wqkvl[(size_t)N_QKV * CC];
__device__ __nv_bfloat16 g_wprojh[(size_t)CC * CC];
__device__ __nv_bfloat16 g_wprojl[(size_t)CC * CC];

// ---------------------------------------------------------------------------
// PTX helpers (base sm_103 target — NO tcgen05, NO 'a'-suffix features)
// ---------------------------------------------------------------------------
__device__ __forceinline__ uint32_t smem_u32(const void* p) {
    uint32_t a;
    asm("{ .reg .u64 t; cvta.to.shared.u64 t, %1; cvt.u32.u64 %0, t; }" : "=r"(a) : "l"(p));
    return a;
}

#define SWZ128(off) ((off) ^ (((off) >> 3) & 0x70))

#define MBAR_INIT(addr, cnt) \
    asm volatile("mbarrier.init.shared.b64 [%0], %1;" :: "r"(addr), "r"(cnt) : "memory")

#define MBAR_EXPECT_TX(addr, bytes) \
    asm volatile("mbarrier.arrive.expect_tx.shared.b64 _, [%0], %1;" :: "r"(addr), "r"(bytes) : "memory")

__device__ __forceinline__ void mbar_wait(uint32_t mbar, uint32_t parity) {
    uint32_t done;
    asm volatile(
        "{\n\t.reg .pred p;\n\t"
        "mbarrier.try_wait.parity.acquire.cta.shared::cta.b64 p, [%1], %2;\n\t"
        "selp.b32 %0, 1, 0, p;\n\t}"
        : "=r"(done) : "r"(mbar), "r"(parity) : "memory");
    if (!done) {
        asm volatile(
            "{\n\t.reg .pred P1;\n\t"
            "WL_%=:\n\t"
            "mbarrier.try_wait.parity.acquire.cta.shared::cta.b64 P1, [%0], %1, 0x989680;\n\t"
            "@P1 bra.uni WD_%=;\n\t"
            "bra.uni WL_%=;\n\t"
            "WD_%=:\n\t}"
            :: "r"(mbar), "r"(parity) : "memory");
    }
}

__device__ __forceinline__ void bulk_g2s(uint32_t dst, const void* src, uint32_t bytes, uint32_t mbar) {
    asm volatile(
        "cp.async.bulk.shared::cluster.global.mbarrier::complete_tx::bytes [%0], [%1], %2, [%3];"
        :: "r"(dst), "l"(src), "r"(bytes), "r"(mbar) : "memory");
}

#define FENCE_ASYNC() asm volatile("fence.proxy.async.shared::cta;" ::: "memory")

__device__ __forceinline__ void ldsm_x4(uint32_t& r0, uint32_t& r1, uint32_t& r2, uint32_t& r3,
                                        uint32_t addr) {
    asm volatile("ldmatrix.sync.aligned.m8n8.x4.shared.b16 {%0,%1,%2,%3}, [%4];"
                 : "=r"(r0), "=r"(r1), "=r"(r2), "=r"(r3) : "r"(addr));
}

__device__ __forceinline__ void mma_bf16(float* d, const uint32_t* a, const uint32_t* b) {
    asm volatile(
        "mma.sync.aligned.m16n8k16.row.col.f32.bf16.bf16.f32 "
        "{%0,%1,%2,%3}, {%4,%5,%6,%7}, {%8,%9}, {%0,%1,%2,%3};"
        : "+f"(d[0]), "+f"(d[1]), "+f"(d[2]), "+f"(d[3])
        : "r"(a[0]), "r"(a[1]), "r"(a[2]), "r"(a[3]), "r"(b[0]), "r"(b[1]));
}

// ---------------------------------------------------------------------------
// hi/lo bf16 split
// ---------------------------------------------------------------------------
__device__ __forceinline__ void split_bf16(float v, __nv_bfloat16& h, __nv_bfloat16& l) {
    h = __float2bfloat16(v);
    l = __float2bfloat16(v - __bfloat162float(h));
}

// ---------------------------------------------------------------------------
// Prep 1: split A [M,1024] fp32 -> tiled SW128-swizzled bf16 hi/lo blocks.
// Block (mt, kc) = 128 rows x 64 cols = 16 KB contiguous. grid=(16, M/128).
// ---------------------------------------------------------------------------
__global__ __launch_bounds__(256) void split_a_kernel(
    const float* __restrict__ in, __nv_bfloat16* __restrict__ oh,
    __nv_bfloat16* __restrict__ ol)
{
    const int kc = blockIdx.x;
    const int mt = blockIdx.y;
    const int t = threadIdx.x;
    const int r = t >> 1;
    const int hh = t & 1;

    const float* src = in + (size_t)(mt * 128 + r) * CC + kc * 64 + hh * 32;
    char* bh = (char*)(oh + ((size_t)mt * NKC + kc) * 8192);
    char* bl = (char*)(ol + ((size_t)mt * NKC + kc) * 8192);

#pragma unroll
    for (int j = 0; j < 4; j++) {
        float4 v0 = ((const float4*)src)[j * 2 + 0];
        float4 v1 = ((const float4*)src)[j * 2 + 1];
        __align__(16) __nv_bfloat16 h8[8], l8[8];
        split_bf16(v0.x, h8[0], l8[0]); split_bf16(v0.y, h8[1], l8[1]);
        split_bf16(v0.z, h8[2], l8[2]); split_bf16(v0.w, h8[3], l8[3]);
        split_bf16(v1.x, h8[4], l8[4]); split_bf16(v1.y, h8[5], l8[5]);
        split_bf16(v1.z, h8[6], l8[6]); split_bf16(v1.w, h8[7], l8[7]);
        uint32_t off = SWZ128((uint32_t)(r * 128 + hh * 64 + j * 16));
        *(uint4*)(bh + off) = *(const uint4*)h8;
        *(uint4*)(bl + off) = *(const uint4*)l8;
    }
}

// ---------------------------------------------------------------------------
// Prep 2: transpose + split W [1024, N] -> W^T tiled bf16 hi/lo blocks.
// Block (nt, kc) = 128 N-rows x 64 K-cols = 16 KB, SW128. grid=(16, N/128).
// ---------------------------------------------------------------------------
__global__ __launch_bounds__(256) void transpose_split_kernel(
    const float* __restrict__ W, __nv_bfloat16* __restrict__ oh,
    __nv_bfloat16* __restrict__ ol, int N)
{
    __shared__ float s[64][128];
    const int kc = blockIdx.x;
    const int nt = blockIdx.y;
    const int t = threadIdx.x;

    for (int idx = t; idx < 64 * 128; idx += 256) {
        int r = idx >> 7, n = idx & 127;
        s[r][n] = W[(size_t)(kc * 64 + r) * N + nt * 128 + n];
    }
    __syncthreads();

    const int np = t & 127;
    const int c0 = (t >> 7) * 4;
    char* bh = (char*)(oh + ((size_t)nt * NKC + kc) * 8192);
    char* bl = (char*)(ol + ((size_t)nt * NKC + kc) * 8192);

#pragma unroll
    for (int c = c0; c < c0 + 4; c++) {
        __align__(16) __nv_bfloat16 h8[8], l8[8];
#pragma unroll
        for (int j = 0; j < 8; j++) {
            split_bf16(s[c * 8 + j][np], h8[j], l8[j]);
        }
        uint32_t off = SWZ128((uint32_t)(np * 128 + c * 16));
        *(uint4*)(bh + off) = *(const uint4*)h8;
        *(uint4*)(bl + off) = *(const uint4*)l8;
    }
}

// ---------------------------------------------------------------------------
// mma.sync GEMM: C[M,N] = A @ W + bias (A, W^T pre-tiled bf16 hi/lo, SW128).
// CTA 128x128, BK=64, 256 threads (8 warps, each 64x32).
// D = Ah@Bh + Ah@Bl + Al@Bh, fp32 accum. 2-stage bulk-copy pipeline.
// ---------------------------------------------------------------------------
#define STAGE_BYTES 65536u      // Ah 16K | Al 16K | Bh 16K | Bl 16K
#define GEMM_SMEM   (1024u + 2u * STAGE_BYTES)

__global__ __launch_bounds__(256) void gemm_mma_kernel(
    const __nv_bfloat16* __restrict__ Ah_, const __nv_bfloat16* __restrict__ Al_,
    const __nv_bfloat16* __restrict__ Bh_, const __nv_bfloat16* __restrict__ Bl_,
    const float* __restrict__ bias, float* __restrict__ C, int N)
{
    extern __shared__ __align__(1024) char smem[];
    const uint32_t sbase = smem_u32(smem);
    const int tid = threadIdx.x;
    const int nt = blockIdx.x;
    const int mt = blockIdx.y;

    const uint32_t mb0 = sbase + 8;
    const uint32_t mb1 = sbase + 16;
    const uint32_t stage0 = sbase + 1024;

    if (tid == 0) { MBAR_INIT(mb0, 1); MBAR_INIT(mb1, 1); }
    __syncthreads();

    const char* pAh = (const char*)(Ah_ + (size_t)mt * NKC * 8192);
    const char* pAl = (const char*)(Al_ + (size_t)mt * NKC * 8192);
    const char* pBh = (const char*)(Bh_ + (size_t)nt * NKC * 8192);
    const char* pBl = (const char*)(Bl_ + (size_t)nt * NKC * 8192);

    if (tid == 0) {
#pragma unroll
        for (int c = 0; c < 2; c++) {
            uint32_t st = stage0 + c * STAGE_BYTES;
            uint32_t mb = c ? mb1 : mb0;
            MBAR_EXPECT_TX(mb, STAGE_BYTES);
            bulk_g2s(st + 0,     pAh + (size_t)c * 16384, 16384, mb);
            bulk_g2s(st + 16384, pAl + (size_t)c * 16384, 16384, mb);
            bulk_g2s(st + 32768, pBh + (size_t)c * 16384, 16384, mb);
            bulk_g2s(st + 49152, pBl + (size_t)c * 16384, 16384, mb);
        }
    }

    const int w = tid >> 5, l = tid & 31;
    const int mrow = (w >> 2) * 64;     // warp M offset (0 or 64)
    const int ncol = (w & 3) * 32;      // warp N offset (0,32,64,96)
    const int mat = l >> 3;             // ldmatrix matrix index 0..3
    const int rin = l & 7;              // row within 8x8

    // A ldmatrix lane geometry: mat 0: (+0 rows, k+0)  1: (+8, k+0)
    //                           mat 2: (+0, k+16B)     3: (+8, k+16B)
    const int a_row_off = rin + ((mat & 1) << 3);       // within m16 tile
    const int a_kb_off  = (mat >> 1) << 4;
    // B ldmatrix lane geometry: mat 0: (n+0, k+0) 1: (n+0, k+16B)
    //                           mat 2: (n+8, k+0) 3: (n+8, k+16B)
    const int b_row_off = rin + ((mat >> 1) << 3);      // within n16 group
    const int b_kb_off  = (mat & 1) << 4;

    float acc[4][4][4];
#pragma unroll
    for (int i = 0; i < 4; i++)
#pragma unroll
        for (int j = 0; j < 4; j++)
#pragma unroll
            for (int k = 0; k < 4; k++) acc[i][j][k] = 0.f;

    for (int c = 0; c < NKC; c++) {
        const int s = c & 1;
        mbar_wait(s ? mb1 : mb0, (uint32_t)((c >> 1) & 1));

        const uint32_t stAh = stage0 + s * STAGE_BYTES;
        const uint32_t stAl = stAh + 16384;
        const uint32_t stBh = stAh + 32768;
        const uint32_t stBl = stAh + 49152;

#pragma unroll
        for (int ks = 0; ks < 4; ks++) {
            const int kb = ks * 32;

            // --- B fragments (hi and lo), 2 n16 groups each -> 4 n8 tiles
            uint32_t bh[4][2], bl[4][2];
#pragma unroll
            for (int n16 = 0; n16 < 2; n16++) {
                int row = ncol + n16 * 16 + b_row_off;
                uint32_t off = (uint32_t)(row * 128) +
                               (uint32_t)((kb + b_kb_off) ^ ((row & 7) << 4));
                ldsm_x4(bh[n16 * 2][0], bh[n16 * 2][1],
                        bh[n16 * 2 + 1][0], bh[n16 * 2 + 1][1], stBh + off);
                ldsm_x4(bl[n16 * 2][0], bl[n16 * 2][1],
                        bl[n16 * 2 + 1][0], bl[n16 * 2 + 1][1], stBl + off);
            }

            // --- A hi: 4 m16 tiles; mma vs Bh and Bl
#pragma unroll
            for (int m16 = 0; m16 < 4; m16++) {
                int row = mrow + m16 * 16 + a_row_off;
                uint32_t off = (uint32_t)(row * 128) +
                               (uint32_t)((kb + a_kb_off) ^ ((row & 7) << 4));
                uint32_t a[4];
                ldsm_x4(a[0], a[1], a[2], a[3], stAh + off);
#pragma unroll
                for (int n8 = 0; n8 < 4; n8++) mma_bf16(acc[m16][n8], a, bh[n8]);
#pragma unroll
                for (int n8 = 0; n8 < 4; n8++) mma_bf16(acc[m16][n8], a, bl[n8]);
            }
            // --- A lo: mma vs Bh only
#pragma unroll
            for (int m16 = 0; m16 < 4; m16++) {
                int row = mrow + m16 * 16 + a_row_off;
                uint32_t off = (uint32_t)(row * 128) +
                               (uint32_t)((kb + a_kb_off) ^ ((row & 7) << 4));
                uint32_t a[4];
                ldsm_x4(a[0], a[1], a[2], a[3], stAl + off);
#pragma unroll
                for (int n8 = 0; n8 < 4; n8++) mma_bf16(acc[m16][n8], a, bh[n8]);
            }
        }

        __syncthreads();   // all warps done reading stage s

        if (tid == 0 && c + 2 < NKC) {
            FENCE_ASYNC();
            const int cn = c + 2;
            const uint32_t mb = s ? mb1 : mb0;
            const uint32_t st = stage0 + s * STAGE_BYTES;
            MBAR_EXPECT_TX(mb, STAGE_BYTES);
            bulk_g2s(st + 0,     pAh + (size_t)cn * 16384, 16384, mb);
            bulk_g2s(st + 16384, pAl + (size_t)cn * 16384, 16384, mb);
            bulk_g2s(st + 32768, pBh + (size_t)cn * 16384, 16384, mb);
            bulk_g2s(st + 49152, pBl + (size_t)cn * 16384, 16384, mb);
        }
    }

    // Epilogue: acc -> C + bias
    const int lr = l >> 2;
    const int lc = (l & 3) * 2;
#pragma unroll
    for (int m16 = 0; m16 < 4; m16++) {
        const size_t r0 = (size_t)(mt * 128 + mrow + m16 * 16 + lr);
        float* c0p = C + r0 * N;
        float* c1p = c0p + (size_t)8 * N;
#pragma unroll
        for (int n8 = 0; n8 < 4; n8++) {
            const int col = nt * 128 + ncol + n8 * 8 + lc;
            const float bx = bias[col], by = bias[col + 1];
            float2 v0 = make_float2(acc[m16][n8][0] + bx, acc[m16][n8][1] + by);
            float2 v1 = make_float2(acc[m16][n8][2] + bx, acc[m16][n8][3] + by);
            *(float2*)(c0p + col) = v0;
            *(float2*)(c1p + col) = v1;
        }
    }
}

// ---------------------------------------------------------------------------
// Flash causal attention, fp32 (unchanged from R1 — passed at rel_err 1e-6).
// ---------------------------------------------------------------------------
__global__ __launch_bounds__(64) void flash_attn_kernel(
    const float* __restrict__ qkv, float* __restrict__ y)
{
    __shared__ float Ks[64][64];
    __shared__ float Vs[64][64];
    __shared__ float Ss[64][64];

    const int qt = blockIdx.x;
    const int h  = blockIdx.y;
    const int b  = blockIdx.z;
    const int i  = threadIdx.x;
    const int qrow = qt * 64 + i;

    const float* Qp = qkv + ((size_t)b * TT + qrow) * N_QKV + h * DD;
    const float* Kb = qkv + (size_t)b * TT * N_QKV + CC + h * DD;
    const float* Vb = qkv + (size_t)b * TT * N_QKV + 2 * CC + h * DD;

    float q[64];
#pragma unroll
    for (int d = 0; d < 64; d += 4) {
        float4 t = *(const float4*)&Qp[d];
        q[d + 0] = t.x * 0.125f;
        q[d + 1] = t.y * 0.125f;
        q[d + 2] = t.z * 0.125f;
        q[d + 3] = t.w * 0.125f;
    }
    float o[64];
#pragma unroll
    for (int d = 0; d < 64; d++) o[d] = 0.f;
    float mval = -1e30f, lsum = 0.f;

    for (int kt = 0; kt <= qt; kt++) {
        __syncthreads();
        const float* Kt = Kb + (size_t)(kt * 64) * N_QKV;
        const float* Vt = Vb + (size_t)(kt * 64) * N_QKV;
#pragma unroll 8
        for (int r = 0; r < 64; r++) {
            Ks[r][i] = Kt[(size_t)r * N_QKV + i];
            Vs[r][i] = Vt[(size_t)r * N_QKV + i];
        }
        __syncthreads();

        const int jmax = (kt == qt) ? (i + 1) : 64;
        float tmax = -1e30f;
#pragma unroll 2
        for (int j = 0; j < 64; j++) {
            float s;
            if (j < jmax) {
                float a0 = 0.f, a1 = 0.f, a2 = 0.f, a3 = 0.f;
#pragma unroll
                for (int d = 0; d < 64; d += 4) {
                    float4 kv = *(const float4*)&Ks[j][d];
                    a0 = fmaf(q[d + 0], kv.x, a0);
                    a1 = fmaf(q[d + 1], kv.y, a1);
                    a2 = fmaf(q[d + 2], kv.z, a2);
                    a3 = fmaf(q[d + 3], kv.w, a3);
                }
                s = (a0 + a1) + (a2 + a3);
            } else {
                s = -1e30f;
            }
            Ss[j][i] = s;
            tmax = fmaxf(tmax, s);
        }

        const float mnew = fmaxf(mval, tmax);
        const float corr = __expf(mval - mnew);
        lsum *= corr;
#pragma unroll
        for (int d = 0; d < 64; d++) o[d] *= corr;
        mval = mnew;

#pragma unroll 1
        for (int j = 0; j < 64; j++) {
            if (j >= jmax) break;
            const float p = __expf(Ss[j][i] - mval);
            lsum += p;
#pragma unroll
            for (int d = 0; d < 64; d += 4) {
                float4 vv = *(const float4*)&Vs[j][d];
                o[d + 0] = fmaf(p, vv.x, o[d + 0]);
                o[d + 1] = fmaf(p, vv.y, o[d + 1]);
                o[d + 2] = fmaf(p, vv.z, o[d + 2]);
                o[d + 3] = fmaf(p, vv.w, o[d + 3]);
            }
        }
    }

    const float inv = 1.f / lsum;
    float* yo = y + ((size_t)b * TT + qrow) * CC + h * DD;
#pragma unroll
    for (int d = 0; d < 64; d += 4) {
        float4 v;
        v.x = o[d + 0] * inv;
        v.y = o[d + 1] * inv;
        v.z = o[d + 2] * inv;
        v.w = o[d + 3] * inv;
        *(float4*)(yo + d) = v;
    }
}

// ---------------------------------------------------------------------------
// Launch
// ---------------------------------------------------------------------------
extern "C" void kernel_launch(void* const* d_in, const int* in_sizes, int n_in,
                              void* d_out, int out_size)
{
    const float* x     = (const float*)d_in[0];
    const float* Wqkv  = (const float*)d_in[1];
    const float* bqkv  = (const float*)d_in[2];
    const float* Wproj = (const float*)d_in[3];
    const float* bproj = (const float*)d_in[4];
    float* out = (float*)d_out;

    float *qkv_ptr, *y_ptr;
    __nv_bfloat16 *xh, *xl, *yh, *yl, *wqh, *wql, *wph, *wpl;
    cudaGetSymbolAddress((void**)&qkv_ptr, g_qkv);
    cudaGetSymbolAddress((void**)&y_ptr, g_y);
    cudaGetSymbolAddress((void**)&xh, g_xh);
    cudaGetSymbolAddress((void**)&xl, g_xl);
    cudaGetSymbolAddress((void**)&yh, g_yh);
    cudaGetSymbolAddress((void**)&yl, g_yl);
    cudaGetSymbolAddress((void**)&wqh, g_wqkvh);
    cudaGetSymbolAddress((void**)&wql, g_wqkvl);
    cudaGetSymbolAddress((void**)&wph, g_wprojh);
    cudaGetSymbolAddress((void**)&wpl, g_wprojl);

    cudaFuncSetAttribute(gemm_mma_kernel,
                         cudaFuncAttributeMaxDynamicSharedMemorySize, GEMM_SMEM);

    // Prep: split/tile x, transpose/split weights
    split_a_kernel<<<dim3(NKC, MTOK / 128), 256>>>(x, xh, xl);
    transpose_split_kernel<<<dim3(NKC, N_QKV / 128), 256>>>(Wqkv, wqh, wql, N_QKV);
    transpose_split_kernel<<<dim3(NKC, CC / 128), 256>>>(Wproj, wph, wpl, CC);

    // QKV GEMM: [8192 x 3072]
    gemm_mma_kernel<<<dim3(N_QKV / 128, MTOK / 128), 256, GEMM_SMEM>>>(
        xh, xl, wqh, wql, bqkv, qkv_ptr, N_QKV);

    // Attention
    flash_attn_kernel<<<dim3(TT / 64, HH, BB), 64>>>(qkv_ptr, y_ptr);

    // Split/tile y, then proj GEMM: [8192 x 1024]
    split_a_kernel<<<dim3(NKC, MTOK / 128), 256>>>(y_ptr, yh, yl);
    gemm_mma_kernel<<<dim3(CC / 128, MTOK / 128), 256, GEMM_SMEM>>>(
        yh, yl, wph, wpl, bproj, out, CC);
}

// round 4
// speedup vs baseline: 3.3981x; 2.3215x over previous
#include <cuda_runtime.h>
#include <cuda_bf16.h>
#include <math.h>
#include <stdint.h>

// Problem constants
#define BB 4
#define TT 2048
#define CC 1024
#define HH 16
#define DD 64
#define MTOK (BB * TT)          // 8192 tokens
#define N_QKV (3 * CC)          // 3072
#define NKC 16                  // K chunks: 1024 / 64

// ---------------------------------------------------------------------------
// Scratch (allocation-free rule: __device__ globals)
// ---------------------------------------------------------------------------
__device__ float g_qkv[(size_t)MTOK * N_QKV];            // 96 MB fp32
__device__ float g_y[(size_t)MTOK * CC];                 // 32 MB fp32
__device__ __nv_bfloat16 g_xh[(size_t)MTOK * CC];
__device__ __nv_bfloat16 g_xl[(size_t)MTOK * CC];
__device__ __nv_bfloat16 g_yh[(size_t)MTOK * CC];
__device__ __nv_bfloat16 g_yl[(size_t)MTOK * CC];
__device__ __nv_bfloat16 g_wqkvh[(size_t)N_QKV * CC];
__device__ __nv_bfloat16 g_wqkvl[(size_t)N_QKV * CC];
__device__ __nv_bfloat16 g_wprojh[(size_t)CC * CC];
__device__ __nv_bfloat16 g_wprojl[(size_t)CC * CC];
// attention operand tiles (per (b,h), SW128 swizzled bf16)
__device__ __nv_bfloat16 g_qh[(size_t)BB * HH * 16 * 8192];
__device__ __nv_bfloat16 g_ql[(size_t)BB * HH * 16 * 8192];
__device__ __nv_bfloat16 g_kh[(size_t)BB * HH * 16 * 8192];
__device__ __nv_bfloat16 g_kl[(size_t)BB * HH * 16 * 8192];
__device__ __nv_bfloat16 g_vh[(size_t)BB * HH * 32 * 4096];
__device__ __nv_bfloat16 g_vl[(size_t)BB * HH * 32 * 4096];

// ---------------------------------------------------------------------------
// PTX helpers (base sm_103 target — NO tcgen05)
// ---------------------------------------------------------------------------
__device__ __forceinline__ uint32_t smem_u32(const void* p) {
    uint32_t a;
    asm("{ .reg .u64 t; cvta.to.shared.u64 t, %1; cvt.u32.u64 %0, t; }" : "=r"(a) : "l"(p));
    return a;
}

#define SWZ128(off) ((off) ^ (((off) >> 3) & 0x70))

#define MBAR_INIT(addr, cnt) \
    asm volatile("mbarrier.init.shared.b64 [%0], %1;" :: "r"(addr), "r"(cnt) : "memory")

#define MBAR_EXPECT_TX(addr, bytes) \
    asm volatile("mbarrier.arrive.expect_tx.shared.b64 _, [%0], %1;" :: "r"(addr), "r"(bytes) : "memory")

__device__ __forceinline__ void mbar_wait(uint32_t mbar, uint32_t parity) {
    uint32_t done;
    asm volatile(
        "{\n\t.reg .pred p;\n\t"
        "mbarrier.try_wait.parity.acquire.cta.shared::cta.b64 p, [%1], %2;\n\t"
        "selp.b32 %0, 1, 0, p;\n\t}"
        : "=r"(done) : "r"(mbar), "r"(parity) : "memory");
    if (!done) {
        asm volatile(
            "{\n\t.reg .pred P1;\n\t"
            "WL_%=:\n\t"
            "mbarrier.try_wait.parity.acquire.cta.shared::cta.b64 P1, [%0], %1, 0x989680;\n\t"
            "@P1 bra.uni WD_%=;\n\t"
            "bra.uni WL_%=;\n\t"
            "WD_%=:\n\t}"
            :: "r"(mbar), "r"(parity) : "memory");
    }
}

__device__ __forceinline__ void bulk_g2s(uint32_t dst, const void* src, uint32_t bytes, uint32_t mbar) {
    asm volatile(
        "cp.async.bulk.shared::cluster.global.mbarrier::complete_tx::bytes [%0], [%1], %2, [%3];"
        :: "r"(dst), "l"(src), "r"(bytes), "r"(mbar) : "memory");
}

#define FENCE_ASYNC() asm volatile("fence.proxy.async.shared::cta;" ::: "memory")

__device__ __forceinline__ void ldsm_x4(uint32_t& r0, uint32_t& r1, uint32_t& r2, uint32_t& r3,
                                        uint32_t addr) {
    asm volatile("ldmatrix.sync.aligned.m8n8.x4.shared.b16 {%0,%1,%2,%3}, [%4];"
                 : "=r"(r0), "=r"(r1), "=r"(r2), "=r"(r3) : "r"(addr));
}

__device__ __forceinline__ void mma_bf16(float* d, const uint32_t* a, const uint32_t* b) {
    asm volatile(
        "mma.sync.aligned.m16n8k16.row.col.f32.bf16.bf16.f32 "
        "{%0,%1,%2,%3}, {%4,%5,%6,%7}, {%8,%9}, {%0,%1,%2,%3};"
        : "+f"(d[0]), "+f"(d[1]), "+f"(d[2]), "+f"(d[3])
        : "r"(a[0]), "r"(a[1]), "r"(a[2]), "r"(a[3]), "r"(b[0]), "r"(b[1]));
}

// ---------------------------------------------------------------------------
// hi/lo bf16 split helpers
// ---------------------------------------------------------------------------
__device__ __forceinline__ void split_bf16(float v, __nv_bfloat16& h, __nv_bfloat16& l) {
    h = __float2bfloat16(v);
    l = __float2bfloat16(v - __bfloat162float(h));
}

// pack two floats into bf16x2 (lo=a, hi=b) and return residuals
__device__ __forceinline__ uint32_t pack2_res(float a, float b, float& ra, float& rb) {
    __nv_bfloat16 ha = __float2bfloat16(a);
    __nv_bfloat16 hb = __float2bfloat16(b);
    ra = a - __bfloat162float(ha);
    rb = b - __bfloat162float(hb);
    return ((uint32_t)__bfloat16_as_ushort(hb) << 16) | (uint32_t)__bfloat16_as_ushort(ha);
}
__device__ __forceinline__ uint32_t pack2(float a, float b) {
    return ((uint32_t)__bfloat16_as_ushort(__float2bfloat16(b)) << 16) |
           (uint32_t)__bfloat16_as_ushort(__float2bfloat16(a));
}

// ---------------------------------------------------------------------------
// Prep 1: split A [M,1024] fp32 -> tiled SW128-swizzled bf16 hi/lo blocks.
// ---------------------------------------------------------------------------
__global__ __launch_bounds__(256) void split_a_kernel(
    const float* __restrict__ in, __nv_bfloat16* __restrict__ oh,
    __nv_bfloat16* __restrict__ ol)
{
    const int kc = blockIdx.x;
    const int mt = blockIdx.y;
    const int t = threadIdx.x;
    const int r = t >> 1;
    const int hh = t & 1;

    const float* src = in + (size_t)(mt * 128 + r) * CC + kc * 64 + hh * 32;
    char* bh = (char*)(oh + ((size_t)mt * NKC + kc) * 8192);
    char* bl = (char*)(ol + ((size_t)mt * NKC + kc) * 8192);

#pragma unroll
    for (int j = 0; j < 4; j++) {
        float4 v0 = ((const float4*)src)[j * 2 + 0];
        float4 v1 = ((const float4*)src)[j * 2 + 1];
        __align__(16) __nv_bfloat16 h8[8], l8[8];
        split_bf16(v0.x, h8[0], l8[0]); split_bf16(v0.y, h8[1], l8[1]);
        split_bf16(v0.z, h8[2], l8[2]); split_bf16(v0.w, h8[3], l8[3]);
        split_bf16(v1.x, h8[4], l8[4]); split_bf16(v1.y, h8[5], l8[5]);
        split_bf16(v1.z, h8[6], l8[6]); split_bf16(v1.w, h8[7], l8[7]);
        uint32_t off = SWZ128((uint32_t)(r * 128 + hh * 64 + j * 16));
        *(uint4*)(bh + off) = *(const uint4*)h8;
        *(uint4*)(bl + off) = *(const uint4*)l8;
    }
}

// ---------------------------------------------------------------------------
// Prep 2: transpose + split W [1024, N] -> W^T tiled bf16 hi/lo blocks.
// ---------------------------------------------------------------------------
__global__ __launch_bounds__(256) void transpose_split_kernel(
    const float* __restrict__ W, __nv_bfloat16* __restrict__ oh,
    __nv_bfloat16* __restrict__ ol, int N)
{
    __shared__ float s[64][128];
    const int kc = blockIdx.x;
    const int nt = blockIdx.y;
    const int t = threadIdx.x;

    for (int idx = t; idx < 64 * 128; idx += 256) {
        int r = idx >> 7, n = idx & 127;
        s[r][n] = W[(size_t)(kc * 64 + r) * N + nt * 128 + n];
    }
    __syncthreads();

    const int np = t & 127;
    const int c0 = (t >> 7) * 4;
    char* bh = (char*)(oh + ((size_t)nt * NKC + kc) * 8192);
    char* bl = (char*)(ol + ((size_t)nt * NKC + kc) * 8192);

#pragma unroll
    for (int c = c0; c < c0 + 4; c++) {
        __align__(16) __nv_bfloat16 h8[8], l8[8];
#pragma unroll
        for (int j = 0; j < 8; j++) {
            split_bf16(s[c * 8 + j][np], h8[j], l8[j]);
        }
        uint32_t off = SWZ128((uint32_t)(np * 128 + c * 16));
        *(uint4*)(bh + off) = *(const uint4*)h8;
        *(uint4*)(bl + off) = *(const uint4*)l8;
    }
}

// ---------------------------------------------------------------------------
// Prep 3 (attention): Q/K per (b,h,qt) 128x64 blocks, Q scaled by 1/8.
// grid = (16 qt, 16 h, 4 b), 256 threads.
// ---------------------------------------------------------------------------
__global__ __launch_bounds__(256) void prep_qk_kernel(
    const float* __restrict__ qkv,
    __nv_bfloat16* __restrict__ qh, __nv_bfloat16* __restrict__ ql,
    __nv_bfloat16* __restrict__ kh, __nv_bfloat16* __restrict__ kl)
{
    const int qt = blockIdx.x;
    const int h  = blockIdx.y;
    const int b  = blockIdx.z;
    const int t = threadIdx.x;
    const int r = t >> 1;
    const int hh = t & 1;

    const float* qsrc = qkv + ((size_t)b * TT + qt * 128 + r) * N_QKV + h * 64 + hh * 32;
    const float* ksrc = qsrc + CC;
    const size_t blk = ((size_t)(b * HH + h) * 16 + qt) * 8192;
    char* bqh = (char*)(qh + blk);
    char* bql = (char*)(ql + blk);
    char* bkh = (char*)(kh + blk);
    char* bkl = (char*)(kl + blk);

#pragma unroll
    for (int j = 0; j < 4; j++) {
        uint32_t off = SWZ128((uint32_t)(r * 128 + hh * 64 + j * 16));
        {   // Q, scaled
            float4 v0 = ((const float4*)qsrc)[j * 2 + 0];
            float4 v1 = ((const float4*)qsrc)[j * 2 + 1];
            __align__(16) __nv_bfloat16 h8[8], l8[8];
            split_bf16(v0.x * 0.125f, h8[0], l8[0]); split_bf16(v0.y * 0.125f, h8[1], l8[1]);
            split_bf16(v0.z * 0.125f, h8[2], l8[2]); split_bf16(v0.w * 0.125f, h8[3], l8[3]);
            split_bf16(v1.x * 0.125f, h8[4], l8[4]); split_bf16(v1.y * 0.125f, h8[5], l8[5]);
            split_bf16(v1.z * 0.125f, h8[6], l8[6]); split_bf16(v1.w * 0.125f, h8[7], l8[7]);
            *(uint4*)(bqh + off) = *(const uint4*)h8;
            *(uint4*)(bql + off) = *(const uint4*)l8;
        }
        {   // K
            float4 v0 = ((const float4*)ksrc)[j * 2 + 0];
            float4 v1 = ((const float4*)ksrc)[j * 2 + 1];
            __align__(16) __nv_bfloat16 h8[8], l8[8];
            split_bf16(v0.x, h8[0], l8[0]); split_bf16(v0.y, h8[1], l8[1]);
            split_bf16(v0.z, h8[2], l8[2]); split_bf16(v0.w, h8[3], l8[3]);
            split_bf16(v1.x, h8[4], l8[4]); split_bf16(v1.y, h8[5], l8[5]);
            split_bf16(v1.z, h8[6], l8[6]); split_bf16(v1.w, h8[7], l8[7]);
            *(uint4*)(bkh + off) = *(const uint4*)h8;
            *(uint4*)(bkl + off) = *(const uint4*)l8;
        }
    }
}

// ---------------------------------------------------------------------------
// Prep 4 (attention): V^T per (b,h,kt2): [64 d][64 key] blocks.
// grid = (32 kt2, 16 h, 4 b), 256 threads.
// ---------------------------------------------------------------------------
__global__ __launch_bounds__(256) void prep_vt_kernel(
    const float* __restrict__ qkv,
    __nv_bfloat16* __restrict__ vh, __nv_bfloat16* __restrict__ vl)
{
    __shared__ float s[64][65];
    const int kt2 = blockIdx.x;
    const int h   = blockIdx.y;
    const int b   = blockIdx.z;
    const int t = threadIdx.x;

#pragma unroll
    for (int i = 0; i < 16; i++) {
        int idx = t + i * 256;
        int key = idx >> 6, d = idx & 63;
        s[d][key] = qkv[((size_t)b * TT + kt2 * 64 + key) * N_QKV + 2 * CC + h * 64 + d];
    }
    __syncthreads();

    const int dd = t >> 2;
    const int q4 = t & 3;
    const size_t blk = ((size_t)(b * HH + h) * 32 + kt2) * 4096;
    char* bh = (char*)(vh + blk);
    char* bl = (char*)(vl + blk);

#pragma unroll
    for (int j = 0; j < 2; j++) {
        const int col = q4 * 16 + j * 8;
        __align__(16) __nv_bfloat16 h8[8], l8[8];
#pragma unroll
        for (int e = 0; e < 8; e++) split_bf16(s[dd][col + e], h8[e], l8[e]);
        uint32_t off = SWZ128((uint32_t)(dd * 128 + q4 * 32 + j * 16));
        *(uint4*)(bh + off) = *(const uint4*)h8;
        *(uint4*)(bl + off) = *(const uint4*)l8;
    }
}

// ---------------------------------------------------------------------------
// mma.sync GEMM (unchanged from R3, passed at 1e-5)
// ---------------------------------------------------------------------------
#define STAGE_BYTES 65536u
#define GEMM_SMEM   (1024u + 2u * STAGE_BYTES)

__global__ __launch_bounds__(256) void gemm_mma_kernel(
    const __nv_bfloat16* __restrict__ Ah_, const __nv_bfloat16* __restrict__ Al_,
    const __nv_bfloat16* __restrict__ Bh_, const __nv_bfloat16* __restrict__ Bl_,
    const float* __restrict__ bias, float* __restrict__ C, int N)
{
    extern __shared__ __align__(1024) char smem[];
    const uint32_t sbase = smem_u32(smem);
    const int tid = threadIdx.x;
    const int nt = blockIdx.x;
    const int mt = blockIdx.y;

    const uint32_t mb0 = sbase + 8;
    const uint32_t mb1 = sbase + 16;
    const uint32_t stage0 = sbase + 1024;

    if (tid == 0) { MBAR_INIT(mb0, 1); MBAR_INIT(mb1, 1); }
    __syncthreads();

    const char* pAh = (const char*)(Ah_ + (size_t)mt * NKC * 8192);
    const char* pAl = (const char*)(Al_ + (size_t)mt * NKC * 8192);
    const char* pBh = (const char*)(Bh_ + (size_t)nt * NKC * 8192);
    const char* pBl = (const char*)(Bl_ + (size_t)nt * NKC * 8192);

    if (tid == 0) {
#pragma unroll
        for (int c = 0; c < 2; c++) {
            uint32_t st = stage0 + c * STAGE_BYTES;
            uint32_t mb = c ? mb1 : mb0;
            MBAR_EXPECT_TX(mb, STAGE_BYTES);
            bulk_g2s(st + 0,     pAh + (size_t)c * 16384, 16384, mb);
            bulk_g2s(st + 16384, pAl + (size_t)c * 16384, 16384, mb);
            bulk_g2s(st + 32768, pBh + (size_t)c * 16384, 16384, mb);
            bulk_g2s(st + 49152, pBl + (size_t)c * 16384, 16384, mb);
        }
    }

    const int w = tid >> 5, l = tid & 31;
    const int mrow = (w >> 2) * 64;
    const int ncol = (w & 3) * 32;
    const int mat = l >> 3;
    const int rin = l & 7;

    const int a_row_off = rin + ((mat & 1) << 3);
    const int a_kb_off  = (mat >> 1) << 4;
    const int b_row_off = rin + ((mat >> 1) << 3);
    const int b_kb_off  = (mat & 1) << 4;

    float acc[4][4][4];
#pragma unroll
    for (int i = 0; i < 4; i++)
#pragma unroll
        for (int j = 0; j < 4; j++)
#pragma unroll
            for (int k = 0; k < 4; k++) acc[i][j][k] = 0.f;

    for (int c = 0; c < NKC; c++) {
        const int s = c & 1;
        mbar_wait(s ? mb1 : mb0, (uint32_t)((c >> 1) & 1));

        const uint32_t stAh = stage0 + s * STAGE_BYTES;
        const uint32_t stAl = stAh + 16384;
        const uint32_t stBh = stAh + 32768;
        const uint32_t stBl = stAh + 49152;

#pragma unroll
        for (int ks = 0; ks < 4; ks++) {
            const int kb = ks * 32;
            uint32_t bh[4][2], bl[4][2];
#pragma unroll
            for (int n16 = 0; n16 < 2; n16++) {
                int row = ncol + n16 * 16 + b_row_off;
                uint32_t off = (uint32_t)(row * 128) +
                               (uint32_t)((kb + b_kb_off) ^ ((row & 7) << 4));
                ldsm_x4(bh[n16 * 2][0], bh[n16 * 2][1],
                        bh[n16 * 2 + 1][0], bh[n16 * 2 + 1][1], stBh + off);
                ldsm_x4(bl[n16 * 2][0], bl[n16 * 2][1],
                        bl[n16 * 2 + 1][0], bl[n16 * 2 + 1][1], stBl + off);
            }
#pragma unroll
            for (int m16 = 0; m16 < 4; m16++) {
                int row = mrow + m16 * 16 + a_row_off;
                uint32_t off = (uint32_t)(row * 128) +
                               (uint32_t)((kb + a_kb_off) ^ ((row & 7) << 4));
                uint32_t a[4];
                ldsm_x4(a[0], a[1], a[2], a[3], stAh + off);
#pragma unroll
                for (int n8 = 0; n8 < 4; n8++) mma_bf16(acc[m16][n8], a, bh[n8]);
#pragma unroll
                for (int n8 = 0; n8 < 4; n8++) mma_bf16(acc[m16][n8], a, bl[n8]);
            }
#pragma unroll
            for (int m16 = 0; m16 < 4; m16++) {
                int row = mrow + m16 * 16 + a_row_off;
                uint32_t off = (uint32_t)(row * 128) +
                               (uint32_t)((kb + a_kb_off) ^ ((row & 7) << 4));
                uint32_t a[4];
                ldsm_x4(a[0], a[1], a[2], a[3], stAl + off);
#pragma unroll
                for (int n8 = 0; n8 < 4; n8++) mma_bf16(acc[m16][n8], a, bh[n8]);
            }
        }

        __syncthreads();

        if (tid == 0 && c + 2 < NKC) {
            FENCE_ASYNC();
            const int cn = c + 2;
            const uint32_t mb = s ? mb1 : mb0;
            const uint32_t st = stage0 + s * STAGE_BYTES;
            MBAR_EXPECT_TX(mb, STAGE_BYTES);
            bulk_g2s(st + 0,     pAh + (size_t)cn * 16384, 16384, mb);
            bulk_g2s(st + 16384, pAl + (size_t)cn * 16384, 16384, mb);
            bulk_g2s(st + 32768, pBh + (size_t)cn * 16384, 16384, mb);
            bulk_g2s(st + 49152, pBl + (size_t)cn * 16384, 16384, mb);
        }
    }

    const int lr = l >> 2;
    const int lc = (l & 3) * 2;
#pragma unroll
    for (int m16 = 0; m16 < 4; m16++) {
        const size_t r0 = (size_t)(mt * 128 + mrow + m16 * 16 + lr);
        float* c0p = C + r0 * N;
        float* c1p = c0p + (size_t)8 * N;
#pragma unroll
        for (int n8 = 0; n8 < 4; n8++) {
            const int col = nt * 128 + ncol + n8 * 8 + lc;
            const float bx = bias[col], by = bias[col + 1];
            float2 v0 = make_float2(acc[m16][n8][0] + bx, acc[m16][n8][1] + by);
            float2 v1 = make_float2(acc[m16][n8][2] + bx, acc[m16][n8][3] + by);
            *(float2*)(c0p + col) = v0;
            *(float2*)(c1p + col) = v1;
        }
    }
}

// ---------------------------------------------------------------------------
// Flash attention on mma.sync (FA2-style register softmax, hi/lo compensated).
// CTA = 128 q-rows x (h, b). 8 warps x 16 rows. 128-key tiles, 2-stage pipe.
// ---------------------------------------------------------------------------
#define ATT_STAGE 65536u       // Kh 16K | Kl 16K | Vh 16K | Vl 16K
#define ATT_SMEM  (1024u + 32768u + 2u * ATT_STAGE)

__global__ __launch_bounds__(256) void flash_mma_kernel(
    const __nv_bfloat16* __restrict__ Qh_, const __nv_bfloat16* __restrict__ Ql_,
    const __nv_bfloat16* __restrict__ Kh_, const __nv_bfloat16* __restrict__ Kl_,
    const __nv_bfloat16* __restrict__ Vh_, const __nv_bfloat16* __restrict__ Vl_,
    float* __restrict__ y)
{
    extern __shared__ __align__(1024) char smem[];
    const uint32_t sbase = smem_u32(smem);
    const int tid = threadIdx.x;
    const int qt = blockIdx.x;
    const int h  = blockIdx.y;
    const int b  = blockIdx.z;

    const uint32_t mbq = sbase + 8;
    const uint32_t mb0 = sbase + 16;
    const uint32_t mb1 = sbase + 24;
    const uint32_t sQh = sbase + 1024;
    const uint32_t sQl = sQh + 16384;
    const uint32_t stage0 = sQl + 16384;

    if (tid == 0) { MBAR_INIT(mbq, 1); MBAR_INIT(mb0, 1); MBAR_INIT(mb1, 1); }
    __syncthreads();

    const int bh_idx = b * HH + h;
    const char* pQh = (const char*)(Qh_ + ((size_t)bh_idx * 16 + qt) * 8192);
    const char* pQl = (const char*)(Ql_ + ((size_t)bh_idx * 16 + qt) * 8192);
    const char* pKh = (const char*)(Kh_ + (size_t)bh_idx * 16 * 8192);
    const char* pKl = (const char*)(Kl_ + (size_t)bh_idx * 16 * 8192);
    const char* pVh = (const char*)(Vh_ + (size_t)bh_idx * 32 * 4096);
    const char* pVl = (const char*)(Vl_ + (size_t)bh_idx * 32 * 4096);

    const int ntiles = qt + 1;

    if (tid == 0) {
        MBAR_EXPECT_TX(mbq, 32768);
        bulk_g2s(sQh, pQh, 16384, mbq);
        bulk_g2s(sQl, pQl, 16384, mbq);
        const int npro = ntiles < 2 ? ntiles : 2;
        for (int c = 0; c < npro; c++) {
            uint32_t st = stage0 + c * ATT_STAGE;
            uint32_t mb = c ? mb1 : mb0;
            MBAR_EXPECT_TX(mb, ATT_STAGE);
            bulk_g2s(st + 0,     pKh + (size_t)c * 16384, 16384, mb);
            bulk_g2s(st + 16384, pKl + (size_t)c * 16384, 16384, mb);
            bulk_g2s(st + 32768, pVh + (size_t)c * 16384, 16384, mb);
            bulk_g2s(st + 49152, pVl + (size_t)c * 16384, 16384, mb);
        }
    }

    const int w = tid >> 5, l = tid & 31;
    const int mat = l >> 3, rin = l & 7;
    const int a_row_off = rin + ((mat & 1) << 3);
    const int a_kb_off  = (mat >> 1) << 4;
    const int b_row_off = rin + ((mat >> 1) << 3);
    const int b_kb_off  = (mat & 1) << 4;
    const int lr = l >> 2, qp = l & 3;

    // Q fragments (persist)
    mbar_wait(mbq, 0);
    uint32_t qh[4][4], ql[4][4];
#pragma unroll
    for (int ks = 0; ks < 4; ks++) {
        int row = w * 16 + a_row_off;
        uint32_t off = (uint32_t)(row * 128) +
                       (uint32_t)((ks * 32 + a_kb_off) ^ ((row & 7) << 4));
        ldsm_x4(qh[ks][0], qh[ks][1], qh[ks][2], qh[ks][3], sQh + off);
        ldsm_x4(ql[ks][0], ql[ks][1], ql[ks][2], ql[ks][3], sQl + off);
    }

    float acc_o[8][4];
#pragma unroll
    for (int j = 0; j < 8; j++)
#pragma unroll
        for (int e = 0; e < 4; e++) acc_o[j][e] = 0.f;
    float m0 = -1e30f, m1 = -1e30f, l0 = 0.f, l1 = 0.f;

    for (int kt = 0; kt < ntiles; kt++) {
        const int s = kt & 1;
        mbar_wait(s ? mb1 : mb0, (uint32_t)((kt >> 1) & 1));
        const uint32_t stKh = stage0 + s * ATT_STAGE;
        const uint32_t stKl = stKh + 16384;
        const uint32_t stVh = stKh + 32768;
        const uint32_t stVl = stKh + 49152;

        // --- S = Q K^T (3-term compensated), S[16 rows, 128 cols] per warp
        float acc_s[16][4];
#pragma unroll
        for (int j = 0; j < 16; j++)
#pragma unroll
            for (int e = 0; e < 4; e++) acc_s[j][e] = 0.f;

#pragma unroll
        for (int ks = 0; ks < 4; ks++) {
            const uint32_t kb = (uint32_t)(ks * 32 + b_kb_off);
#pragma unroll
            for (int g = 0; g < 8; g++) {
                int row = g * 16 + b_row_off;
                uint32_t off = (uint32_t)(row * 128) + (kb ^ (uint32_t)((row & 7) << 4));
                uint32_t kfh[4], kfl[4];
                ldsm_x4(kfh[0], kfh[1], kfh[2], kfh[3], stKh + off);
                ldsm_x4(kfl[0], kfl[1], kfl[2], kfl[3], stKl + off);
                mma_bf16(acc_s[2 * g],     qh[ks], kfh);
                mma_bf16(acc_s[2 * g],     qh[ks], kfl);
                mma_bf16(acc_s[2 * g],     ql[ks], kfh);
                mma_bf16(acc_s[2 * g + 1], qh[ks], kfh + 2);
                mma_bf16(acc_s[2 * g + 1], qh[ks], kfl + 2);
                mma_bf16(acc_s[2 * g + 1], ql[ks], kfh + 2);
            }
        }

        // --- causal mask on the diagonal tile
        if (kt == qt) {
            const int rr0 = w * 16 + lr, rr1 = rr0 + 8;
#pragma unroll
            for (int j = 0; j < 16; j++) {
                const int c0 = j * 8 + qp * 2;
                if (c0     > rr0) acc_s[j][0] = -1e30f;
                if (c0 + 1 > rr0) acc_s[j][1] = -1e30f;
                if (c0     > rr1) acc_s[j][2] = -1e30f;
                if (c0 + 1 > rr1) acc_s[j][3] = -1e30f;
            }
        }

        // --- online softmax (register, FA2)
        float t0 = -1e30f, t1 = -1e30f;
#pragma unroll
        for (int j = 0; j < 16; j++) {
            t0 = fmaxf(t0, fmaxf(acc_s[j][0], acc_s[j][1]));
            t1 = fmaxf(t1, fmaxf(acc_s[j][2], acc_s[j][3]));
        }
        t0 = fmaxf(t0, __shfl_xor_sync(0xffffffffu, t0, 1));
        t0 = fmaxf(t0, __shfl_xor_sync(0xffffffffu, t0, 2));
        t1 = fmaxf(t1, __shfl_xor_sync(0xffffffffu, t1, 1));
        t1 = fmaxf(t1, __shfl_xor_sync(0xffffffffu, t1, 2));

        const float mn0 = fmaxf(m0, t0);
        const float mn1 = fmaxf(m1, t1);
        const float cr0 = __expf(m0 - mn0);
        const float cr1 = __expf(m1 - mn1);
        m0 = mn0; m1 = mn1;
        l0 *= cr0; l1 *= cr1;
#pragma unroll
        for (int j = 0; j < 8; j++) {
            acc_o[j][0] *= cr0; acc_o[j][1] *= cr0;
            acc_o[j][2] *= cr1; acc_o[j][3] *= cr1;
        }

        // --- P = exp(S - m), pack hi/lo A-fragments
        uint32_t ph[8][4], pl[8][4];
#pragma unroll
        for (int j = 0; j < 16; j++) {
            const float p0 = __expf(acc_s[j][0] - mn0);
            const float p1 = __expf(acc_s[j][1] - mn0);
            const float p2 = __expf(acc_s[j][2] - mn1);
            const float p3 = __expf(acc_s[j][3] - mn1);
            l0 += p0 + p1; l1 += p2 + p3;
            float r0, r1, r2, r3;
            const uint32_t h01 = pack2_res(p0, p1, r0, r1);
            const uint32_t h23 = pack2_res(p2, p3, r2, r3);
            const uint32_t l01 = pack2(r0, r1);
            const uint32_t l23 = pack2(r2, r3);
            const int kc = j >> 1;
            if ((j & 1) == 0) {
                ph[kc][0] = h01; ph[kc][1] = h23;
                pl[kc][0] = l01; pl[kc][1] = l23;
            } else {
                ph[kc][2] = h01; ph[kc][3] = h23;
                pl[kc][2] = l01; pl[kc][3] = l23;
            }
        }

        // --- O += P V (3-term compensated)
#pragma unroll
        for (int kc = 0; kc < 8; kc++) {
            const uint32_t vhb = stVh + ((kc < 4) ? 0u : 8192u);
            const uint32_t vlb = stVl + ((kc < 4) ? 0u : 8192u);
            const uint32_t kb = (uint32_t)((kc & 3) * 32 + b_kb_off);
#pragma unroll
            for (int g = 0; g < 4; g++) {
                int row = g * 16 + b_row_off;
                uint32_t off = (uint32_t)(row * 128) + (kb ^ (uint32_t)((row & 7) << 4));
                uint32_t vfh[4], vfl[4];
                ldsm_x4(vfh[0], vfh[1], vfh[2], vfh[3], vhb + off);
                ldsm_x4(vfl[0], vfl[1], vfl[2], vfl[3], vlb + off);
                mma_bf16(acc_o[2 * g],     ph[kc], vfh);
                mma_bf16(acc_o[2 * g],     ph[kc], vfl);
                mma_bf16(acc_o[2 * g],     pl[kc], vfh);
                mma_bf16(acc_o[2 * g + 1], ph[kc], vfh + 2);
                mma_bf16(acc_o[2 * g + 1], ph[kc], vfl + 2);
                mma_bf16(acc_o[2 * g + 1], pl[kc], vfh + 2);
            }
        }

        __syncthreads();

        if (tid == 0 && kt + 2 < ntiles) {
            FENCE_ASYNC();
            const int cn = kt + 2;
            const uint32_t mb = s ? mb1 : mb0;
            const uint32_t st = stage0 + s * ATT_STAGE;
            MBAR_EXPECT_TX(mb, ATT_STAGE);
            bulk_g2s(st + 0,     pKh + (size_t)cn * 16384, 16384, mb);
            bulk_g2s(st + 16384, pKl + (size_t)cn * 16384, 16384, mb);
            bulk_g2s(st + 32768, pVh + (size_t)cn * 16384, 16384, mb);
            bulk_g2s(st + 49152, pVl + (size_t)cn * 16384, 16384, mb);
        }
    }

    // --- epilogue: normalize, store fp32
    l0 += __shfl_xor_sync(0xffffffffu, l0, 1);
    l0 += __shfl_xor_sync(0xffffffffu, l0, 2);
    l1 += __shfl_xor_sync(0xffffffffu, l1, 1);
    l1 += __shfl_xor_sync(0xffffffffu, l1, 2);
    const float inv0 = 1.f / l0;
    const float inv1 = 1.f / l1;

    const int row0 = qt * 128 + w * 16 + lr;
    float* y0 = y + ((size_t)b * TT + row0) * CC + h * 64;
    float* y1 = y0 + (size_t)8 * CC;
#pragma unroll
    for (int j = 0; j < 8; j++) {
        const int dc = j * 8 + qp * 2;
        *(float2*)(y0 + dc) = make_float2(acc_o[j][0] * inv0, acc_o[j][1] * inv0);
        *(float2*)(y1 + dc) = make_float2(acc_o[j][2] * inv1, acc_o[j][3] * inv1);
    }
}

// ---------------------------------------------------------------------------
// Launch
// ---------------------------------------------------------------------------
extern "C" void kernel_launch(void* const* d_in, const int* in_sizes, int n_in,
                              void* d_out, int out_size)
{
    const float* x     = (const float*)d_in[0];
    const float* Wqkv  = (const float*)d_in[1];
    const float* bqkv  = (const float*)d_in[2];
    const float* Wproj = (const float*)d_in[3];
    const float* bproj = (const float*)d_in[4];
    float* out = (float*)d_out;

    float *qkv_ptr, *y_ptr;
    __nv_bfloat16 *xh, *xl, *yh, *yl, *wqh, *wql, *wph, *wpl;
    __nv_bfloat16 *aqh, *aql, *akh, *akl, *avh, *avl;
    cudaGetSymbolAddress((void**)&qkv_ptr, g_qkv);
    cudaGetSymbolAddress((void**)&y_ptr, g_y);
    cudaGetSymbolAddress((void**)&xh, g_xh);
    cudaGetSymbolAddress((void**)&xl, g_xl);
    cudaGetSymbolAddress((void**)&yh, g_yh);
    cudaGetSymbolAddress((void**)&yl, g_yl);
    cudaGetSymbolAddress((void**)&wqh, g_wqkvh);
    cudaGetSymbolAddress((void**)&wql, g_wqkvl);
    cudaGetSymbolAddress((void**)&wph, g_wprojh);
    cudaGetSymbolAddress((void**)&wpl, g_wprojl);
    cudaGetSymbolAddress((void**)&aqh, g_qh);
    cudaGetSymbolAddress((void**)&aql, g_ql);
    cudaGetSymbolAddress((void**)&akh, g_kh);
    cudaGetSymbolAddress((void**)&akl, g_kl);
    cudaGetSymbolAddress((void**)&avh, g_vh);
    cudaGetSymbolAddress((void**)&avl, g_vl);

    cudaFuncSetAttribute(gemm_mma_kernel,
                         cudaFuncAttributeMaxDynamicSharedMemorySize, GEMM_SMEM);
    cudaFuncSetAttribute(flash_mma_kernel,
                         cudaFuncAttributeMaxDynamicSharedMemorySize, ATT_SMEM);

    // Prep: split/tile x, transpose/split weights
    split_a_kernel<<<dim3(NKC, MTOK / 128), 256>>>(x, xh, xl);
    transpose_split_kernel<<<dim3(NKC, N_QKV / 128), 256>>>(Wqkv, wqh, wql, N_QKV);
    transpose_split_kernel<<<dim3(NKC, CC / 128), 256>>>(Wproj, wph, wpl, CC);

    // QKV GEMM: [8192 x 3072]
    gemm_mma_kernel<<<dim3(N_QKV / 128, MTOK / 128), 256, GEMM_SMEM>>>(
        xh, xl, wqh, wql, bqkv, qkv_ptr, N_QKV);

    // Attention prep: per-head tiles
    prep_qk_kernel<<<dim3(16, HH, BB), 256>>>(qkv_ptr, aqh, aql, akh, akl);
    prep_vt_kernel<<<dim3(32, HH, BB), 256>>>(qkv_ptr, avh, avl);

    // Flash attention (tensor cores)
    flash_mma_kernel<<<dim3(TT / 128, HH, BB), 256, ATT_SMEM>>>(
        aqh, aql, akh, akl, avh, avl, y_ptr);

    // Split/tile y, then proj GEMM: [8192 x 1024]
    split_a_kernel<<<dim3(NKC, MTOK / 128), 256>>>(y_ptr, yh, yl);
    gemm_mma_kernel<<<dim3(CC / 128, MTOK / 128), 256, GEMM_SMEM>>>(
        yh, yl, wph, wpl, bproj, out, CC);
}

// round 5
// speedup vs baseline: 3.4960x; 1.0288x over previous
#include <cuda_runtime.h>
#include <cuda_bf16.h>
#include <math.h>
#include <stdint.h>

// Problem constants
#define BB 4
#define TT 2048
#define CC 1024
#define HH 16
#define DD 64
#define MTOK (BB * TT)          // 8192 tokens
#define N_QKV (3 * CC)          // 3072
#define NKC 16                  // K chunks: 1024 / 64

// ---------------------------------------------------------------------------
// Scratch (allocation-free rule: __device__ globals)
// ---------------------------------------------------------------------------
__device__ float g_qkv[(size_t)MTOK * N_QKV];            // 96 MB fp32
__device__ float g_y[(size_t)MTOK * CC];                 // 32 MB fp32
__device__ __nv_bfloat16 g_xh[(size_t)MTOK * CC];
__device__ __nv_bfloat16 g_xl[(size_t)MTOK * CC];
__device__ __nv_bfloat16 g_yh[(size_t)MTOK * CC];
__device__ __nv_bfloat16 g_yl[(size_t)MTOK * CC];
__device__ __nv_bfloat16 g_wqkvh[(size_t)N_QKV * CC];
__device__ __nv_bfloat16 g_wqkvl[(size_t)N_QKV * CC];
__device__ __nv_bfloat16 g_wprojh[(size_t)CC * CC];
__device__ __nv_bfloat16 g_wprojl[(size_t)CC * CC];
// attention operand tiles (per (b,h), SW128 swizzled bf16)
__device__ __nv_bfloat16 g_qh[(size_t)BB * HH * 16 * 8192];
__device__ __nv_bfloat16 g_ql[(size_t)BB * HH * 16 * 8192];
__device__ __nv_bfloat16 g_kh[(size_t)BB * HH * 16 * 8192];
__device__ __nv_bfloat16 g_kl[(size_t)BB * HH * 16 * 8192];
__device__ __nv_bfloat16 g_vh[(size_t)BB * HH * 32 * 4096];
__device__ __nv_bfloat16 g_vl[(size_t)BB * HH * 32 * 4096];

// ---------------------------------------------------------------------------
// PTX helpers (base sm_103 target — NO tcgen05)
// ---------------------------------------------------------------------------
__device__ __forceinline__ uint32_t smem_u32(const void* p) {
    uint32_t a;
    asm("{ .reg .u64 t; cvta.to.shared.u64 t, %1; cvt.u32.u64 %0, t; }" : "=r"(a) : "l"(p));
    return a;
}

#define SWZ128(off) ((off) ^ (((off) >> 3) & 0x70))

#define MBAR_INIT(addr, cnt) \
    asm volatile("mbarrier.init.shared.b64 [%0], %1;" :: "r"(addr), "r"(cnt) : "memory")

#define MBAR_EXPECT_TX(addr, bytes) \
    asm volatile("mbarrier.arrive.expect_tx.shared.b64 _, [%0], %1;" :: "r"(addr), "r"(bytes) : "memory")

#define MBAR_ARRIVE(addr) \
    asm volatile("mbarrier.arrive.shared.b64 _, [%0];" :: "r"(addr) : "memory")

__device__ __forceinline__ void mbar_wait(uint32_t mbar, uint32_t parity) {
    uint32_t done;
    asm volatile(
        "{\n\t.reg .pred p;\n\t"
        "mbarrier.try_wait.parity.acquire.cta.shared::cta.b64 p, [%1], %2;\n\t"
        "selp.b32 %0, 1, 0, p;\n\t}"
        : "=r"(done) : "r"(mbar), "r"(parity) : "memory");
    if (!done) {
        asm volatile(
            "{\n\t.reg .pred P1;\n\t"
            "WL_%=:\n\t"
            "mbarrier.try_wait.parity.acquire.cta.shared::cta.b64 P1, [%0], %1, 0x989680;\n\t"
            "@P1 bra.uni WD_%=;\n\t"
            "bra.uni WL_%=;\n\t"
            "WD_%=:\n\t}"
            :: "r"(mbar), "r"(parity) : "memory");
    }
}

__device__ __forceinline__ void bulk_g2s(uint32_t dst, const void* src, uint32_t bytes, uint32_t mbar) {
    asm volatile(
        "cp.async.bulk.shared::cluster.global.mbarrier::complete_tx::bytes [%0], [%1], %2, [%3];"
        :: "r"(dst), "l"(src), "r"(bytes), "r"(mbar) : "memory");
}

#define FENCE_ASYNC() asm volatile("fence.proxy.async.shared::cta;" ::: "memory")

__device__ __forceinline__ void ldsm_x4(uint32_t& r0, uint32_t& r1, uint32_t& r2, uint32_t& r3,
                                        uint32_t addr) {
    asm volatile("ldmatrix.sync.aligned.m8n8.x4.shared.b16 {%0,%1,%2,%3}, [%4];"
                 : "=r"(r0), "=r"(r1), "=r"(r2), "=r"(r3) : "r"(addr));
}

__device__ __forceinline__ void mma_bf16(float* d, const uint32_t* a, const uint32_t* b) {
    asm volatile(
        "mma.sync.aligned.m16n8k16.row.col.f32.bf16.bf16.f32 "
        "{%0,%1,%2,%3}, {%4,%5,%6,%7}, {%8,%9}, {%0,%1,%2,%3};"
        : "+f"(d[0]), "+f"(d[1]), "+f"(d[2]), "+f"(d[3])
        : "r"(a[0]), "r"(a[1]), "r"(a[2]), "r"(a[3]), "r"(b[0]), "r"(b[1]));
}

// ---------------------------------------------------------------------------
// hi/lo bf16 split helpers
// ---------------------------------------------------------------------------
__device__ __forceinline__ void split_bf16(float v, __nv_bfloat16& h, __nv_bfloat16& l) {
    h = __float2bfloat16(v);
    l = __float2bfloat16(v - __bfloat162float(h));
}

__device__ __forceinline__ uint32_t pack2_res(float a, float b, float& ra, float& rb) {
    __nv_bfloat16 ha = __float2bfloat16(a);
    __nv_bfloat16 hb = __float2bfloat16(b);
    ra = a - __bfloat162float(ha);
    rb = b - __bfloat162float(hb);
    return ((uint32_t)__bfloat16_as_ushort(hb) << 16) | (uint32_t)__bfloat16_as_ushort(ha);
}
__device__ __forceinline__ uint32_t pack2(float a, float b) {
    return ((uint32_t)__bfloat16_as_ushort(__float2bfloat16(b)) << 16) |
           (uint32_t)__bfloat16_as_ushort(__float2bfloat16(a));
}

// ---------------------------------------------------------------------------
// Prep 1: split A [M,1024] fp32 -> tiled SW128-swizzled bf16 hi/lo blocks.
// ---------------------------------------------------------------------------
__global__ __launch_bounds__(256) void split_a_kernel(
    const float* __restrict__ in, __nv_bfloat16* __restrict__ oh,
    __nv_bfloat16* __restrict__ ol)
{
    const int kc = blockIdx.x;
    const int mt = blockIdx.y;
    const int t = threadIdx.x;
    const int r = t >> 1;
    const int hh = t & 1;

    const float* src = in + (size_t)(mt * 128 + r) * CC + kc * 64 + hh * 32;
    char* bh = (char*)(oh + ((size_t)mt * NKC + kc) * 8192);
    char* bl = (char*)(ol + ((size_t)mt * NKC + kc) * 8192);

#pragma unroll
    for (int j = 0; j < 4; j++) {
        float4 v0 = ((const float4*)src)[j * 2 + 0];
        float4 v1 = ((const float4*)src)[j * 2 + 1];
        __align__(16) __nv_bfloat16 h8[8], l8[8];
        split_bf16(v0.x, h8[0], l8[0]); split_bf16(v0.y, h8[1], l8[1]);
        split_bf16(v0.z, h8[2], l8[2]); split_bf16(v0.w, h8[3], l8[3]);
        split_bf16(v1.x, h8[4], l8[4]); split_bf16(v1.y, h8[5], l8[5]);
        split_bf16(v1.z, h8[6], l8[6]); split_bf16(v1.w, h8[7], l8[7]);
        uint32_t off = SWZ128((uint32_t)(r * 128 + hh * 64 + j * 16));
        *(uint4*)(bh + off) = *(const uint4*)h8;
        *(uint4*)(bl + off) = *(const uint4*)l8;
    }
}

// ---------------------------------------------------------------------------
// Prep 2: transpose + split W [1024, N] -> W^T tiled bf16 hi/lo blocks.
// ---------------------------------------------------------------------------
__global__ __launch_bounds__(256) void transpose_split_kernel(
    const float* __restrict__ W, __nv_bfloat16* __restrict__ oh,
    __nv_bfloat16* __restrict__ ol, int N)
{
    __shared__ float s[64][128];
    const int kc = blockIdx.x;
    const int nt = blockIdx.y;
    const int t = threadIdx.x;

    for (int idx = t; idx < 64 * 128; idx += 256) {
        int r = idx >> 7, n = idx & 127;
        s[r][n] = W[(size_t)(kc * 64 + r) * N + nt * 128 + n];
    }
    __syncthreads();

    const int np = t & 127;
    const int c0 = (t >> 7) * 4;
    char* bh = (char*)(oh + ((size_t)nt * NKC + kc) * 8192);
    char* bl = (char*)(ol + ((size_t)nt * NKC + kc) * 8192);

#pragma unroll
    for (int c = c0; c < c0 + 4; c++) {
        __align__(16) __nv_bfloat16 h8[8], l8[8];
#pragma unroll
        for (int j = 0; j < 8; j++) {
            split_bf16(s[c * 8 + j][np], h8[j], l8[j]);
        }
        uint32_t off = SWZ128((uint32_t)(np * 128 + c * 16));
        *(uint4*)(bh + off) = *(const uint4*)h8;
        *(uint4*)(bl + off) = *(const uint4*)l8;
    }
}

// ---------------------------------------------------------------------------
// Prep 3 (attention): Q/K per (b,h,qt) 128x64 blocks, Q scaled by 1/8.
// ---------------------------------------------------------------------------
__global__ __launch_bounds__(256) void prep_qk_kernel(
    const float* __restrict__ qkv,
    __nv_bfloat16* __restrict__ qh, __nv_bfloat16* __restrict__ ql,
    __nv_bfloat16* __restrict__ kh, __nv_bfloat16* __restrict__ kl)
{
    const int qt = blockIdx.x;
    const int h  = blockIdx.y;
    const int b  = blockIdx.z;
    const int t = threadIdx.x;
    const int r = t >> 1;
    const int hh = t & 1;

    const float* qsrc = qkv + ((size_t)b * TT + qt * 128 + r) * N_QKV + h * 64 + hh * 32;
    const float* ksrc = qsrc + CC;
    const size_t blk = ((size_t)(b * HH + h) * 16 + qt) * 8192;
    char* bqh = (char*)(qh + blk);
    char* bql = (char*)(ql + blk);
    char* bkh = (char*)(kh + blk);
    char* bkl = (char*)(kl + blk);

#pragma unroll
    for (int j = 0; j < 4; j++) {
        uint32_t off = SWZ128((uint32_t)(r * 128 + hh * 64 + j * 16));
        {
            float4 v0 = ((const float4*)qsrc)[j * 2 + 0];
            float4 v1 = ((const float4*)qsrc)[j * 2 + 1];
            __align__(16) __nv_bfloat16 h8[8], l8[8];
            split_bf16(v0.x * 0.125f, h8[0], l8[0]); split_bf16(v0.y * 0.125f, h8[1], l8[1]);
            split_bf16(v0.z * 0.125f, h8[2], l8[2]); split_bf16(v0.w * 0.125f, h8[3], l8[3]);
            split_bf16(v1.x * 0.125f, h8[4], l8[4]); split_bf16(v1.y * 0.125f, h8[5], l8[5]);
            split_bf16(v1.z * 0.125f, h8[6], l8[6]); split_bf16(v1.w * 0.125f, h8[7], l8[7]);
            *(uint4*)(bqh + off) = *(const uint4*)h8;
            *(uint4*)(bql + off) = *(const uint4*)l8;
        }
        {
            float4 v0 = ((const float4*)ksrc)[j * 2 + 0];
            float4 v1 = ((const float4*)ksrc)[j * 2 + 1];
            __align__(16) __nv_bfloat16 h8[8], l8[8];
            split_bf16(v0.x, h8[0], l8[0]); split_bf16(v0.y, h8[1], l8[1]);
            split_bf16(v0.z, h8[2], l8[2]); split_bf16(v0.w, h8[3], l8[3]);
            split_bf16(v1.x, h8[4], l8[4]); split_bf16(v1.y, h8[5], l8[5]);
            split_bf16(v1.z, h8[6], l8[6]); split_bf16(v1.w, h8[7], l8[7]);
            *(uint4*)(bkh + off) = *(const uint4*)h8;
            *(uint4*)(bkl + off) = *(const uint4*)l8;
        }
    }
}

// ---------------------------------------------------------------------------
// Prep 4 (attention): V^T per (b,h,kt2): [64 d][64 key] blocks.
// ---------------------------------------------------------------------------
__global__ __launch_bounds__(256) void prep_vt_kernel(
    const float* __restrict__ qkv,
    __nv_bfloat16* __restrict__ vh, __nv_bfloat16* __restrict__ vl)
{
    __shared__ float s[64][65];
    const int kt2 = blockIdx.x;
    const int h   = blockIdx.y;
    const int b   = blockIdx.z;
    const int t = threadIdx.x;

#pragma unroll
    for (int i = 0; i < 16; i++) {
        int idx = t + i * 256;
        int key = idx >> 6, d = idx & 63;
        s[d][key] = qkv[((size_t)b * TT + kt2 * 64 + key) * N_QKV + 2 * CC + h * 64 + d];
    }
    __syncthreads();

    const int dd = t >> 2;
    const int q4 = t & 3;
    const size_t blk = ((size_t)(b * HH + h) * 32 + kt2) * 4096;
    char* bh = (char*)(vh + blk);
    char* bl = (char*)(vl + blk);

#pragma unroll
    for (int j = 0; j < 2; j++) {
        const int col = q4 * 16 + j * 8;
        __align__(16) __nv_bfloat16 h8[8], l8[8];
#pragma unroll
        for (int e = 0; e < 8; e++) split_bf16(s[dd][col + e], h8[e], l8[e]);
        uint32_t off = SWZ128((uint32_t)(dd * 128 + q4 * 32 + j * 16));
        *(uint4*)(bh + off) = *(const uint4*)h8;
        *(uint4*)(bl + off) = *(const uint4*)l8;
    }
}

// ---------------------------------------------------------------------------
// mma.sync GEMM, 3-stage mbarrier pipeline (full + empty barriers, no
// mainloop __syncthreads). CTA 128x128, BK=64, 8 warps.
// ---------------------------------------------------------------------------
#define STAGE_BYTES 65536u
#define NSTAGE 3
#define GEMM_SMEM   (1024u + NSTAGE * STAGE_BYTES)

__global__ __launch_bounds__(256) void gemm_mma_kernel(
    const __nv_bfloat16* __restrict__ Ah_, const __nv_bfloat16* __restrict__ Al_,
    const __nv_bfloat16* __restrict__ Bh_, const __nv_bfloat16* __restrict__ Bl_,
    const float* __restrict__ bias, float* __restrict__ C, int N)
{
    extern __shared__ __align__(1024) char smem[];
    const uint32_t sbase = smem_u32(smem);
    const int tid = threadIdx.x;
    const int nt = blockIdx.x;
    const int mt = blockIdx.y;

    // header: full[s] = sbase+8+8s, empty[s] = sbase+40+8s
    const uint32_t stage0 = sbase + 1024;

    if (tid == 0) {
#pragma unroll
        for (int s = 0; s < NSTAGE; s++) {
            MBAR_INIT(sbase + 8 + 8 * s, 1);
            MBAR_INIT(sbase + 40 + 8 * s, 256);
        }
    }
    __syncthreads();

    const char* pAh = (const char*)(Ah_ + (size_t)mt * NKC * 8192);
    const char* pAl = (const char*)(Al_ + (size_t)mt * NKC * 8192);
    const char* pBh = (const char*)(Bh_ + (size_t)nt * NKC * 8192);
    const char* pBl = (const char*)(Bl_ + (size_t)nt * NKC * 8192);

    if (tid == 0) {
#pragma unroll
        for (int c = 0; c < NSTAGE; c++) {
            uint32_t st = stage0 + c * STAGE_BYTES;
            uint32_t mb = sbase + 8 + 8 * c;
            MBAR_EXPECT_TX(mb, STAGE_BYTES);
            bulk_g2s(st + 0,     pAh + (size_t)c * 16384, 16384, mb);
            bulk_g2s(st + 16384, pAl + (size_t)c * 16384, 16384, mb);
            bulk_g2s(st + 32768, pBh + (size_t)c * 16384, 16384, mb);
            bulk_g2s(st + 49152, pBl + (size_t)c * 16384, 16384, mb);
        }
    }

    const int w = tid >> 5, l = tid & 31;
    const int mrow = (w >> 2) * 64;
    const int ncol = (w & 3) * 32;
    const int mat = l >> 3;
    const int rin = l & 7;

    const int a_row_off = rin + ((mat & 1) << 3);
    const int a_kb_off  = (mat >> 1) << 4;
    const int b_row_off = rin + ((mat >> 1) << 3);
    const int b_kb_off  = (mat & 1) << 4;

    float acc[4][4][4];
#pragma unroll
    for (int i = 0; i < 4; i++)
#pragma unroll
        for (int j = 0; j < 4; j++)
#pragma unroll
            for (int k = 0; k < 4; k++) acc[i][j][k] = 0.f;

    for (int c = 0; c < NKC; c++) {
        const int s = c % NSTAGE;
        const uint32_t ph = (uint32_t)((c / NSTAGE) & 1);
        mbar_wait(sbase + 8 + 8 * s, ph);

        const uint32_t stAh = stage0 + s * STAGE_BYTES;
        const uint32_t stAl = stAh + 16384;
        const uint32_t stBh = stAh + 32768;
        const uint32_t stBl = stAh + 49152;

#pragma unroll
        for (int ks = 0; ks < 4; ks++) {
            const int kb = ks * 32;
            uint32_t bh[4][2], bl[4][2];
#pragma unroll
            for (int n16 = 0; n16 < 2; n16++) {
                int row = ncol + n16 * 16 + b_row_off;
                uint32_t off = (uint32_t)(row * 128) +
                               (uint32_t)((kb + b_kb_off) ^ ((row & 7) << 4));
                ldsm_x4(bh[n16 * 2][0], bh[n16 * 2][1],
                        bh[n16 * 2 + 1][0], bh[n16 * 2 + 1][1], stBh + off);
                ldsm_x4(bl[n16 * 2][0], bl[n16 * 2][1],
                        bl[n16 * 2 + 1][0], bl[n16 * 2 + 1][1], stBl + off);
            }
#pragma unroll
            for (int m16 = 0; m16 < 4; m16++) {
                int row = mrow + m16 * 16 + a_row_off;
                uint32_t off = (uint32_t)(row * 128) +
                               (uint32_t)((kb + a_kb_off) ^ ((row & 7) << 4));
                uint32_t a[4];
                ldsm_x4(a[0], a[1], a[2], a[3], stAh + off);
#pragma unroll
                for (int n8 = 0; n8 < 4; n8++) mma_bf16(acc[m16][n8], a, bh[n8]);
#pragma unroll
                for (int n8 = 0; n8 < 4; n8++) mma_bf16(acc[m16][n8], a, bl[n8]);
            }
#pragma unroll
            for (int m16 = 0; m16 < 4; m16++) {
                int row = mrow + m16 * 16 + a_row_off;
                uint32_t off = (uint32_t)(row * 128) +
                               (uint32_t)((kb + a_kb_off) ^ ((row & 7) << 4));
                uint32_t a[4];
                ldsm_x4(a[0], a[1], a[2], a[3], stAl + off);
#pragma unroll
                for (int n8 = 0; n8 < 4; n8++) mma_bf16(acc[m16][n8], a, bh[n8]);
            }
        }

        // signal stage consumed
        MBAR_ARRIVE(sbase + 40 + 8 * s);

        if (tid == 0 && c + NSTAGE < NKC) {
            mbar_wait(sbase + 40 + 8 * s, ph);   // all 256 done with stage s
            FENCE_ASYNC();
            const int cn = c + NSTAGE;
            const uint32_t mb = sbase + 8 + 8 * s;
            const uint32_t st = stage0 + s * STAGE_BYTES;
            MBAR_EXPECT_TX(mb, STAGE_BYTES);
            bulk_g2s(st + 0,     pAh + (size_t)cn * 16384, 16384, mb);
            bulk_g2s(st + 16384, pAl + (size_t)cn * 16384, 16384, mb);
            bulk_g2s(st + 32768, pBh + (size_t)cn * 16384, 16384, mb);
            bulk_g2s(st + 49152, pBl + (size_t)cn * 16384, 16384, mb);
        }
    }

    const int lr = l >> 2;
    const int lc = (l & 3) * 2;
#pragma unroll
    for (int m16 = 0; m16 < 4; m16++) {
        const size_t r0 = (size_t)(mt * 128 + mrow + m16 * 16 + lr);
        float* c0p = C + r0 * N;
        float* c1p = c0p + (size_t)8 * N;
#pragma unroll
        for (int n8 = 0; n8 < 4; n8++) {
            const int col = nt * 128 + ncol + n8 * 8 + lc;
            const float bx = bias[col], by = bias[col + 1];
            float2 v0 = make_float2(acc[m16][n8][0] + bx, acc[m16][n8][1] + by);
            float2 v1 = make_float2(acc[m16][n8][2] + bx, acc[m16][n8][3] + by);
            *(float2*)(c0p + col) = v0;
            *(float2*)(c1p + col) = v1;
        }
    }
}

// ---------------------------------------------------------------------------
// Flash attention on mma.sync, 3-stage K/V pipeline with empty barriers.
// CTA = 128 q-rows x (h, b); qt reversed for scheduling (big tiles first).
// ---------------------------------------------------------------------------
#define ATT_STAGE 65536u       // Kh 16K | Kl 16K | Vh 16K | Vl 16K
#define ATT_SMEM  (1024u + 32768u + NSTAGE * ATT_STAGE)

__global__ __launch_bounds__(256) void flash_mma_kernel(
    const __nv_bfloat16* __restrict__ Qh_, const __nv_bfloat16* __restrict__ Ql_,
    const __nv_bfloat16* __restrict__ Kh_, const __nv_bfloat16* __restrict__ Kl_,
    const __nv_bfloat16* __restrict__ Vh_, const __nv_bfloat16* __restrict__ Vl_,
    float* __restrict__ y)
{
    extern __shared__ __align__(1024) char smem[];
    const uint32_t sbase = smem_u32(smem);
    const int tid = threadIdx.x;
    const int qt = (int)gridDim.x - 1 - (int)blockIdx.x;   // big tiles first
    const int h  = blockIdx.y;
    const int b  = blockIdx.z;

    // header: mbq=+8, full[s]=+16+8s, empty[s]=+40+8s
    const uint32_t mbq = sbase + 8;
    const uint32_t sQh = sbase + 1024;
    const uint32_t sQl = sQh + 16384;
    const uint32_t stage0 = sQl + 16384;

    if (tid == 0) {
        MBAR_INIT(mbq, 1);
#pragma unroll
        for (int s = 0; s < NSTAGE; s++) {
            MBAR_INIT(sbase + 16 + 8 * s, 1);
            MBAR_INIT(sbase + 40 + 8 * s, 256);
        }
    }
    __syncthreads();

    const int bh_idx = b * HH + h;
    const char* pQh = (const char*)(Qh_ + ((size_t)bh_idx * 16 + qt) * 8192);
    const char* pQl = (const char*)(Ql_ + ((size_t)bh_idx * 16 + qt) * 8192);
    const char* pKh = (const char*)(Kh_ + (size_t)bh_idx * 16 * 8192);
    const char* pKl = (const char*)(Kl_ + (size_t)bh_idx * 16 * 8192);
    const char* pVh = (const char*)(Vh_ + (size_t)bh_idx * 32 * 4096);
    const char* pVl = (const char*)(Vl_ + (size_t)bh_idx * 32 * 4096);

    const int ntiles = qt + 1;

    if (tid == 0) {
        MBAR_EXPECT_TX(mbq, 32768);
        bulk_g2s(sQh, pQh, 16384, mbq);
        bulk_g2s(sQl, pQl, 16384, mbq);
        const int npro = ntiles < NSTAGE ? ntiles : NSTAGE;
        for (int c = 0; c < npro; c++) {
            uint32_t st = stage0 + c * ATT_STAGE;
            uint32_t mb = sbase + 16 + 8 * c;
            MBAR_EXPECT_TX(mb, ATT_STAGE);
            bulk_g2s(st + 0,     pKh + (size_t)c * 16384, 16384, mb);
            bulk_g2s(st + 16384, pKl + (size_t)c * 16384, 16384, mb);
            bulk_g2s(st + 32768, pVh + (size_t)c * 16384, 16384, mb);
            bulk_g2s(st + 49152, pVl + (size_t)c * 16384, 16384, mb);
        }
    }

    const int w = tid >> 5, l = tid & 31;
    const int mat = l >> 3, rin = l & 7;
    const int a_row_off = rin + ((mat & 1) << 3);
    const int a_kb_off  = (mat >> 1) << 4;
    const int b_row_off = rin + ((mat >> 1) << 3);
    const int b_kb_off  = (mat & 1) << 4;
    const int lr = l >> 2, qp = l & 3;

    // Q fragments (persist)
    mbar_wait(mbq, 0);
    uint32_t qh[4][4], ql[4][4];
#pragma unroll
    for (int ks = 0; ks < 4; ks++) {
        int row = w * 16 + a_row_off;
        uint32_t off = (uint32_t)(row * 128) +
                       (uint32_t)((ks * 32 + a_kb_off) ^ ((row & 7) << 4));
        ldsm_x4(qh[ks][0], qh[ks][1], qh[ks][2], qh[ks][3], sQh + off);
        ldsm_x4(ql[ks][0], ql[ks][1], ql[ks][2], ql[ks][3], sQl + off);
    }

    float acc_o[8][4];
#pragma unroll
    for (int j = 0; j < 8; j++)
#pragma unroll
        for (int e = 0; e < 4; e++) acc_o[j][e] = 0.f;
    float m0 = -1e30f, m1 = -1e30f, l0 = 0.f, l1 = 0.f;

    for (int kt = 0; kt < ntiles; kt++) {
        const int s = kt % NSTAGE;
        const uint32_t phs = (uint32_t)((kt / NSTAGE) & 1);
        mbar_wait(sbase + 16 + 8 * s, phs);
        const uint32_t stKh = stage0 + s * ATT_STAGE;
        const uint32_t stKl = stKh + 16384;
        const uint32_t stVh = stKh + 32768;
        const uint32_t stVl = stKh + 49152;

        // --- S = Q K^T (3-term compensated)
        float acc_s[16][4];
#pragma unroll
        for (int j = 0; j < 16; j++)
#pragma unroll
            for (int e = 0; e < 4; e++) acc_s[j][e] = 0.f;

#pragma unroll
        for (int ks = 0; ks < 4; ks++) {
            const uint32_t kb = (uint32_t)(ks * 32 + b_kb_off);
#pragma unroll
            for (int g = 0; g < 8; g++) {
                int row = g * 16 + b_row_off;
                uint32_t off = (uint32_t)(row * 128) + (kb ^ (uint32_t)((row & 7) << 4));
                uint32_t kfh[4], kfl[4];
                ldsm_x4(kfh[0], kfh[1], kfh[2], kfh[3], stKh + off);
                ldsm_x4(kfl[0], kfl[1], kfl[2], kfl[3], stKl + off);
                mma_bf16(acc_s[2 * g],     qh[ks], kfh);
                mma_bf16(acc_s[2 * g],     qh[ks], kfl);
                mma_bf16(acc_s[2 * g],     ql[ks], kfh);
                mma_bf16(acc_s[2 * g + 1], qh[ks], kfh + 2);
                mma_bf16(acc_s[2 * g + 1], qh[ks], kfl + 2);
                mma_bf16(acc_s[2 * g + 1], ql[ks], kfh + 2);
            }
        }

        // --- causal mask on the diagonal tile
        if (kt == qt) {
            const int rr0 = w * 16 + lr, rr1 = rr0 + 8;
#pragma unroll
            for (int j = 0; j < 16; j++) {
                const int c0 = j * 8 + qp * 2;
                if (c0     > rr0) acc_s[j][0] = -1e30f;
                if (c0 + 1 > rr0) acc_s[j][1] = -1e30f;
                if (c0     > rr1) acc_s[j][2] = -1e30f;
                if (c0 + 1 > rr1) acc_s[j][3] = -1e30f;
            }
        }

        // --- online softmax
        float t0 = -1e30f, t1 = -1e30f;
#pragma unroll
        for (int j = 0; j < 16; j++) {
            t0 = fmaxf(t0, fmaxf(acc_s[j][0], acc_s[j][1]));
            t1 = fmaxf(t1, fmaxf(acc_s[j][2], acc_s[j][3]));
        }
        t0 = fmaxf(t0, __shfl_xor_sync(0xffffffffu, t0, 1));
        t0 = fmaxf(t0, __shfl_xor_sync(0xffffffffu, t0, 2));
        t1 = fmaxf(t1, __shfl_xor_sync(0xffffffffu, t1, 1));
        t1 = fmaxf(t1, __shfl_xor_sync(0xffffffffu, t1, 2));

        const float mn0 = fmaxf(m0, t0);
        const float mn1 = fmaxf(m1, t1);
        const float cr0 = __expf(m0 - mn0);
        const float cr1 = __expf(m1 - mn1);
        m0 = mn0; m1 = mn1;
        l0 *= cr0; l1 *= cr1;
#pragma unroll
        for (int j = 0; j < 8; j++) {
            acc_o[j][0] *= cr0; acc_o[j][1] *= cr0;
            acc_o[j][2] *= cr1; acc_o[j][3] *= cr1;
        }

        // --- P = exp(S - m), pack hi/lo A-fragments
        uint32_t ph[8][4], pl[8][4];
#pragma unroll
        for (int j = 0; j < 16; j++) {
            const float p0 = __expf(acc_s[j][0] - mn0);
            const float p1 = __expf(acc_s[j][1] - mn0);
            const float p2 = __expf(acc_s[j][2] - mn1);
            const float p3 = __expf(acc_s[j][3] - mn1);
            l0 += p0 + p1; l1 += p2 + p3;
            float r0, r1, r2, r3;
            const uint32_t h01 = pack2_res(p0, p1, r0, r1);
            const uint32_t h23 = pack2_res(p2, p3, r2, r3);
            const uint32_t l01 = pack2(r0, r1);
            const uint32_t l23 = pack2(r2, r3);
            const int kc = j >> 1;
            if ((j & 1) == 0) {
                ph[kc][0] = h01; ph[kc][1] = h23;
                pl[kc][0] = l01; pl[kc][1] = l23;
            } else {
                ph[kc][2] = h01; ph[kc][3] = h23;
                pl[kc][2] = l01; pl[kc][3] = l23;
            }
        }

        // --- O += P V (3-term compensated)
#pragma unroll
        for (int kc = 0; kc < 8; kc++) {
            const uint32_t vhb = stVh + ((kc < 4) ? 0u : 8192u);
            const uint32_t vlb = stVl + ((kc < 4) ? 0u : 8192u);
            const uint32_t kb = (uint32_t)((kc & 3) * 32 + b_kb_off);
#pragma unroll
            for (int g = 0; g < 4; g++) {
                int row = g * 16 + b_row_off;
                uint32_t off = (uint32_t)(row * 128) + (kb ^ (uint32_t)((row & 7) << 4));
                uint32_t vfh[4], vfl[4];
                ldsm_x4(vfh[0], vfh[1], vfh[2], vfh[3], vhb + off);
                ldsm_x4(vfl[0], vfl[1], vfl[2], vfl[3], vlb + off);
                mma_bf16(acc_o[2 * g],     ph[kc], vfh);
                mma_bf16(acc_o[2 * g],     ph[kc], vfl);
                mma_bf16(acc_o[2 * g],     pl[kc], vfh);
                mma_bf16(acc_o[2 * g + 1], ph[kc], vfh + 2);
                mma_bf16(acc_o[2 * g + 1], ph[kc], vfl + 2);
                mma_bf16(acc_o[2 * g + 1], pl[kc], vfh + 2);
            }
        }

        // signal stage consumed
        MBAR_ARRIVE(sbase + 40 + 8 * s);

        if (tid == 0 && kt + NSTAGE < ntiles) {
            mbar_wait(sbase + 40 + 8 * s, phs);
            FENCE_ASYNC();
            const int cn = kt + NSTAGE;
            const uint32_t mb = sbase + 16 + 8 * s;
            const uint32_t st = stage0 + s * ATT_STAGE;
            MBAR_EXPECT_TX(mb, ATT_STAGE);
            bulk_g2s(st + 0,     pKh + (size_t)cn * 16384, 16384, mb);
            bulk_g2s(st + 16384, pKl + (size_t)cn * 16384, 16384, mb);
            bulk_g2s(st + 32768, pVh + (size_t)cn * 16384, 16384, mb);
            bulk_g2s(st + 49152, pVl + (size_t)cn * 16384, 16384, mb);
        }
    }

    // --- epilogue: normalize, store fp32
    l0 += __shfl_xor_sync(0xffffffffu, l0, 1);
    l0 += __shfl_xor_sync(0xffffffffu, l0, 2);
    l1 += __shfl_xor_sync(0xffffffffu, l1, 1);
    l1 += __shfl_xor_sync(0xffffffffu, l1, 2);
    const float inv0 = 1.f / l0;
    const float inv1 = 1.f / l1;

    const int row0 = qt * 128 + w * 16 + lr;
    float* y0 = y + ((size_t)b * TT + row0) * CC + h * 64;
    float* y1 = y0 + (size_t)8 * CC;
#pragma unroll
    for (int j = 0; j < 8; j++) {
        const int dc = j * 8 + qp * 2;
        *(float2*)(y0 + dc) = make_float2(acc_o[j][0] * inv0, acc_o[j][1] * inv0);
        *(float2*)(y1 + dc) = make_float2(acc_o[j][2] * inv1, acc_o[j][3] * inv1);
    }
}

// ---------------------------------------------------------------------------
// Launch
// ---------------------------------------------------------------------------
extern "C" void kernel_launch(void* const* d_in, const int* in_sizes, int n_in,
                              void* d_out, int out_size)
{
    const float* x     = (const float*)d_in[0];
    const float* Wqkv  = (const float*)d_in[1];
    const float* bqkv  = (const float*)d_in[2];
    const float* Wproj = (const float*)d_in[3];
    const float* bproj = (const float*)d_in[4];
    float* out = (float*)d_out;

    float *qkv_ptr, *y_ptr;
    __nv_bfloat16 *xh, *xl, *yh, *yl, *wqh, *wql, *wph, *wpl;
    __nv_bfloat16 *aqh, *aql, *akh, *akl, *avh, *avl;
    cudaGetSymbolAddress((void**)&qkv_ptr, g_qkv);
    cudaGetSymbolAddress((void**)&y_ptr, g_y);
    cudaGetSymbolAddress((void**)&xh, g_xh);
    cudaGetSymbolAddress((void**)&xl, g_xl);
    cudaGetSymbolAddress((void**)&yh, g_yh);
    cudaGetSymbolAddress((void**)&yl, g_yl);
    cudaGetSymbolAddress((void**)&wqh, g_wqkvh);
    cudaGetSymbolAddress((void**)&wql, g_wqkvl);
    cudaGetSymbolAddress((void**)&wph, g_wprojh);
    cudaGetSymbolAddress((void**)&wpl, g_wprojl);
    cudaGetSymbolAddress((void**)&aqh, g_qh);
    cudaGetSymbolAddress((void**)&aql, g_ql);
    cudaGetSymbolAddress((void**)&akh, g_kh);
    cudaGetSymbolAddress((void**)&akl, g_kl);
    cudaGetSymbolAddress((void**)&avh, g_vh);
    cudaGetSymbolAddress((void**)&avl, g_vl);

    cudaFuncSetAttribute(gemm_mma_kernel,
                         cudaFuncAttributeMaxDynamicSharedMemorySize, GEMM_SMEM);
    cudaFuncSetAttribute(flash_mma_kernel,
                         cudaFuncAttributeMaxDynamicSharedMemorySize, ATT_SMEM);

    // Prep: split/tile x, transpose/split weights
    split_a_kernel<<<dim3(NKC, MTOK / 128), 256>>>(x, xh, xl);
    transpose_split_kernel<<<dim3(NKC, N_QKV / 128), 256>>>(Wqkv, wqh, wql, N_QKV);
    transpose_split_kernel<<<dim3(NKC, CC / 128), 256>>>(Wproj, wph, wpl, CC);

    // QKV GEMM: [8192 x 3072]
    gemm_mma_kernel<<<dim3(N_QKV / 128, MTOK / 128), 256, GEMM_SMEM>>>(
        xh, xl, wqh, wql, bqkv, qkv_ptr, N_QKV);

    // Attention prep: per-head tiles
    prep_qk_kernel<<<dim3(16, HH, BB), 256>>>(qkv_ptr, aqh, aql, akh, akl);
    prep_vt_kernel<<<dim3(32, HH, BB), 256>>>(qkv_ptr, avh, avl);

    // Flash attention (tensor cores)
    flash_mma_kernel<<<dim3(TT / 128, HH, BB), 256, ATT_SMEM>>>(
        aqh, aql, akh, akl, avh, avl, y_ptr);

    // Split/tile y, then proj GEMM: [8192 x 1024]
    split_a_kernel<<<dim3(NKC, MTOK / 128), 256>>>(y_ptr, yh, yl);
    gemm_mma_kernel<<<dim3(CC / 128, MTOK / 128), 256, GEMM_SMEM>>>(
        yh, yl, wph, wpl, bproj, out, CC);
}

// round 6
// speedup vs baseline: 3.8648x; 1.1055x over previous
#include <cuda_runtime.h>
#include <cuda_bf16.h>
#include <math.h>
#include <stdint.h>

// Problem constants
#define BB 4
#define TT 2048
#define CC 1024
#define HH 16
#define DD 64
#define MTOK (BB * TT)          // 8192 tokens
#define N_QKV (3 * CC)          // 3072
#define NKC 16                  // K chunks: 1024 / 64

// ---------------------------------------------------------------------------
// Scratch (allocation-free rule: __device__ globals)
// ---------------------------------------------------------------------------
__device__ __nv_bfloat16 g_xh[(size_t)MTOK * CC];
__device__ __nv_bfloat16 g_xl[(size_t)MTOK * CC];
__device__ __nv_bfloat16 g_yh[(size_t)MTOK * CC];
__device__ __nv_bfloat16 g_yl[(size_t)MTOK * CC];
__device__ __nv_bfloat16 g_wqkvh[(size_t)N_QKV * CC];
__device__ __nv_bfloat16 g_wqkvl[(size_t)N_QKV * CC];
__device__ __nv_bfloat16 g_wprojh[(size_t)CC * CC];
__device__ __nv_bfloat16 g_wprojl[(size_t)CC * CC];
// attention operand tiles (per (b,h), SW128 swizzled bf16)
__device__ __nv_bfloat16 g_qh[(size_t)BB * HH * 16 * 8192];
__device__ __nv_bfloat16 g_ql[(size_t)BB * HH * 16 * 8192];
__device__ __nv_bfloat16 g_kh[(size_t)BB * HH * 16 * 8192];
__device__ __nv_bfloat16 g_kl[(size_t)BB * HH * 16 * 8192];
__device__ __nv_bfloat16 g_vh[(size_t)BB * HH * 32 * 4096];
__device__ __nv_bfloat16 g_vl[(size_t)BB * HH * 32 * 4096];

// ---------------------------------------------------------------------------
// PTX helpers (base sm_103 target — NO tcgen05)
// ---------------------------------------------------------------------------
__device__ __forceinline__ uint32_t smem_u32(const void* p) {
    uint32_t a;
    asm("{ .reg .u64 t; cvta.to.shared.u64 t, %1; cvt.u32.u64 %0, t; }" : "=r"(a) : "l"(p));
    return a;
}

#define SWZ128(off) ((off) ^ (((off) >> 3) & 0x70))

#define MBAR_INIT(addr, cnt) \
    asm volatile("mbarrier.init.shared.b64 [%0], %1;" :: "r"(addr), "r"(cnt) : "memory")

#define MBAR_EXPECT_TX(addr, bytes) \
    asm volatile("mbarrier.arrive.expect_tx.shared.b64 _, [%0], %1;" :: "r"(addr), "r"(bytes) : "memory")

#define MBAR_ARRIVE(addr) \
    asm volatile("mbarrier.arrive.shared.b64 _, [%0];" :: "r"(addr) : "memory")

__device__ __forceinline__ void mbar_wait(uint32_t mbar, uint32_t parity) {
    uint32_t done;
    asm volatile(
        "{\n\t.reg .pred p;\n\t"
        "mbarrier.try_wait.parity.acquire.cta.shared::cta.b64 p, [%1], %2;\n\t"
        "selp.b32 %0, 1, 0, p;\n\t}"
        : "=r"(done) : "r"(mbar), "r"(parity) : "memory");
    if (!done) {
        asm volatile(
            "{\n\t.reg .pred P1;\n\t"
            "WL_%=:\n\t"
            "mbarrier.try_wait.parity.acquire.cta.shared::cta.b64 P1, [%0], %1, 0x989680;\n\t"
            "@P1 bra.uni WD_%=;\n\t"
            "bra.uni WL_%=;\n\t"
            "WD_%=:\n\t}"
            :: "r"(mbar), "r"(parity) : "memory");
    }
}

__device__ __forceinline__ void bulk_g2s(uint32_t dst, const void* src, uint32_t bytes, uint32_t mbar) {
    asm volatile(
        "cp.async.bulk.shared::cluster.global.mbarrier::complete_tx::bytes [%0], [%1], %2, [%3];"
        :: "r"(dst), "l"(src), "r"(bytes), "r"(mbar) : "memory");
}

#define FENCE_ASYNC() asm volatile("fence.proxy.async.shared::cta;" ::: "memory")

__device__ __forceinline__ void ldsm_x4(uint32_t& r0, uint32_t& r1, uint32_t& r2, uint32_t& r3,
                                        uint32_t addr) {
    asm volatile("ldmatrix.sync.aligned.m8n8.x4.shared.b16 {%0,%1,%2,%3}, [%4];"
                 : "=r"(r0), "=r"(r1), "=r"(r2), "=r"(r3) : "r"(addr));
}

__device__ __forceinline__ void mma_bf16(float* d, const uint32_t* a, const uint32_t* b) {
    asm volatile(
        "mma.sync.aligned.m16n8k16.row.col.f32.bf16.bf16.f32 "
        "{%0,%1,%2,%3}, {%4,%5,%6,%7}, {%8,%9}, {%0,%1,%2,%3};"
        : "+f"(d[0]), "+f"(d[1]), "+f"(d[2]), "+f"(d[3])
        : "r"(a[0]), "r"(a[1]), "r"(a[2]), "r"(a[3]), "r"(b[0]), "r"(b[1]));
}

// ---------------------------------------------------------------------------
// hi/lo bf16 split helpers
// ---------------------------------------------------------------------------
__device__ __forceinline__ void split_bf16(float v, __nv_bfloat16& h, __nv_bfloat16& l) {
    h = __float2bfloat16(v);
    l = __float2bfloat16(v - __bfloat162float(h));
}

__device__ __forceinline__ uint32_t pack2_res(float a, float b, float& ra, float& rb) {
    __nv_bfloat16 ha = __float2bfloat16(a);
    __nv_bfloat16 hb = __float2bfloat16(b);
    ra = a - __bfloat162float(ha);
    rb = b - __bfloat162float(hb);
    return ((uint32_t)__bfloat16_as_ushort(hb) << 16) | (uint32_t)__bfloat16_as_ushort(ha);
}
__device__ __forceinline__ uint32_t pack2(float a, float b) {
    return ((uint32_t)__bfloat16_as_ushort(__float2bfloat16(b)) << 16) |
           (uint32_t)__bfloat16_as_ushort(__float2bfloat16(a));
}

// ---------------------------------------------------------------------------
// Prep 1: split A [M,1024] fp32 -> tiled SW128-swizzled bf16 hi/lo blocks.
// ---------------------------------------------------------------------------
__global__ __launch_bounds__(256) void split_a_kernel(
    const float* __restrict__ in, __nv_bfloat16* __restrict__ oh,
    __nv_bfloat16* __restrict__ ol)
{
    const int kc = blockIdx.x;
    const int mt = blockIdx.y;
    const int t = threadIdx.x;
    const int r = t >> 1;
    const int hh = t & 1;

    const float* src = in + (size_t)(mt * 128 + r) * CC + kc * 64 + hh * 32;
    char* bh = (char*)(oh + ((size_t)mt * NKC + kc) * 8192);
    char* bl = (char*)(ol + ((size_t)mt * NKC + kc) * 8192);

#pragma unroll
    for (int j = 0; j < 4; j++) {
        float4 v0 = ((const float4*)src)[j * 2 + 0];
        float4 v1 = ((const float4*)src)[j * 2 + 1];
        __align__(16) __nv_bfloat16 h8[8], l8[8];
        split_bf16(v0.x, h8[0], l8[0]); split_bf16(v0.y, h8[1], l8[1]);
        split_bf16(v0.z, h8[2], l8[2]); split_bf16(v0.w, h8[3], l8[3]);
        split_bf16(v1.x, h8[4], l8[4]); split_bf16(v1.y, h8[5], l8[5]);
        split_bf16(v1.z, h8[6], l8[6]); split_bf16(v1.w, h8[7], l8[7]);
        uint32_t off = SWZ128((uint32_t)(r * 128 + hh * 64 + j * 16));
        *(uint4*)(bh + off) = *(const uint4*)h8;
        *(uint4*)(bl + off) = *(const uint4*)l8;
    }
}

// ---------------------------------------------------------------------------
// Prep 2: transpose + split W [1024, N] -> W^T tiled bf16 hi/lo blocks.
// ---------------------------------------------------------------------------
__global__ __launch_bounds__(256) void transpose_split_kernel(
    const float* __restrict__ W, __nv_bfloat16* __restrict__ oh,
    __nv_bfloat16* __restrict__ ol, int N)
{
    __shared__ float s[64][128];
    const int kc = blockIdx.x;
    const int nt = blockIdx.y;
    const int t = threadIdx.x;

    for (int idx = t; idx < 64 * 128; idx += 256) {
        int r = idx >> 7, n = idx & 127;
        s[r][n] = W[(size_t)(kc * 64 + r) * N + nt * 128 + n];
    }
    __syncthreads();

    const int np = t & 127;
    const int c0 = (t >> 7) * 4;
    char* bh = (char*)(oh + ((size_t)nt * NKC + kc) * 8192);
    char* bl = (char*)(ol + ((size_t)nt * NKC + kc) * 8192);

#pragma unroll
    for (int c = c0; c < c0 + 4; c++) {
        __align__(16) __nv_bfloat16 h8[8], l8[8];
#pragma unroll
        for (int j = 0; j < 8; j++) {
            split_bf16(s[c * 8 + j][np], h8[j], l8[j]);
        }
        uint32_t off = SWZ128((uint32_t)(np * 128 + c * 16));
        *(uint4*)(bh + off) = *(const uint4*)h8;
        *(uint4*)(bl + off) = *(const uint4*)l8;
    }
}

// ---------------------------------------------------------------------------
// mma.sync GEMM, 3-stage mbarrier pipeline.
// MODE 0: C = A@W + bias (fp32 out).
// MODE 1: QKV fused epilogue — writes Q (scaled)/K/V^T attention tiles
//         (bias + hi/lo split + SW128 swizzle) directly; C unused.
// ---------------------------------------------------------------------------
#define STAGE_BYTES 65536u
#define NSTAGE 3
#define GEMM_SMEM   (1024u + NSTAGE * STAGE_BYTES)

template <int MODE>
__global__ __launch_bounds__(256) void gemm_mma_kernel(
    const __nv_bfloat16* __restrict__ Ah_, const __nv_bfloat16* __restrict__ Al_,
    const __nv_bfloat16* __restrict__ Bh_, const __nv_bfloat16* __restrict__ Bl_,
    const float* __restrict__ bias, float* __restrict__ C, int N,
    __nv_bfloat16* __restrict__ oQh, __nv_bfloat16* __restrict__ oQl,
    __nv_bfloat16* __restrict__ oKh, __nv_bfloat16* __restrict__ oKl,
    __nv_bfloat16* __restrict__ oVh, __nv_bfloat16* __restrict__ oVl)
{
    extern __shared__ __align__(1024) char smem[];
    const uint32_t sbase = smem_u32(smem);
    const int tid = threadIdx.x;
    const int nt = blockIdx.x;
    const int mt = blockIdx.y;

    const uint32_t stage0 = sbase + 1024;

    if (tid == 0) {
#pragma unroll
        for (int s = 0; s < NSTAGE; s++) {
            MBAR_INIT(sbase + 8 + 8 * s, 1);
            MBAR_INIT(sbase + 40 + 8 * s, 256);
        }
    }
    __syncthreads();

    const char* pAh = (const char*)(Ah_ + (size_t)mt * NKC * 8192);
    const char* pAl = (const char*)(Al_ + (size_t)mt * NKC * 8192);
    const char* pBh = (const char*)(Bh_ + (size_t)nt * NKC * 8192);
    const char* pBl = (const char*)(Bl_ + (size_t)nt * NKC * 8192);

    if (tid == 0) {
#pragma unroll
        for (int c = 0; c < NSTAGE; c++) {
            uint32_t st = stage0 + c * STAGE_BYTES;
            uint32_t mb = sbase + 8 + 8 * c;
            MBAR_EXPECT_TX(mb, STAGE_BYTES);
            bulk_g2s(st + 0,     pAh + (size_t)c * 16384, 16384, mb);
            bulk_g2s(st + 16384, pAl + (size_t)c * 16384, 16384, mb);
            bulk_g2s(st + 32768, pBh + (size_t)c * 16384, 16384, mb);
            bulk_g2s(st + 49152, pBl + (size_t)c * 16384, 16384, mb);
        }
    }

    const int w = tid >> 5, l = tid & 31;
    const int mrow = (w >> 2) * 64;
    const int ncol = (w & 3) * 32;
    const int mat = l >> 3;
    const int rin = l & 7;

    const int a_row_off = rin + ((mat & 1) << 3);
    const int a_kb_off  = (mat >> 1) << 4;
    const int b_row_off = rin + ((mat >> 1) << 3);
    const int b_kb_off  = (mat & 1) << 4;

    float acc[4][4][4];
#pragma unroll
    for (int i = 0; i < 4; i++)
#pragma unroll
        for (int j = 0; j < 4; j++)
#pragma unroll
            for (int k = 0; k < 4; k++) acc[i][j][k] = 0.f;

    for (int c = 0; c < NKC; c++) {
        const int s = c % NSTAGE;
        const uint32_t ph = (uint32_t)((c / NSTAGE) & 1);
        mbar_wait(sbase + 8 + 8 * s, ph);

        const uint32_t stAh = stage0 + s * STAGE_BYTES;
        const uint32_t stAl = stAh + 16384;
        const uint32_t stBh = stAh + 32768;
        const uint32_t stBl = stAh + 49152;

#pragma unroll
        for (int ks = 0; ks < 4; ks++) {
            const int kb = ks * 32;
            uint32_t bh[4][2], bl[4][2];
#pragma unroll
            for (int n16 = 0; n16 < 2; n16++) {
                int row = ncol + n16 * 16 + b_row_off;
                uint32_t off = (uint32_t)(row * 128) +
                               (uint32_t)((kb + b_kb_off) ^ ((row & 7) << 4));
                ldsm_x4(bh[n16 * 2][0], bh[n16 * 2][1],
                        bh[n16 * 2 + 1][0], bh[n16 * 2 + 1][1], stBh + off);
                ldsm_x4(bl[n16 * 2][0], bl[n16 * 2][1],
                        bl[n16 * 2 + 1][0], bl[n16 * 2 + 1][1], stBl + off);
            }
#pragma unroll
            for (int m16 = 0; m16 < 4; m16++) {
                int row = mrow + m16 * 16 + a_row_off;
                uint32_t off = (uint32_t)(row * 128) +
                               (uint32_t)((kb + a_kb_off) ^ ((row & 7) << 4));
                uint32_t a[4];
                ldsm_x4(a[0], a[1], a[2], a[3], stAh + off);
#pragma unroll
                for (int n8 = 0; n8 < 4; n8++) mma_bf16(acc[m16][n8], a, bh[n8]);
#pragma unroll
                for (int n8 = 0; n8 < 4; n8++) mma_bf16(acc[m16][n8], a, bl[n8]);
            }
#pragma unroll
            for (int m16 = 0; m16 < 4; m16++) {
                int row = mrow + m16 * 16 + a_row_off;
                uint32_t off = (uint32_t)(row * 128) +
                               (uint32_t)((kb + a_kb_off) ^ ((row & 7) << 4));
                uint32_t a[4];
                ldsm_x4(a[0], a[1], a[2], a[3], stAl + off);
#pragma unroll
                for (int n8 = 0; n8 < 4; n8++) mma_bf16(acc[m16][n8], a, bh[n8]);
            }
        }

        MBAR_ARRIVE(sbase + 40 + 8 * s);

        if (tid == 0 && c + NSTAGE < NKC) {
            mbar_wait(sbase + 40 + 8 * s, ph);
            FENCE_ASYNC();
            const int cn = c + NSTAGE;
            const uint32_t mb = sbase + 8 + 8 * s;
            const uint32_t st = stage0 + s * STAGE_BYTES;
            MBAR_EXPECT_TX(mb, STAGE_BYTES);
            bulk_g2s(st + 0,     pAh + (size_t)cn * 16384, 16384, mb);
            bulk_g2s(st + 16384, pAl + (size_t)cn * 16384, 16384, mb);
            bulk_g2s(st + 32768, pBh + (size_t)cn * 16384, 16384, mb);
            bulk_g2s(st + 49152, pBl + (size_t)cn * 16384, 16384, mb);
        }
    }

    const int lr = l >> 2;
    const int lc = (l & 3) * 2;

    if constexpr (MODE == 0) {
        // Plain fp32 epilogue: C + bias
#pragma unroll
        for (int m16 = 0; m16 < 4; m16++) {
            const size_t r0 = (size_t)(mt * 128 + mrow + m16 * 16 + lr);
            float* c0p = C + r0 * N;
            float* c1p = c0p + (size_t)8 * N;
#pragma unroll
            for (int n8 = 0; n8 < 4; n8++) {
                const int col = nt * 128 + ncol + n8 * 8 + lc;
                const float bx = bias[col], by = bias[col + 1];
                float2 v0 = make_float2(acc[m16][n8][0] + bx, acc[m16][n8][1] + by);
                float2 v1 = make_float2(acc[m16][n8][2] + bx, acc[m16][n8][3] + by);
                *(float2*)(c0p + col) = v0;
                *(float2*)(c1p + col) = v1;
            }
        }
    } else {
        // QKV fused epilogue
        const int b_ = mt >> 4;      // batch
        const int qt_ = mt & 15;     // token tile within batch
        if (nt < 16) {
            // Q (nt<8, scale 1/8) or K (nt in [8,16)) head-tiles
            const bool isQ = (nt < 8);
            __nv_bfloat16* oh = isQ ? oQh : oKh;
            __nv_bfloat16* ol = isQ ? oQl : oKl;
            const float scale = isQ ? 0.125f : 1.0f;
            const int nth = isQ ? nt : nt - 8;
#pragma unroll
            for (int m16 = 0; m16 < 4; m16++) {
                const int rl0 = mrow + m16 * 16 + lr;
#pragma unroll
                for (int n8 = 0; n8 < 4; n8++) {
                    const int c = ncol + n8 * 8 + lc;
                    const int hh2 = c >> 6;
                    const int d = c & 63;
                    const float bx = bias[nt * 128 + c];
                    const float by = bias[nt * 128 + c + 1];
                    const size_t tb = ((size_t)(b_ * HH + 2 * nth + hh2) * 16 + qt_) * 8192;
                    char* th = (char*)(oh + tb);
                    char* tl = (char*)(ol + tb);
                    float r0, r1;
                    const float v00 = (acc[m16][n8][0] + bx) * scale;
                    const float v01 = (acc[m16][n8][1] + by) * scale;
                    const uint32_t h0 = pack2_res(v00, v01, r0, r1);
                    const uint32_t l0 = pack2(r0, r1);
                    const uint32_t off0 = SWZ128((uint32_t)(rl0 * 128 + d * 2));
                    *(uint32_t*)(th + off0) = h0;
                    *(uint32_t*)(tl + off0) = l0;
                    const float v10 = (acc[m16][n8][2] + bx) * scale;
                    const float v11 = (acc[m16][n8][3] + by) * scale;
                    const uint32_t h1 = pack2_res(v10, v11, r0, r1);
                    const uint32_t l1 = pack2(r0, r1);
                    const uint32_t off1 = SWZ128((uint32_t)((rl0 + 8) * 128 + d * 2));
                    *(uint32_t*)(th + off1) = h1;
                    *(uint32_t*)(tl + off1) = l1;
                }
            }
        } else {
            // V: transpose through smem (stage buffers free now), write V^T tiles
            float* sf = (float*)(smem + 1024);  // [128][129] fp32
            __syncthreads();
#pragma unroll
            for (int m16 = 0; m16 < 4; m16++) {
                const int rl0 = mrow + m16 * 16 + lr;
#pragma unroll
                for (int n8 = 0; n8 < 4; n8++) {
                    const int c = ncol + n8 * 8 + lc;
                    const float bx = bias[nt * 128 + c];
                    const float by = bias[nt * 128 + c + 1];
                    sf[rl0 * 129 + c]           = acc[m16][n8][0] + bx;
                    sf[rl0 * 129 + c + 1]       = acc[m16][n8][1] + by;
                    sf[(rl0 + 8) * 129 + c]     = acc[m16][n8][2] + bx;
                    sf[(rl0 + 8) * 129 + c + 1] = acc[m16][n8][3] + by;
                }
            }
            __syncthreads();
            const int ntv = nt - 16;
            for (int it = tid; it < 2048; it += 256) {
                const int hh2 = it >> 10;
                const int rem = it & 1023;
                const int kt2loc = rem >> 9;
                const int d = (rem >> 3) & 63;
                const int oct = rem & 7;
                __align__(16) __nv_bfloat16 h8[8], l8[8];
#pragma unroll
                for (int e = 0; e < 8; e++) {
                    const int key = oct * 8 + e;
                    split_bf16(sf[(kt2loc * 64 + key) * 129 + hh2 * 64 + d], h8[e], l8[e]);
                }
                const size_t tb =
                    ((size_t)(b_ * HH + 2 * ntv + hh2) * 32 + qt_ * 2 + kt2loc) * 4096;
                const uint32_t off = SWZ128((uint32_t)(d * 128 + oct * 16));
                *(uint4*)((char*)(oVh + tb) + off) = *(const uint4*)h8;
                *(uint4*)((char*)(oVl + tb) + off) = *(const uint4*)l8;
            }
        }
    }
}

// ---------------------------------------------------------------------------
// Flash attention on mma.sync, 3-stage K/V pipeline; fused split-tile epilogue
// writing y directly as A-operand tiles for the proj GEMM.
// ---------------------------------------------------------------------------
#define ATT_STAGE 65536u
#define ATT_SMEM  (1024u + 32768u + NSTAGE * ATT_STAGE)

__global__ __launch_bounds__(256) void flash_mma_kernel(
    const __nv_bfloat16* __restrict__ Qh_, const __nv_bfloat16* __restrict__ Ql_,
    const __nv_bfloat16* __restrict__ Kh_, const __nv_bfloat16* __restrict__ Kl_,
    const __nv_bfloat16* __restrict__ Vh_, const __nv_bfloat16* __restrict__ Vl_,
    __nv_bfloat16* __restrict__ oYh, __nv_bfloat16* __restrict__ oYl)
{
    extern __shared__ __align__(1024) char smem[];
    const uint32_t sbase = smem_u32(smem);
    const int tid = threadIdx.x;
    const int qt = (int)gridDim.x - 1 - (int)blockIdx.x;   // big tiles first
    const int h  = blockIdx.y;
    const int b  = blockIdx.z;

    const uint32_t mbq = sbase + 8;
    const uint32_t sQh = sbase + 1024;
    const uint32_t sQl = sQh + 16384;
    const uint32_t stage0 = sQl + 16384;

    if (tid == 0) {
        MBAR_INIT(mbq, 1);
#pragma unroll
        for (int s = 0; s < NSTAGE; s++) {
            MBAR_INIT(sbase + 16 + 8 * s, 1);
            MBAR_INIT(sbase + 40 + 8 * s, 256);
        }
    }
    __syncthreads();

    const int bh_idx = b * HH + h;
    const char* pQh = (const char*)(Qh_ + ((size_t)bh_idx * 16 + qt) * 8192);
    const char* pQl = (const char*)(Ql_ + ((size_t)bh_idx * 16 + qt) * 8192);
    const char* pKh = (const char*)(Kh_ + (size_t)bh_idx * 16 * 8192);
    const char* pKl = (const char*)(Kl_ + (size_t)bh_idx * 16 * 8192);
    const char* pVh = (const char*)(Vh_ + (size_t)bh_idx * 32 * 4096);
    const char* pVl = (const char*)(Vl_ + (size_t)bh_idx * 32 * 4096);

    const int ntiles = qt + 1;

    if (tid == 0) {
        MBAR_EXPECT_TX(mbq, 32768);
        bulk_g2s(sQh, pQh, 16384, mbq);
        bulk_g2s(sQl, pQl, 16384, mbq);
        const int npro = ntiles < NSTAGE ? ntiles : NSTAGE;
        for (int c = 0; c < npro; c++) {
            uint32_t st = stage0 + c * ATT_STAGE;
            uint32_t mb = sbase + 16 + 8 * c;
            MBAR_EXPECT_TX(mb, ATT_STAGE);
            bulk_g2s(st + 0,     pKh + (size_t)c * 16384, 16384, mb);
            bulk_g2s(st + 16384, pKl + (size_t)c * 16384, 16384, mb);
            bulk_g2s(st + 32768, pVh + (size_t)c * 16384, 16384, mb);
            bulk_g2s(st + 49152, pVl + (size_t)c * 16384, 16384, mb);
        }
    }

    const int w = tid >> 5, l = tid & 31;
    const int mat = l >> 3, rin = l & 7;
    const int a_row_off = rin + ((mat & 1) << 3);
    const int a_kb_off  = (mat >> 1) << 4;
    const int b_row_off = rin + ((mat >> 1) << 3);
    const int b_kb_off  = (mat & 1) << 4;
    const int lr = l >> 2, qp = l & 3;

    // Q fragments (persist)
    mbar_wait(mbq, 0);
    uint32_t qh[4][4], ql[4][4];
#pragma unroll
    for (int ks = 0; ks < 4; ks++) {
        int row = w * 16 + a_row_off;
        uint32_t off = (uint32_t)(row * 128) +
                       (uint32_t)((ks * 32 + a_kb_off) ^ ((row & 7) << 4));
        ldsm_x4(qh[ks][0], qh[ks][1], qh[ks][2], qh[ks][3], sQh + off);
        ldsm_x4(ql[ks][0], ql[ks][1], ql[ks][2], ql[ks][3], sQl + off);
    }

    float acc_o[8][4];
#pragma unroll
    for (int j = 0; j < 8; j++)
#pragma unroll
        for (int e = 0; e < 4; e++) acc_o[j][e] = 0.f;
    float m0 = -1e30f, m1 = -1e30f, l0 = 0.f, l1 = 0.f;

    for (int kt = 0; kt < ntiles; kt++) {
        const int s = kt % NSTAGE;
        const uint32_t phs = (uint32_t)((kt / NSTAGE) & 1);
        mbar_wait(sbase + 16 + 8 * s, phs);
        const uint32_t stKh = stage0 + s * ATT_STAGE;
        const uint32_t stKl = stKh + 16384;
        const uint32_t stVh = stKh + 32768;
        const uint32_t stVl = stKh + 49152;

        // --- S = Q K^T (3-term compensated)
        float acc_s[16][4];
#pragma unroll
        for (int j = 0; j < 16; j++)
#pragma unroll
            for (int e = 0; e < 4; e++) acc_s[j][e] = 0.f;

#pragma unroll
        for (int ks = 0; ks < 4; ks++) {
            const uint32_t kb = (uint32_t)(ks * 32 + b_kb_off);
#pragma unroll
            for (int g = 0; g < 8; g++) {
                int row = g * 16 + b_row_off;
                uint32_t off = (uint32_t)(row * 128) + (kb ^ (uint32_t)((row & 7) << 4));
                uint32_t kfh[4], kfl[4];
                ldsm_x4(kfh[0], kfh[1], kfh[2], kfh[3], stKh + off);
                ldsm_x4(kfl[0], kfl[1], kfl[2], kfl[3], stKl + off);
                mma_bf16(acc_s[2 * g],     qh[ks], kfh);
                mma_bf16(acc_s[2 * g],     qh[ks], kfl);
                mma_bf16(acc_s[2 * g],     ql[ks], kfh);
                mma_bf16(acc_s[2 * g + 1], qh[ks], kfh + 2);
                mma_bf16(acc_s[2 * g + 1], qh[ks], kfl + 2);
                mma_bf16(acc_s[2 * g + 1], ql[ks], kfh + 2);
            }
        }

        // --- causal mask on the diagonal tile
        if (kt == qt) {
            const int rr0 = w * 16 + lr, rr1 = rr0 + 8;
#pragma unroll
            for (int j = 0; j < 16; j++) {
                const int c0 = j * 8 + qp * 2;
                if (c0     > rr0) acc_s[j][0] = -1e30f;
                if (c0 + 1 > rr0) acc_s[j][1] = -1e30f;
                if (c0     > rr1) acc_s[j][2] = -1e30f;
                if (c0 + 1 > rr1) acc_s[j][3] = -1e30f;
            }
        }

        // --- online softmax
        float t0 = -1e30f, t1 = -1e30f;
#pragma unroll
        for (int j = 0; j < 16; j++) {
            t0 = fmaxf(t0, fmaxf(acc_s[j][0], acc_s[j][1]));
            t1 = fmaxf(t1, fmaxf(acc_s[j][2], acc_s[j][3]));
        }
        t0 = fmaxf(t0, __shfl_xor_sync(0xffffffffu, t0, 1));
        t0 = fmaxf(t0, __shfl_xor_sync(0xffffffffu, t0, 2));
        t1 = fmaxf(t1, __shfl_xor_sync(0xffffffffu, t1, 1));
        t1 = fmaxf(t1, __shfl_xor_sync(0xffffffffu, t1, 2));

        const float mn0 = fmaxf(m0, t0);
        const float mn1 = fmaxf(m1, t1);
        const float cr0 = __expf(m0 - mn0);
        const float cr1 = __expf(m1 - mn1);
        m0 = mn0; m1 = mn1;
        l0 *= cr0; l1 *= cr1;
#pragma unroll
        for (int j = 0; j < 8; j++) {
            acc_o[j][0] *= cr0; acc_o[j][1] *= cr0;
            acc_o[j][2] *= cr1; acc_o[j][3] *= cr1;
        }

        // --- P = exp(S - m), pack hi/lo A-fragments
        uint32_t ph[8][4], pl[8][4];
#pragma unroll
        for (int j = 0; j < 16; j++) {
            const float p0 = __expf(acc_s[j][0] - mn0);
            const float p1 = __expf(acc_s[j][1] - mn0);
            const float p2 = __expf(acc_s[j][2] - mn1);
            const float p3 = __expf(acc_s[j][3] - mn1);
            l0 += p0 + p1; l1 += p2 + p3;
            float r0, r1, r2, r3;
            const uint32_t h01 = pack2_res(p0, p1, r0, r1);
            const uint32_t h23 = pack2_res(p2, p3, r2, r3);
            const uint32_t l01 = pack2(r0, r1);
            const uint32_t l23 = pack2(r2, r3);
            const int kc = j >> 1;
            if ((j & 1) == 0) {
                ph[kc][0] = h01; ph[kc][1] = h23;
                pl[kc][0] = l01; pl[kc][1] = l23;
            } else {
                ph[kc][2] = h01; ph[kc][3] = h23;
                pl[kc][2] = l01; pl[kc][3] = l23;
            }
        }

        // --- O += P V (3-term compensated)
#pragma unroll
        for (int kc = 0; kc < 8; kc++) {
            const uint32_t vhb = stVh + ((kc < 4) ? 0u : 8192u);
            const uint32_t vlb = stVl + ((kc < 4) ? 0u : 8192u);
            const uint32_t kb = (uint32_t)((kc & 3) * 32 + b_kb_off);
#pragma unroll
            for (int g = 0; g < 4; g++) {
                int row = g * 16 + b_row_off;
                uint32_t off = (uint32_t)(row * 128) + (kb ^ (uint32_t)((row & 7) << 4));
                uint32_t vfh[4], vfl[4];
                ldsm_x4(vfh[0], vfh[1], vfh[2], vfh[3], vhb + off);
                ldsm_x4(vfl[0], vfl[1], vfl[2], vfl[3], vlb + off);
                mma_bf16(acc_o[2 * g],     ph[kc], vfh);
                mma_bf16(acc_o[2 * g],     ph[kc], vfl);
                mma_bf16(acc_o[2 * g],     pl[kc], vfh);
                mma_bf16(acc_o[2 * g + 1], ph[kc], vfh + 2);
                mma_bf16(acc_o[2 * g + 1], ph[kc], vfl + 2);
                mma_bf16(acc_o[2 * g + 1], pl[kc], vfh + 2);
            }
        }

        MBAR_ARRIVE(sbase + 40 + 8 * s);

        if (tid == 0 && kt + NSTAGE < ntiles) {
            mbar_wait(sbase + 40 + 8 * s, phs);
            FENCE_ASYNC();
            const int cn = kt + NSTAGE;
            const uint32_t mb = sbase + 16 + 8 * s;
            const uint32_t st = stage0 + s * ATT_STAGE;
            MBAR_EXPECT_TX(mb, ATT_STAGE);
            bulk_g2s(st + 0,     pKh + (size_t)cn * 16384, 16384, mb);
            bulk_g2s(st + 16384, pKl + (size_t)cn * 16384, 16384, mb);
            bulk_g2s(st + 32768, pVh + (size_t)cn * 16384, 16384, mb);
            bulk_g2s(st + 49152, pVl + (size_t)cn * 16384, 16384, mb);
        }
    }

    // --- epilogue: normalize, split hi/lo, write y directly as proj A-tiles
    l0 += __shfl_xor_sync(0xffffffffu, l0, 1);
    l0 += __shfl_xor_sync(0xffffffffu, l0, 2);
    l1 += __shfl_xor_sync(0xffffffffu, l1, 1);
    l1 += __shfl_xor_sync(0xffffffffu, l1, 2);
    const float inv0 = 1.f / l0;
    const float inv1 = 1.f / l1;

    const size_t tb = ((size_t)(b * 16 + qt) * NKC + h) * 8192;
    char* th = (char*)(oYh + tb);
    char* tl = (char*)(oYl + tb);
    const int rl0 = w * 16 + lr;
#pragma unroll
    for (int j = 0; j < 8; j++) {
        const int dc = j * 8 + qp * 2;
        float r0, r1;
        const uint32_t h0 = pack2_res(acc_o[j][0] * inv0, acc_o[j][1] * inv0, r0, r1);
        const uint32_t lo0 = pack2(r0, r1);
        const uint32_t off0 = SWZ128((uint32_t)(rl0 * 128 + dc * 2));
        *(uint32_t*)(th + off0) = h0;
        *(uint32_t*)(tl + off0) = lo0;
        const uint32_t h1 = pack2_res(acc_o[j][2] * inv1, acc_o[j][3] * inv1, r0, r1);
        const uint32_t lo1 = pack2(r0, r1);
        const uint32_t off1 = SWZ128((uint32_t)((rl0 + 8) * 128 + dc * 2));
        *(uint32_t*)(th + off1) = h1;
        *(uint32_t*)(tl + off1) = lo1;
    }
}

// ---------------------------------------------------------------------------
// Launch
// ---------------------------------------------------------------------------
extern "C" void kernel_launch(void* const* d_in, const int* in_sizes, int n_in,
                              void* d_out, int out_size)
{
    const float* x     = (const float*)d_in[0];
    const float* Wqkv  = (const float*)d_in[1];
    const float* bqkv  = (const float*)d_in[2];
    const float* Wproj = (const float*)d_in[3];
    const float* bproj = (const float*)d_in[4];
    float* out = (float*)d_out;

    __nv_bfloat16 *xh, *xl, *yh, *yl, *wqh, *wql, *wph, *wpl;
    __nv_bfloat16 *aqh, *aql, *akh, *akl, *avh, *avl;
    cudaGetSymbolAddress((void**)&xh, g_xh);
    cudaGetSymbolAddress((void**)&xl, g_xl);
    cudaGetSymbolAddress((void**)&yh, g_yh);
    cudaGetSymbolAddress((void**)&yl, g_yl);
    cudaGetSymbolAddress((void**)&wqh, g_wqkvh);
    cudaGetSymbolAddress((void**)&wql, g_wqkvl);
    cudaGetSymbolAddress((void**)&wph, g_wprojh);
    cudaGetSymbolAddress((void**)&wpl, g_wprojl);
    cudaGetSymbolAddress((void**)&aqh, g_qh);
    cudaGetSymbolAddress((void**)&aql, g_ql);
    cudaGetSymbolAddress((void**)&akh, g_kh);
    cudaGetSymbolAddress((void**)&akl, g_kl);
    cudaGetSymbolAddress((void**)&avh, g_vh);
    cudaGetSymbolAddress((void**)&avl, g_vl);

    cudaFuncSetAttribute(gemm_mma_kernel<0>,
                         cudaFuncAttributeMaxDynamicSharedMemorySize, GEMM_SMEM);
    cudaFuncSetAttribute(gemm_mma_kernel<1>,
                         cudaFuncAttributeMaxDynamicSharedMemorySize, GEMM_SMEM);
    cudaFuncSetAttribute(flash_mma_kernel,
                         cudaFuncAttributeMaxDynamicSharedMemorySize, ATT_SMEM);

    // Prep: split/tile x, transpose/split weights
    split_a_kernel<<<dim3(NKC, MTOK / 128), 256>>>(x, xh, xl);
    transpose_split_kernel<<<dim3(NKC, N_QKV / 128), 256>>>(Wqkv, wqh, wql, N_QKV);
    transpose_split_kernel<<<dim3(NKC, CC / 128), 256>>>(Wproj, wph, wpl, CC);

    // QKV GEMM with fused Q/K/V-tile epilogue
    gemm_mma_kernel<1><<<dim3(N_QKV / 128, MTOK / 128), 256, GEMM_SMEM>>>(
        xh, xl, wqh, wql, bqkv, nullptr, N_QKV,
        aqh, aql, akh, akl, avh, avl);

    // Flash attention (tensor cores) -> split y tiles
    flash_mma_kernel<<<dim3(TT / 128, HH, BB), 256, ATT_SMEM>>>(
        aqh, aql, akh, akl, avh, avl, yh, yl);

    // Proj GEMM: out = y @ Wproj + bproj (fp32 epilogue)
    gemm_mma_kernel<0><<<dim3(CC / 128, MTOK / 128), 256, GEMM_SMEM>>>(
        yh, yl, wph, wpl, bproj, out, CC,
        nullptr, nullptr, nullptr, nullptr, nullptr, nullptr);
}

// round 7
// speedup vs baseline: 4.1256x; 1.0675x over previous
#include <cuda_runtime.h>
#include <cuda_bf16.h>
#include <math.h>
#include <stdint.h>

// Problem constants
#define BB 4
#define TT 2048
#define CC 1024
#define HH 16
#define DD 64
#define MTOK (BB * TT)          // 8192 tokens
#define N_QKV (3 * CC)          // 3072
#define NKC 16                  // K chunks: 1024 / 64

#define LOG2E 1.4426950408889634f

// ---------------------------------------------------------------------------
// Scratch (allocation-free rule: __device__ globals)
// ---------------------------------------------------------------------------
__device__ __nv_bfloat16 g_xh[(size_t)MTOK * CC];
__device__ __nv_bfloat16 g_xl[(size_t)MTOK * CC];
__device__ __nv_bfloat16 g_yh[(size_t)MTOK * CC];
__device__ __nv_bfloat16 g_yl[(size_t)MTOK * CC];
__device__ __nv_bfloat16 g_wqkvh[(size_t)N_QKV * CC];
__device__ __nv_bfloat16 g_wqkvl[(size_t)N_QKV * CC];
__device__ __nv_bfloat16 g_wprojh[(size_t)CC * CC];
__device__ __nv_bfloat16 g_wprojl[(size_t)CC * CC];
// attention operand tiles (per (b,h), SW128 swizzled bf16)
__device__ __nv_bfloat16 g_qh[(size_t)BB * HH * 16 * 8192];
__device__ __nv_bfloat16 g_ql[(size_t)BB * HH * 16 * 8192];
__device__ __nv_bfloat16 g_kh[(size_t)BB * HH * 16 * 8192];
__device__ __nv_bfloat16 g_kl[(size_t)BB * HH * 16 * 8192];
__device__ __nv_bfloat16 g_vh[(size_t)BB * HH * 32 * 4096];
__device__ __nv_bfloat16 g_vl[(size_t)BB * HH * 32 * 4096];

// ---------------------------------------------------------------------------
// PTX helpers (base sm_103 target — NO tcgen05)
// ---------------------------------------------------------------------------
__device__ __forceinline__ uint32_t smem_u32(const void* p) {
    uint32_t a;
    asm("{ .reg .u64 t; cvta.to.shared.u64 t, %1; cvt.u32.u64 %0, t; }" : "=r"(a) : "l"(p));
    return a;
}

#define SWZ128(off) ((off) ^ (((off) >> 3) & 0x70))

#define MBAR_INIT(addr, cnt) \
    asm volatile("mbarrier.init.shared.b64 [%0], %1;" :: "r"(addr), "r"(cnt) : "memory")

#define MBAR_EXPECT_TX(addr, bytes) \
    asm volatile("mbarrier.arrive.expect_tx.shared.b64 _, [%0], %1;" :: "r"(addr), "r"(bytes) : "memory")

#define MBAR_ARRIVE(addr) \
    asm volatile("mbarrier.arrive.shared.b64 _, [%0];" :: "r"(addr) : "memory")

__device__ __forceinline__ void mbar_wait(uint32_t mbar, uint32_t parity) {
    uint32_t done;
    asm volatile(
        "{\n\t.reg .pred p;\n\t"
        "mbarrier.try_wait.parity.acquire.cta.shared::cta.b64 p, [%1], %2;\n\t"
        "selp.b32 %0, 1, 0, p;\n\t}"
        : "=r"(done) : "r"(mbar), "r"(parity) : "memory");
    if (!done) {
        asm volatile(
            "{\n\t.reg .pred P1;\n\t"
            "WL_%=:\n\t"
            "mbarrier.try_wait.parity.acquire.cta.shared::cta.b64 P1, [%0], %1, 0x989680;\n\t"
            "@P1 bra.uni WD_%=;\n\t"
            "bra.uni WL_%=;\n\t"
            "WD_%=:\n\t}"
            :: "r"(mbar), "r"(parity) : "memory");
    }
}

__device__ __forceinline__ void bulk_g2s(uint32_t dst, const void* src, uint32_t bytes, uint32_t mbar) {
    asm volatile(
        "cp.async.bulk.shared::cluster.global.mbarrier::complete_tx::bytes [%0], [%1], %2, [%3];"
        :: "r"(dst), "l"(src), "r"(bytes), "r"(mbar) : "memory");
}

#define FENCE_ASYNC() asm volatile("fence.proxy.async.shared::cta;" ::: "memory")

__device__ __forceinline__ void ldsm_x4(uint32_t& r0, uint32_t& r1, uint32_t& r2, uint32_t& r3,
                                        uint32_t addr) {
    asm volatile("ldmatrix.sync.aligned.m8n8.x4.shared.b16 {%0,%1,%2,%3}, [%4];"
                 : "=r"(r0), "=r"(r1), "=r"(r2), "=r"(r3) : "r"(addr));
}

__device__ __forceinline__ void mma_bf16(float* d, const uint32_t* a, const uint32_t* b) {
    asm volatile(
        "mma.sync.aligned.m16n8k16.row.col.f32.bf16.bf16.f32 "
        "{%0,%1,%2,%3}, {%4,%5,%6,%7}, {%8,%9}, {%0,%1,%2,%3};"
        : "+f"(d[0]), "+f"(d[1]), "+f"(d[2]), "+f"(d[3])
        : "r"(a[0]), "r"(a[1]), "r"(a[2]), "r"(a[3]), "r"(b[0]), "r"(b[1]));
}

__device__ __forceinline__ float ex2(float x) {
    float r;
    asm("ex2.approx.f32 %0, %1;" : "=f"(r) : "f"(x));
    return r;
}

// ---------------------------------------------------------------------------
// hi/lo bf16 split helpers
// ---------------------------------------------------------------------------
__device__ __forceinline__ void split_bf16(float v, __nv_bfloat16& h, __nv_bfloat16& l) {
    h = __float2bfloat16(v);
    l = __float2bfloat16(v - __bfloat162float(h));
}

// pack (lo=a, hi=b) into bf16x2, return residuals via shift-trick
__device__ __forceinline__ uint32_t packres(float a, float b, float& ra, float& rb) {
    uint32_t h;
    asm("cvt.rn.bf16x2.f32 %0, %1, %2;" : "=r"(h) : "f"(b), "f"(a));
    ra = a - __uint_as_float(h << 16);
    rb = b - __uint_as_float(h & 0xffff0000u);
    return h;
}
__device__ __forceinline__ uint32_t packlo(float a, float b) {
    uint32_t h;
    asm("cvt.rn.bf16x2.f32 %0, %1, %2;" : "=r"(h) : "f"(b), "f"(a));
    return h;
}

// ---------------------------------------------------------------------------
// Combined prep kernel: dispatches on flattened block id.
//  [0,1024):     split x  -> xh/xl tiles
//  [1024,1408):  transpose+split Wqkv
//  [1408,1536):  transpose+split Wproj
// ---------------------------------------------------------------------------
__global__ __launch_bounds__(256) void prep_all_kernel(
    const float* __restrict__ x, __nv_bfloat16* __restrict__ xh, __nv_bfloat16* __restrict__ xl,
    const float* __restrict__ Wq, __nv_bfloat16* __restrict__ wqh, __nv_bfloat16* __restrict__ wql,
    const float* __restrict__ Wp, __nv_bfloat16* __restrict__ wph, __nv_bfloat16* __restrict__ wpl)
{
    __shared__ float s[64][128];
    const int id = blockIdx.x;
    const int t = threadIdx.x;

    if (id < 1024) {
        // split A
        const int kc = id & 15;
        const int mt = id >> 4;
        const int r = t >> 1;
        const int hh = t & 1;
        const float* src = x + (size_t)(mt * 128 + r) * CC + kc * 64 + hh * 32;
        char* bh = (char*)(xh + ((size_t)mt * NKC + kc) * 8192);
        char* bl = (char*)(xl + ((size_t)mt * NKC + kc) * 8192);
#pragma unroll
        for (int j = 0; j < 4; j++) {
            float4 v0 = ((const float4*)src)[j * 2 + 0];
            float4 v1 = ((const float4*)src)[j * 2 + 1];
            __align__(16) __nv_bfloat16 h8[8], l8[8];
            split_bf16(v0.x, h8[0], l8[0]); split_bf16(v0.y, h8[1], l8[1]);
            split_bf16(v0.z, h8[2], l8[2]); split_bf16(v0.w, h8[3], l8[3]);
            split_bf16(v1.x, h8[4], l8[4]); split_bf16(v1.y, h8[5], l8[5]);
            split_bf16(v1.z, h8[6], l8[6]); split_bf16(v1.w, h8[7], l8[7]);
            uint32_t off = SWZ128((uint32_t)(r * 128 + hh * 64 + j * 16));
            *(uint4*)(bh + off) = *(const uint4*)h8;
            *(uint4*)(bl + off) = *(const uint4*)l8;
        }
        return;
    }

    const bool isQ = (id < 1408);
    const int v = isQ ? (id - 1024) : (id - 1408);
    const int kc = v & 15;
    const int nt = v >> 4;
    const float* W = isQ ? Wq : Wp;
    __nv_bfloat16* oh = isQ ? wqh : wph;
    __nv_bfloat16* ol = isQ ? wql : wpl;
    const int N = isQ ? N_QKV : CC;

    for (int idx = t; idx < 64 * 128; idx += 256) {
        int r = idx >> 7, n = idx & 127;
        s[r][n] = W[(size_t)(kc * 64 + r) * N + nt * 128 + n];
    }
    __syncthreads();

    const int np = t & 127;
    const int c0 = (t >> 7) * 4;
    char* bh = (char*)(oh + ((size_t)nt * NKC + kc) * 8192);
    char* bl = (char*)(ol + ((size_t)nt * NKC + kc) * 8192);

#pragma unroll
    for (int c = c0; c < c0 + 4; c++) {
        __align__(16) __nv_bfloat16 h8[8], l8[8];
#pragma unroll
        for (int j = 0; j < 8; j++) {
            split_bf16(s[c * 8 + j][np], h8[j], l8[j]);
        }
        uint32_t off = SWZ128((uint32_t)(np * 128 + c * 16));
        *(uint4*)(bh + off) = *(const uint4*)h8;
        *(uint4*)(bl + off) = *(const uint4*)l8;
    }
}

// ---------------------------------------------------------------------------
// mma.sync GEMM, CTA 128x256, warps 64x64, BK=64, 2-stage mbarrier pipeline.
// MODE 0: C = A@W + bias (fp32).  MODE 1: QKV fused epilogue (Q scaled by
// 0.125*log2e for exp2-softmax; K/V^T tiles written swizzled hi/lo).
// ---------------------------------------------------------------------------
#define G_STAGE 98304u      // Ah16K Al16K Bh32K Bl32K
#define G_NSTAGE 2
#define GEMM_SMEM (1024u + G_NSTAGE * G_STAGE)

template <int MODE>
__global__ __launch_bounds__(256) void gemm_mma_kernel(
    const __nv_bfloat16* __restrict__ Ah_, const __nv_bfloat16* __restrict__ Al_,
    const __nv_bfloat16* __restrict__ Bh_, const __nv_bfloat16* __restrict__ Bl_,
    const float* __restrict__ bias, float* __restrict__ C, int N,
    __nv_bfloat16* __restrict__ oQh, __nv_bfloat16* __restrict__ oQl,
    __nv_bfloat16* __restrict__ oKh, __nv_bfloat16* __restrict__ oKl,
    __nv_bfloat16* __restrict__ oVh, __nv_bfloat16* __restrict__ oVl)
{
    extern __shared__ __align__(1024) char smem[];
    const uint32_t sbase = smem_u32(smem);
    const int tid = threadIdx.x;
    const int nt = blockIdx.x;
    const int mt = blockIdx.y;

    const uint32_t stage0 = sbase + 1024;

    if (tid == 0) {
#pragma unroll
        for (int s = 0; s < G_NSTAGE; s++) {
            MBAR_INIT(sbase + 8 + 8 * s, 1);
            MBAR_INIT(sbase + 40 + 8 * s, 256);
        }
    }
    __syncthreads();

    const char* pAh = (const char*)(Ah_ + (size_t)mt * NKC * 8192);
    const char* pAl = (const char*)(Al_ + (size_t)mt * NKC * 8192);
    const char* pBh0 = (const char*)(Bh_ + (size_t)(2 * nt) * NKC * 8192);
    const char* pBh1 = (const char*)(Bh_ + (size_t)(2 * nt + 1) * NKC * 8192);
    const char* pBl0 = (const char*)(Bl_ + (size_t)(2 * nt) * NKC * 8192);
    const char* pBl1 = (const char*)(Bl_ + (size_t)(2 * nt + 1) * NKC * 8192);

    if (tid == 0) {
#pragma unroll
        for (int c = 0; c < G_NSTAGE; c++) {
            uint32_t st = stage0 + c * G_STAGE;
            uint32_t mb = sbase + 8 + 8 * c;
            MBAR_EXPECT_TX(mb, G_STAGE);
            bulk_g2s(st + 0,     pAh  + (size_t)c * 16384, 16384, mb);
            bulk_g2s(st + 16384, pAl  + (size_t)c * 16384, 16384, mb);
            bulk_g2s(st + 32768, pBh0 + (size_t)c * 16384, 16384, mb);
            bulk_g2s(st + 49152, pBh1 + (size_t)c * 16384, 16384, mb);
            bulk_g2s(st + 65536, pBl0 + (size_t)c * 16384, 16384, mb);
            bulk_g2s(st + 81920, pBl1 + (size_t)c * 16384, 16384, mb);
        }
    }

    const int w = tid >> 5, l = tid & 31;
    const int mrow = (w >> 2) * 64;      // 0 or 64
    const int ncol = (w & 3) * 64;       // 0,64,128,192
    const int mat = l >> 3;
    const int rin = l & 7;

    const int a_row_off = rin + ((mat & 1) << 3);
    const int a_kb_off  = (mat >> 1) << 4;
    const int b_row_off = rin + ((mat >> 1) << 3);
    const int b_kb_off  = (mat & 1) << 4;

    float acc[4][8][4];
#pragma unroll
    for (int i = 0; i < 4; i++)
#pragma unroll
        for (int j = 0; j < 8; j++)
#pragma unroll
            for (int k = 0; k < 4; k++) acc[i][j][k] = 0.f;

    for (int c = 0; c < NKC; c++) {
        const int s = c & 1;
        const uint32_t ph = (uint32_t)((c >> 1) & 1);
        mbar_wait(sbase + 8 + 8 * s, ph);

        const uint32_t stAh = stage0 + s * G_STAGE;
        const uint32_t stAl = stAh + 16384;
        const uint32_t stBh = stAh + 32768;   // 256 rows x 128B contiguous
        const uint32_t stBl = stAh + 65536;

#pragma unroll
        for (int ks = 0; ks < 4; ks++) {
            const int kb = ks * 32;
            uint32_t bh[8][2], bl[8][2];
#pragma unroll
            for (int n16 = 0; n16 < 4; n16++) {
                int row = ncol + n16 * 16 + b_row_off;
                uint32_t off = (uint32_t)(row * 128) +
                               (uint32_t)((kb + b_kb_off) ^ ((row & 7) << 4));
                ldsm_x4(bh[n16 * 2][0], bh[n16 * 2][1],
                        bh[n16 * 2 + 1][0], bh[n16 * 2 + 1][1], stBh + off);
                ldsm_x4(bl[n16 * 2][0], bl[n16 * 2][1],
                        bl[n16 * 2 + 1][0], bl[n16 * 2 + 1][1], stBl + off);
            }
#pragma unroll
            for (int m16 = 0; m16 < 4; m16++) {
                int row = mrow + m16 * 16 + a_row_off;
                uint32_t off = (uint32_t)(row * 128) +
                               (uint32_t)((kb + a_kb_off) ^ ((row & 7) << 4));
                uint32_t a[4];
                ldsm_x4(a[0], a[1], a[2], a[3], stAh + off);
#pragma unroll
                for (int n8 = 0; n8 < 8; n8++) mma_bf16(acc[m16][n8], a, bh[n8]);
#pragma unroll
                for (int n8 = 0; n8 < 8; n8++) mma_bf16(acc[m16][n8], a, bl[n8]);
            }
#pragma unroll
            for (int m16 = 0; m16 < 4; m16++) {
                int row = mrow + m16 * 16 + a_row_off;
                uint32_t off = (uint32_t)(row * 128) +
                               (uint32_t)((kb + a_kb_off) ^ ((row & 7) << 4));
                uint32_t a[4];
                ldsm_x4(a[0], a[1], a[2], a[3], stAl + off);
#pragma unroll
                for (int n8 = 0; n8 < 8; n8++) mma_bf16(acc[m16][n8], a, bh[n8]);
            }
        }

        MBAR_ARRIVE(sbase + 40 + 8 * s);

        if (tid == 0 && c + G_NSTAGE < NKC) {
            mbar_wait(sbase + 40 + 8 * s, ph);
            FENCE_ASYNC();
            const int cn = c + G_NSTAGE;
            const uint32_t mb = sbase + 8 + 8 * s;
            const uint32_t st = stage0 + s * G_STAGE;
            MBAR_EXPECT_TX(mb, G_STAGE);
            bulk_g2s(st + 0,     pAh  + (size_t)cn * 16384, 16384, mb);
            bulk_g2s(st + 16384, pAl  + (size_t)cn * 16384, 16384, mb);
            bulk_g2s(st + 32768, pBh0 + (size_t)cn * 16384, 16384, mb);
            bulk_g2s(st + 49152, pBh1 + (size_t)cn * 16384, 16384, mb);
            bulk_g2s(st + 65536, pBl0 + (size_t)cn * 16384, 16384, mb);
            bulk_g2s(st + 81920, pBl1 + (size_t)cn * 16384, 16384, mb);
        }
    }

    const int lr = l >> 2;
    const int lc = (l & 3) * 2;

    if constexpr (MODE == 0) {
#pragma unroll
        for (int m16 = 0; m16 < 4; m16++) {
            const size_t r0 = (size_t)(mt * 128 + mrow + m16 * 16 + lr);
            float* c0p = C + r0 * N;
            float* c1p = c0p + (size_t)8 * N;
#pragma unroll
            for (int n8 = 0; n8 < 8; n8++) {
                const int col = nt * 256 + ncol + n8 * 8 + lc;
                const float bx = bias[col], by = bias[col + 1];
                float2 v0 = make_float2(acc[m16][n8][0] + bx, acc[m16][n8][1] + by);
                float2 v1 = make_float2(acc[m16][n8][2] + bx, acc[m16][n8][3] + by);
                *(float2*)(c0p + col) = v0;
                *(float2*)(c1p + col) = v1;
            }
        }
    } else {
        const int b_ = mt >> 4;
        const int qt_ = mt & 15;
        if (nt < 8) {
            // Q (nt<4, scale by 0.125*log2e) or K (nt in [4,8))
            const bool isQ = (nt < 4);
            __nv_bfloat16* oh = isQ ? oQh : oKh;
            __nv_bfloat16* ol = isQ ? oQl : oKl;
            const float scale = isQ ? (0.125f * LOG2E) : 1.0f;
            const int base0 = nt * 256 - (isQ ? 0 : 1024);
#pragma unroll
            for (int m16 = 0; m16 < 4; m16++) {
                const int rl0 = mrow + m16 * 16 + lr;
#pragma unroll
                for (int n8 = 0; n8 < 8; n8++) {
                    const int cl = ncol + n8 * 8 + lc;
                    const int base = base0 + cl;
                    const int head = base >> 6;
                    const int d = base & 63;
                    const float bx = bias[nt * 256 + cl];
                    const float by = bias[nt * 256 + cl + 1];
                    const size_t tb = ((size_t)(b_ * HH + head) * 16 + qt_) * 8192;
                    char* th = (char*)(oh + tb);
                    char* tl = (char*)(ol + tb);
                    float r0, r1;
                    const uint32_t h0 = packres((acc[m16][n8][0] + bx) * scale,
                                                (acc[m16][n8][1] + by) * scale, r0, r1);
                    const uint32_t l0 = packlo(r0, r1);
                    const uint32_t off0 = SWZ128((uint32_t)(rl0 * 128 + d * 2));
                    *(uint32_t*)(th + off0) = h0;
                    *(uint32_t*)(tl + off0) = l0;
                    const uint32_t h1 = packres((acc[m16][n8][2] + bx) * scale,
                                                (acc[m16][n8][3] + by) * scale, r0, r1);
                    const uint32_t l1 = packlo(r0, r1);
                    const uint32_t off1 = SWZ128((uint32_t)((rl0 + 8) * 128 + d * 2));
                    *(uint32_t*)(th + off1) = h1;
                    *(uint32_t*)(tl + off1) = l1;
                }
            }
        } else {
            // V: transpose through smem (stages are free), write V^T tiles
            float* sf = (float*)(smem + 1024);   // [128][260] fp32
            __syncthreads();
#pragma unroll
            for (int m16 = 0; m16 < 4; m16++) {
                const int rl0 = mrow + m16 * 16 + lr;
#pragma unroll
                for (int n8 = 0; n8 < 8; n8++) {
                    const int cl = ncol + n8 * 8 + lc;
                    const float bx = bias[nt * 256 + cl];
                    const float by = bias[nt * 256 + cl + 1];
                    sf[rl0 * 260 + cl]           = acc[m16][n8][0] + bx;
                    sf[rl0 * 260 + cl + 1]       = acc[m16][n8][1] + by;
                    sf[(rl0 + 8) * 260 + cl]     = acc[m16][n8][2] + bx;
                    sf[(rl0 + 8) * 260 + cl + 1] = acc[m16][n8][3] + by;
                }
            }
            __syncthreads();
            const int ntv = nt - 8;   // 0..3, 4 heads each
            for (int ch = tid; ch < 4096; ch += 256) {
                const int hh2 = ch >> 10;           // head within CTA (0..3)
                const int rem = ch & 1023;
                const int kt2loc = rem >> 9;        // 0..1
                const int d = (rem >> 3) & 63;
                const int oct = rem & 7;
                __align__(16) __nv_bfloat16 h8[8], l8[8];
#pragma unroll
                for (int e = 0; e < 8; e++) {
                    const int key = kt2loc * 64 + oct * 8 + e;
                    split_bf16(sf[key * 260 + hh2 * 64 + d], h8[e], l8[e]);
                }
                const size_t tb =
                    ((size_t)(b_ * HH + ntv * 4 + hh2) * 32 + qt_ * 2 + kt2loc) * 4096;
                const uint32_t off = SWZ128((uint32_t)(d * 128 + oct * 16));
                *(uint4*)((char*)(oVh + tb) + off) = *(const uint4*)h8;
                *(uint4*)((char*)(oVl + tb) + off) = *(const uint4*)l8;
            }
        }
    }
}

// ---------------------------------------------------------------------------
// Flash attention on mma.sync, 3-stage K/V pipeline, exp2 softmax interleaved
// with PV MMAs; fused split-tile epilogue for the proj GEMM.
// ---------------------------------------------------------------------------
#define ATT_STAGE 65536u
#define A_NSTAGE 3
#define ATT_SMEM  (1024u + 32768u + A_NSTAGE * ATT_STAGE)

__global__ __launch_bounds__(256) void flash_mma_kernel(
    const __nv_bfloat16* __restrict__ Qh_, const __nv_bfloat16* __restrict__ Ql_,
    const __nv_bfloat16* __restrict__ Kh_, const __nv_bfloat16* __restrict__ Kl_,
    const __nv_bfloat16* __restrict__ Vh_, const __nv_bfloat16* __restrict__ Vl_,
    __nv_bfloat16* __restrict__ oYh, __nv_bfloat16* __restrict__ oYl)
{
    extern __shared__ __align__(1024) char smem[];
    const uint32_t sbase = smem_u32(smem);
    const int tid = threadIdx.x;
    const int qt = (int)gridDim.x - 1 - (int)blockIdx.x;   // big tiles first
    const int h  = blockIdx.y;
    const int b  = blockIdx.z;

    const uint32_t mbq = sbase + 8;
    const uint32_t sQh = sbase + 1024;
    const uint32_t sQl = sQh + 16384;
    const uint32_t stage0 = sQl + 16384;

    if (tid == 0) {
        MBAR_INIT(mbq, 1);
#pragma unroll
        for (int s = 0; s < A_NSTAGE; s++) {
            MBAR_INIT(sbase + 16 + 8 * s, 1);
            MBAR_INIT(sbase + 40 + 8 * s, 256);
        }
    }
    __syncthreads();

    const int bh_idx = b * HH + h;
    const char* pQh = (const char*)(Qh_ + ((size_t)bh_idx * 16 + qt) * 8192);
    const char* pQl = (const char*)(Ql_ + ((size_t)bh_idx * 16 + qt) * 8192);
    const char* pKh = (const char*)(Kh_ + (size_t)bh_idx * 16 * 8192);
    const char* pKl = (const char*)(Kl_ + (size_t)bh_idx * 16 * 8192);
    const char* pVh = (const char*)(Vh_ + (size_t)bh_idx * 32 * 4096);
    const char* pVl = (const char*)(Vl_ + (size_t)bh_idx * 32 * 4096);

    const int ntiles = qt + 1;

    if (tid == 0) {
        MBAR_EXPECT_TX(mbq, 32768);
        bulk_g2s(sQh, pQh, 16384, mbq);
        bulk_g2s(sQl, pQl, 16384, mbq);
        const int npro = ntiles < A_NSTAGE ? ntiles : A_NSTAGE;
        for (int c = 0; c < npro; c++) {
            uint32_t st = stage0 + c * ATT_STAGE;
            uint32_t mb = sbase + 16 + 8 * c;
            MBAR_EXPECT_TX(mb, ATT_STAGE);
            bulk_g2s(st + 0,     pKh + (size_t)c * 16384, 16384, mb);
            bulk_g2s(st + 16384, pKl + (size_t)c * 16384, 16384, mb);
            bulk_g2s(st + 32768, pVh + (size_t)c * 16384, 16384, mb);
            bulk_g2s(st + 49152, pVl + (size_t)c * 16384, 16384, mb);
        }
    }

    const int w = tid >> 5, l = tid & 31;
    const int mat = l >> 3, rin = l & 7;
    const int a_row_off = rin + ((mat & 1) << 3);
    const int a_kb_off  = (mat >> 1) << 4;
    const int b_row_off = rin + ((mat >> 1) << 3);
    const int b_kb_off  = (mat & 1) << 4;
    const int lr = l >> 2, qp = l & 3;

    // Q fragments (persist)
    mbar_wait(mbq, 0);
    uint32_t qh[4][4], ql[4][4];
#pragma unroll
    for (int ks = 0; ks < 4; ks++) {
        int row = w * 16 + a_row_off;
        uint32_t off = (uint32_t)(row * 128) +
                       (uint32_t)((ks * 32 + a_kb_off) ^ ((row & 7) << 4));
        ldsm_x4(qh[ks][0], qh[ks][1], qh[ks][2], qh[ks][3], sQh + off);
        ldsm_x4(ql[ks][0], ql[ks][1], ql[ks][2], ql[ks][3], sQl + off);
    }

    float acc_o[8][4];
#pragma unroll
    for (int j = 0; j < 8; j++)
#pragma unroll
        for (int e = 0; e < 4; e++) acc_o[j][e] = 0.f;
    float m0 = -1e30f, m1 = -1e30f, l0 = 0.f, l1 = 0.f;

    for (int kt = 0; kt < ntiles; kt++) {
        const int s = kt % A_NSTAGE;
        const uint32_t phs = (uint32_t)((kt / A_NSTAGE) & 1);
        mbar_wait(sbase + 16 + 8 * s, phs);
        const uint32_t stKh = stage0 + s * ATT_STAGE;
        const uint32_t stKl = stKh + 16384;
        const uint32_t stVh = stKh + 32768;
        const uint32_t stVl = stKh + 49152;

        // --- S = Q K^T (3-term compensated), log2 units
        float acc_s[16][4];
#pragma unroll
        for (int j = 0; j < 16; j++)
#pragma unroll
            for (int e = 0; e < 4; e++) acc_s[j][e] = 0.f;

#pragma unroll
        for (int ks = 0; ks < 4; ks++) {
            const uint32_t kb = (uint32_t)(ks * 32 + b_kb_off);
#pragma unroll
            for (int g = 0; g < 8; g++) {
                int row = g * 16 + b_row_off;
                uint32_t off = (uint32_t)(row * 128) + (kb ^ (uint32_t)((row & 7) << 4));
                uint32_t kfh[4], kfl[4];
                ldsm_x4(kfh[0], kfh[1], kfh[2], kfh[3], stKh + off);
                ldsm_x4(kfl[0], kfl[1], kfl[2], kfl[3], stKl + off);
                mma_bf16(acc_s[2 * g],     qh[ks], kfh);
                mma_bf16(acc_s[2 * g],     qh[ks], kfl);
                mma_bf16(acc_s[2 * g],     ql[ks], kfh);
                mma_bf16(acc_s[2 * g + 1], qh[ks], kfh + 2);
                mma_bf16(acc_s[2 * g + 1], qh[ks], kfl + 2);
                mma_bf16(acc_s[2 * g + 1], ql[ks], kfh + 2);
            }
        }

        // --- causal mask on the diagonal tile
        if (kt == qt) {
            const int rr0 = w * 16 + lr, rr1 = rr0 + 8;
#pragma unroll
            for (int j = 0; j < 16; j++) {
                const int c0 = j * 8 + qp * 2;
                if (c0     > rr0) acc_s[j][0] = -1e30f;
                if (c0 + 1 > rr0) acc_s[j][1] = -1e30f;
                if (c0     > rr1) acc_s[j][2] = -1e30f;
                if (c0 + 1 > rr1) acc_s[j][3] = -1e30f;
            }
        }

        // --- online softmax (base-2)
        float t0 = -1e30f, t1 = -1e30f;
#pragma unroll
        for (int j = 0; j < 16; j++) {
            t0 = fmaxf(t0, fmaxf(acc_s[j][0], acc_s[j][1]));
            t1 = fmaxf(t1, fmaxf(acc_s[j][2], acc_s[j][3]));
        }
        t0 = fmaxf(t0, __shfl_xor_sync(0xffffffffu, t0, 1));
        t0 = fmaxf(t0, __shfl_xor_sync(0xffffffffu, t0, 2));
        t1 = fmaxf(t1, __shfl_xor_sync(0xffffffffu, t1, 1));
        t1 = fmaxf(t1, __shfl_xor_sync(0xffffffffu, t1, 2));

        const float mn0 = fmaxf(m0, t0);
        const float mn1 = fmaxf(m1, t1);
        const float cr0 = ex2(m0 - mn0);
        const float cr1 = ex2(m1 - mn1);
        m0 = mn0; m1 = mn1;
        l0 *= cr0; l1 *= cr1;
#pragma unroll
        for (int j = 0; j < 8; j++) {
            acc_o[j][0] *= cr0; acc_o[j][1] *= cr0;
            acc_o[j][2] *= cr1; acc_o[j][3] *= cr1;
        }

        // --- interleaved: exp/pack one 16-key slice, then its PV MMAs
#pragma unroll
        for (int kc = 0; kc < 8; kc++) {
            uint32_t ph[4], pl[4];
#pragma unroll
            for (int jj = 0; jj < 2; jj++) {
                const int j = 2 * kc + jj;
                const float p0 = ex2(acc_s[j][0] - mn0);
                const float p1 = ex2(acc_s[j][1] - mn0);
                const float p2 = ex2(acc_s[j][2] - mn1);
                const float p3 = ex2(acc_s[j][3] - mn1);
                l0 += p0 + p1; l1 += p2 + p3;
                float r0, r1, r2, r3;
                ph[jj * 2 + 0] = packres(p0, p1, r0, r1);
                ph[jj * 2 + 1] = packres(p2, p3, r2, r3);
                pl[jj * 2 + 0] = packlo(r0, r1);
                pl[jj * 2 + 1] = packlo(r2, r3);
            }
            // wait: A fragment order must be (j0 frag0, j0 frag1, j1 frag0, j1 frag1)?
            // A-frag layout for m16n8k16: a[0],a[1] cover rows, a[2],a[3] k+16B half.
            // ph[0]=j0 rows0-7/k0, ph[1]=j0 rows8-15... matches previous mapping:
            // previous: ph[kc][0]=h01(j even), ph[kc][1]=h23(j even), [2],[3] = j odd.
            const uint32_t vhb = stVh + ((kc < 4) ? 0u : 8192u);
            const uint32_t vlb = stVl + ((kc < 4) ? 0u : 8192u);
            const uint32_t kb = (uint32_t)((kc & 3) * 32 + b_kb_off);
#pragma unroll
            for (int g = 0; g < 4; g++) {
                int row = g * 16 + b_row_off;
                uint32_t off = (uint32_t)(row * 128) + (kb ^ (uint32_t)((row & 7) << 4));
                uint32_t vfh[4], vfl[4];
                ldsm_x4(vfh[0], vfh[1], vfh[2], vfh[3], vhb + off);
                ldsm_x4(vfl[0], vfl[1], vfl[2], vfl[3], vlb + off);
                mma_bf16(acc_o[2 * g],     ph, vfh);
                mma_bf16(acc_o[2 * g],     ph, vfl);
                mma_bf16(acc_o[2 * g],     pl, vfh);
                mma_bf16(acc_o[2 * g + 1], ph, vfh + 2);
                mma_bf16(acc_o[2 * g + 1], ph, vfl + 2);
                mma_bf16(acc_o[2 * g + 1], pl, vfh + 2);
            }
        }

        MBAR_ARRIVE(sbase + 40 + 8 * s);

        if (tid == 0 && kt + A_NSTAGE < ntiles) {
            mbar_wait(sbase + 40 + 8 * s, phs);
            FENCE_ASYNC();
            const int cn = kt + A_NSTAGE;
            const uint32_t mb = sbase + 16 + 8 * s;
            const uint32_t st = stage0 + s * ATT_STAGE;
            MBAR_EXPECT_TX(mb, ATT_STAGE);
            bulk_g2s(st + 0,     pKh + (size_t)cn * 16384, 16384, mb);
            bulk_g2s(st + 16384, pKl + (size_t)cn * 16384, 16384, mb);
            bulk_g2s(st + 32768, pVh + (size_t)cn * 16384, 16384, mb);
            bulk_g2s(st + 49152, pVl + (size_t)cn * 16384, 16384, mb);
        }
    }

    // --- epilogue: normalize, split hi/lo, write y as proj A-tiles
    l0 += __shfl_xor_sync(0xffffffffu, l0, 1);
    l0 += __shfl_xor_sync(0xffffffffu, l0, 2);
    l1 += __shfl_xor_sync(0xffffffffu, l1, 1);
    l1 += __shfl_xor_sync(0xffffffffu, l1, 2);
    const float inv0 = 1.f / l0;
    const float inv1 = 1.f / l1;

    const size_t tb = ((size_t)(b * 16 + qt) * NKC + h) * 8192;
    char* th = (char*)(oYh + tb);
    char* tl = (char*)(oYl + tb);
    const int rl0 = w * 16 + lr;
#pragma unroll
    for (int j = 0; j < 8; j++) {
        const int dc = j * 8 + qp * 2;
        float r0, r1;
        const uint32_t h0 = packres(acc_o[j][0] * inv0, acc_o[j][1] * inv0, r0, r1);
        const uint32_t lo0 = packlo(r0, r1);
        const uint32_t off0 = SWZ128((uint32_t)(rl0 * 128 + dc * 2));
        *(uint32_t*)(th + off0) = h0;
        *(uint32_t*)(tl + off0) = lo0;
        const uint32_t h1 = packres(acc_o[j][2] * inv1, acc_o[j][3] * inv1, r0, r1);
        const uint32_t lo1 = packlo(r0, r1);
        const uint32_t off1 = SWZ128((uint32_t)((rl0 + 8) * 128 + dc * 2));
        *(uint32_t*)(th + off1) = h1;
        *(uint32_t*)(tl + off1) = lo1;
    }
}

// ---------------------------------------------------------------------------
// Launch
// ---------------------------------------------------------------------------
extern "C" void kernel_launch(void* const* d_in, const int* in_sizes, int n_in,
                              void* d_out, int out_size)
{
    const float* x     = (const float*)d_in[0];
    const float* Wqkv  = (const float*)d_in[1];
    const float* bqkv  = (const float*)d_in[2];
    const float* Wproj = (const float*)d_in[3];
    const float* bproj = (const float*)d_in[4];
    float* out = (float*)d_out;

    __nv_bfloat16 *xh, *xl, *yh, *yl, *wqh, *wql, *wph, *wpl;
    __nv_bfloat16 *aqh, *aql, *akh, *akl, *avh, *avl;
    cudaGetSymbolAddress((void**)&xh, g_xh);
    cudaGetSymbolAddress((void**)&xl, g_xl);
    cudaGetSymbolAddress((void**)&yh, g_yh);
    cudaGetSymbolAddress((void**)&yl, g_yl);
    cudaGetSymbolAddress((void**)&wqh, g_wqkvh);
    cudaGetSymbolAddress((void**)&wql, g_wqkvl);
    cudaGetSymbolAddress((void**)&wph, g_wprojh);
    cudaGetSymbolAddress((void**)&wpl, g_wprojl);
    cudaGetSymbolAddress((void**)&aqh, g_qh);
    cudaGetSymbolAddress((void**)&aql, g_ql);
    cudaGetSymbolAddress((void**)&akh, g_kh);
    cudaGetSymbolAddress((void**)&akl, g_kl);
    cudaGetSymbolAddress((void**)&avh, g_vh);
    cudaGetSymbolAddress((void**)&avl, g_vl);

    cudaFuncSetAttribute(gemm_mma_kernel<0>,
                         cudaFuncAttributeMaxDynamicSharedMemorySize, GEMM_SMEM);
    cudaFuncSetAttribute(gemm_mma_kernel<1>,
                         cudaFuncAttributeMaxDynamicSharedMemorySize, GEMM_SMEM);
    cudaFuncSetAttribute(flash_mma_kernel,
                         cudaFuncAttributeMaxDynamicSharedMemorySize, ATT_SMEM);

    // Combined prep (x split + both weight transposes)
    prep_all_kernel<<<1536, 256>>>(x, xh, xl, Wqkv, wqh, wql, Wproj, wph, wpl);

    // QKV GEMM with fused Q/K/V-tile epilogue (Q pre-scaled for exp2 softmax)
    gemm_mma_kernel<1><<<dim3(N_QKV / 256, MTOK / 128), 256, GEMM_SMEM>>>(
        xh, xl, wqh, wql, bqkv, nullptr, N_QKV,
        aqh, aql, akh, akl, avh, avl);

    // Flash attention (tensor cores) -> split y tiles
    flash_mma_kernel<<<dim3(TT / 128, HH, BB), 256, ATT_SMEM>>>(
        aqh, aql, akh, akl, avh, avl, yh, yl);

    // Proj GEMM: out = y @ Wproj + bproj (fp32 epilogue)
    gemm_mma_kernel<0><<<dim3(CC / 256, MTOK / 128), 256, GEMM_SMEM>>>(
        yh, yl, wph, wpl, bproj, out, CC,
        nullptr, nullptr, nullptr, nullptr, nullptr, nullptr);
}

// round 8
// speedup vs baseline: 4.4356x; 1.0751x over previous
#include <cuda_runtime.h>
#include <cuda_bf16.h>
#include <math.h>
#include <stdint.h>

// Problem constants
#define BB 4
#define TT 2048
#define CC 1024
#define HH 16
#define DD 64
#define MTOK (BB * TT)          // 8192 tokens
#define N_QKV (3 * CC)          // 3072
#define NKC 16                  // K chunks: 1024 / 64

#define LOG2E 1.4426950408889634f
#define NWORK 152               // persistent attention workers (GB300: 152 SMs)

// ---------------------------------------------------------------------------
// Scratch (allocation-free rule: __device__ globals)
// ---------------------------------------------------------------------------
__device__ __nv_bfloat16 g_xh[(size_t)MTOK * CC];
__device__ __nv_bfloat16 g_xl[(size_t)MTOK * CC];
__device__ __nv_bfloat16 g_yh[(size_t)MTOK * CC];
__device__ __nv_bfloat16 g_yl[(size_t)MTOK * CC];
__device__ __nv_bfloat16 g_wqkvh[(size_t)N_QKV * CC];
__device__ __nv_bfloat16 g_wqkvl[(size_t)N_QKV * CC];
__device__ __nv_bfloat16 g_wprojh[(size_t)CC * CC];
__device__ __nv_bfloat16 g_wprojl[(size_t)CC * CC];
// attention operand tiles (per (b,h), SW128 swizzled bf16)
__device__ __nv_bfloat16 g_qh[(size_t)BB * HH * 16 * 8192];
__device__ __nv_bfloat16 g_ql[(size_t)BB * HH * 16 * 8192];
__device__ __nv_bfloat16 g_kh[(size_t)BB * HH * 16 * 8192];
__device__ __nv_bfloat16 g_kl[(size_t)BB * HH * 16 * 8192];
__device__ __nv_bfloat16 g_vh[(size_t)BB * HH * 32 * 4096];
__device__ __nv_bfloat16 g_vl[(size_t)BB * HH * 32 * 4096];

// ---------------------------------------------------------------------------
// PTX helpers (base sm_103 target — NO tcgen05)
// ---------------------------------------------------------------------------
__device__ __forceinline__ uint32_t smem_u32(const void* p) {
    uint32_t a;
    asm("{ .reg .u64 t; cvta.to.shared.u64 t, %1; cvt.u32.u64 %0, t; }" : "=r"(a) : "l"(p));
    return a;
}

#define SWZ128(off) ((off) ^ (((off) >> 3) & 0x70))

#define MBAR_INIT(addr, cnt) \
    asm volatile("mbarrier.init.shared.b64 [%0], %1;" :: "r"(addr), "r"(cnt) : "memory")

#define MBAR_EXPECT_TX(addr, bytes) \
    asm volatile("mbarrier.arrive.expect_tx.shared.b64 _, [%0], %1;" :: "r"(addr), "r"(bytes) : "memory")

#define MBAR_ARRIVE(addr) \
    asm volatile("mbarrier.arrive.shared.b64 _, [%0];" :: "r"(addr) : "memory")

__device__ __forceinline__ void mbar_wait(uint32_t mbar, uint32_t parity) {
    uint32_t done;
    asm volatile(
        "{\n\t.reg .pred p;\n\t"
        "mbarrier.try_wait.parity.acquire.cta.shared::cta.b64 p, [%1], %2;\n\t"
        "selp.b32 %0, 1, 0, p;\n\t}"
        : "=r"(done) : "r"(mbar), "r"(parity) : "memory");
    if (!done) {
        asm volatile(
            "{\n\t.reg .pred P1;\n\t"
            "WL_%=:\n\t"
            "mbarrier.try_wait.parity.acquire.cta.shared::cta.b64 P1, [%0], %1, 0x989680;\n\t"
            "@P1 bra.uni WD_%=;\n\t"
            "bra.uni WL_%=;\n\t"
            "WD_%=:\n\t}"
            :: "r"(mbar), "r"(parity) : "memory");
    }
}

__device__ __forceinline__ void bulk_g2s(uint32_t dst, const void* src, uint32_t bytes, uint32_t mbar) {
    asm volatile(
        "cp.async.bulk.shared::cluster.global.mbarrier::complete_tx::bytes [%0], [%1], %2, [%3];"
        :: "r"(dst), "l"(src), "r"(bytes), "r"(mbar) : "memory");
}

#define FENCE_ASYNC() asm volatile("fence.proxy.async.shared::cta;" ::: "memory")

__device__ __forceinline__ void ldsm_x4(uint32_t& r0, uint32_t& r1, uint32_t& r2, uint32_t& r3,
                                        uint32_t addr) {
    asm volatile("ldmatrix.sync.aligned.m8n8.x4.shared.b16 {%0,%1,%2,%3}, [%4];"
                 : "=r"(r0), "=r"(r1), "=r"(r2), "=r"(r3) : "r"(addr));
}

__device__ __forceinline__ void mma_bf16(float* d, const uint32_t* a, const uint32_t* b) {
    asm volatile(
        "mma.sync.aligned.m16n8k16.row.col.f32.bf16.bf16.f32 "
        "{%0,%1,%2,%3}, {%4,%5,%6,%7}, {%8,%9}, {%0,%1,%2,%3};"
        : "+f"(d[0]), "+f"(d[1]), "+f"(d[2]), "+f"(d[3])
        : "r"(a[0]), "r"(a[1]), "r"(a[2]), "r"(a[3]), "r"(b[0]), "r"(b[1]));
}

__device__ __forceinline__ float ex2(float x) {
    float r;
    asm("ex2.approx.f32 %0, %1;" : "=f"(r) : "f"(x));
    return r;
}

// ---------------------------------------------------------------------------
// hi/lo bf16 split helpers
// ---------------------------------------------------------------------------
__device__ __forceinline__ void split_bf16(float v, __nv_bfloat16& h, __nv_bfloat16& l) {
    h = __float2bfloat16(v);
    l = __float2bfloat16(v - __bfloat162float(h));
}

__device__ __forceinline__ uint32_t packres(float a, float b, float& ra, float& rb) {
    uint32_t h;
    asm("cvt.rn.bf16x2.f32 %0, %1, %2;" : "=r"(h) : "f"(b), "f"(a));
    ra = a - __uint_as_float(h << 16);
    rb = b - __uint_as_float(h & 0xffff0000u);
    return h;
}
__device__ __forceinline__ uint32_t packlo(float a, float b) {
    uint32_t h;
    asm("cvt.rn.bf16x2.f32 %0, %1, %2;" : "=r"(h) : "f"(b), "f"(a));
    return h;
}

// ---------------------------------------------------------------------------
// Combined prep kernel (unchanged from R7)
// ---------------------------------------------------------------------------
__global__ __launch_bounds__(256) void prep_all_kernel(
    const float* __restrict__ x, __nv_bfloat16* __restrict__ xh, __nv_bfloat16* __restrict__ xl,
    const float* __restrict__ Wq, __nv_bfloat16* __restrict__ wqh, __nv_bfloat16* __restrict__ wql,
    const float* __restrict__ Wp, __nv_bfloat16* __restrict__ wph, __nv_bfloat16* __restrict__ wpl)
{
    __shared__ float s[64][128];
    const int id = blockIdx.x;
    const int t = threadIdx.x;

    if (id < 1024) {
        const int kc = id & 15;
        const int mt = id >> 4;
        const int r = t >> 1;
        const int hh = t & 1;
        const float* src = x + (size_t)(mt * 128 + r) * CC + kc * 64 + hh * 32;
        char* bh = (char*)(xh + ((size_t)mt * NKC + kc) * 8192);
        char* bl = (char*)(xl + ((size_t)mt * NKC + kc) * 8192);
#pragma unroll
        for (int j = 0; j < 4; j++) {
            float4 v0 = ((const float4*)src)[j * 2 + 0];
            float4 v1 = ((const float4*)src)[j * 2 + 1];
            __align__(16) __nv_bfloat16 h8[8], l8[8];
            split_bf16(v0.x, h8[0], l8[0]); split_bf16(v0.y, h8[1], l8[1]);
            split_bf16(v0.z, h8[2], l8[2]); split_bf16(v0.w, h8[3], l8[3]);
            split_bf16(v1.x, h8[4], l8[4]); split_bf16(v1.y, h8[5], l8[5]);
            split_bf16(v1.z, h8[6], l8[6]); split_bf16(v1.w, h8[7], l8[7]);
            uint32_t off = SWZ128((uint32_t)(r * 128 + hh * 64 + j * 16));
            *(uint4*)(bh + off) = *(const uint4*)h8;
            *(uint4*)(bl + off) = *(const uint4*)l8;
        }
        return;
    }

    const bool isQ = (id < 1408);
    const int v = isQ ? (id - 1024) : (id - 1408);
    const int kc = v & 15;
    const int nt = v >> 4;
    const float* W = isQ ? Wq : Wp;
    __nv_bfloat16* oh = isQ ? wqh : wph;
    __nv_bfloat16* ol = isQ ? wql : wpl;
    const int N = isQ ? N_QKV : CC;

    for (int idx = t; idx < 64 * 128; idx += 256) {
        int r = idx >> 7, n = idx & 127;
        s[r][n] = W[(size_t)(kc * 64 + r) * N + nt * 128 + n];
    }
    __syncthreads();

    const int np = t & 127;
    const int c0 = (t >> 7) * 4;
    char* bh = (char*)(oh + ((size_t)nt * NKC + kc) * 8192);
    char* bl = (char*)(ol + ((size_t)nt * NKC + kc) * 8192);

#pragma unroll
    for (int c = c0; c < c0 + 4; c++) {
        __align__(16) __nv_bfloat16 h8[8], l8[8];
#pragma unroll
        for (int j = 0; j < 8; j++) {
            split_bf16(s[c * 8 + j][np], h8[j], l8[j]);
        }
        uint32_t off = SWZ128((uint32_t)(np * 128 + c * 16));
        *(uint4*)(bh + off) = *(const uint4*)h8;
        *(uint4*)(bl + off) = *(const uint4*)l8;
    }
}

// ---------------------------------------------------------------------------
// mma.sync GEMM, CTA 128x256, warps 64x64, BK=64, 2-stage pipeline
// (unchanged from R7).
// ---------------------------------------------------------------------------
#define G_STAGE 98304u
#define G_NSTAGE 2
#define GEMM_SMEM (1024u + G_NSTAGE * G_STAGE)

template <int MODE>
__global__ __launch_bounds__(256) void gemm_mma_kernel(
    const __nv_bfloat16* __restrict__ Ah_, const __nv_bfloat16* __restrict__ Al_,
    const __nv_bfloat16* __restrict__ Bh_, const __nv_bfloat16* __restrict__ Bl_,
    const float* __restrict__ bias, float* __restrict__ C, int N,
    __nv_bfloat16* __restrict__ oQh, __nv_bfloat16* __restrict__ oQl,
    __nv_bfloat16* __restrict__ oKh, __nv_bfloat16* __restrict__ oKl,
    __nv_bfloat16* __restrict__ oVh, __nv_bfloat16* __restrict__ oVl)
{
    extern __shared__ __align__(1024) char smem[];
    const uint32_t sbase = smem_u32(smem);
    const int tid = threadIdx.x;
    const int nt = blockIdx.x;
    const int mt = blockIdx.y;

    const uint32_t stage0 = sbase + 1024;

    if (tid == 0) {
#pragma unroll
        for (int s = 0; s < G_NSTAGE; s++) {
            MBAR_INIT(sbase + 8 + 8 * s, 1);
            MBAR_INIT(sbase + 40 + 8 * s, 256);
        }
    }
    __syncthreads();

    const char* pAh = (const char*)(Ah_ + (size_t)mt * NKC * 8192);
    const char* pAl = (const char*)(Al_ + (size_t)mt * NKC * 8192);
    const char* pBh0 = (const char*)(Bh_ + (size_t)(2 * nt) * NKC * 8192);
    const char* pBh1 = (const char*)(Bh_ + (size_t)(2 * nt + 1) * NKC * 8192);
    const char* pBl0 = (const char*)(Bl_ + (size_t)(2 * nt) * NKC * 8192);
    const char* pBl1 = (const char*)(Bl_ + (size_t)(2 * nt + 1) * NKC * 8192);

    if (tid == 0) {
#pragma unroll
        for (int c = 0; c < G_NSTAGE; c++) {
            uint32_t st = stage0 + c * G_STAGE;
            uint32_t mb = sbase + 8 + 8 * c;
            MBAR_EXPECT_TX(mb, G_STAGE);
            bulk_g2s(st + 0,     pAh  + (size_t)c * 16384, 16384, mb);
            bulk_g2s(st + 16384, pAl  + (size_t)c * 16384, 16384, mb);
            bulk_g2s(st + 32768, pBh0 + (size_t)c * 16384, 16384, mb);
            bulk_g2s(st + 49152, pBh1 + (size_t)c * 16384, 16384, mb);
            bulk_g2s(st + 65536, pBl0 + (size_t)c * 16384, 16384, mb);
            bulk_g2s(st + 81920, pBl1 + (size_t)c * 16384, 16384, mb);
        }
    }

    const int w = tid >> 5, l = tid & 31;
    const int mrow = (w >> 2) * 64;
    const int ncol = (w & 3) * 64;
    const int mat = l >> 3;
    const int rin = l & 7;

    const int a_row_off = rin + ((mat & 1) << 3);
    const int a_kb_off  = (mat >> 1) << 4;
    const int b_row_off = rin + ((mat >> 1) << 3);
    const int b_kb_off  = (mat & 1) << 4;

    float acc[4][8][4];
#pragma unroll
    for (int i = 0; i < 4; i++)
#pragma unroll
        for (int j = 0; j < 8; j++)
#pragma unroll
            for (int k = 0; k < 4; k++) acc[i][j][k] = 0.f;

    for (int c = 0; c < NKC; c++) {
        const int s = c & 1;
        const uint32_t ph = (uint32_t)((c >> 1) & 1);
        mbar_wait(sbase + 8 + 8 * s, ph);

        const uint32_t stAh = stage0 + s * G_STAGE;
        const uint32_t stAl = stAh + 16384;
        const uint32_t stBh = stAh + 32768;
        const uint32_t stBl = stAh + 65536;

#pragma unroll
        for (int ks = 0; ks < 4; ks++) {
            const int kb = ks * 32;
            uint32_t bh[8][2], bl[8][2];
#pragma unroll
            for (int n16 = 0; n16 < 4; n16++) {
                int row = ncol + n16 * 16 + b_row_off;
                uint32_t off = (uint32_t)(row * 128) +
                               (uint32_t)((kb + b_kb_off) ^ ((row & 7) << 4));
                ldsm_x4(bh[n16 * 2][0], bh[n16 * 2][1],
                        bh[n16 * 2 + 1][0], bh[n16 * 2 + 1][1], stBh + off);
                ldsm_x4(bl[n16 * 2][0], bl[n16 * 2][1],
                        bl[n16 * 2 + 1][0], bl[n16 * 2 + 1][1], stBl + off);
            }
#pragma unroll
            for (int m16 = 0; m16 < 4; m16++) {
                int row = mrow + m16 * 16 + a_row_off;
                uint32_t off = (uint32_t)(row * 128) +
                               (uint32_t)((kb + a_kb_off) ^ ((row & 7) << 4));
                uint32_t a[4];
                ldsm_x4(a[0], a[1], a[2], a[3], stAh + off);
#pragma unroll
                for (int n8 = 0; n8 < 8; n8++) mma_bf16(acc[m16][n8], a, bh[n8]);
#pragma unroll
                for (int n8 = 0; n8 < 8; n8++) mma_bf16(acc[m16][n8], a, bl[n8]);
            }
#pragma unroll
            for (int m16 = 0; m16 < 4; m16++) {
                int row = mrow + m16 * 16 + a_row_off;
                uint32_t off = (uint32_t)(row * 128) +
                               (uint32_t)((kb + a_kb_off) ^ ((row & 7) << 4));
                uint32_t a[4];
                ldsm_x4(a[0], a[1], a[2], a[3], stAl + off);
#pragma unroll
                for (int n8 = 0; n8 < 8; n8++) mma_bf16(acc[m16][n8], a, bh[n8]);
            }
        }

        MBAR_ARRIVE(sbase + 40 + 8 * s);

        if (tid == 0 && c + G_NSTAGE < NKC) {
            mbar_wait(sbase + 40 + 8 * s, ph);
            FENCE_ASYNC();
            const int cn = c + G_NSTAGE;
            const uint32_t mb = sbase + 8 + 8 * s;
            const uint32_t st = stage0 + s * G_STAGE;
            MBAR_EXPECT_TX(mb, G_STAGE);
            bulk_g2s(st + 0,     pAh  + (size_t)cn * 16384, 16384, mb);
            bulk_g2s(st + 16384, pAl  + (size_t)cn * 16384, 16384, mb);
            bulk_g2s(st + 32768, pBh0 + (size_t)cn * 16384, 16384, mb);
            bulk_g2s(st + 49152, pBh1 + (size_t)cn * 16384, 16384, mb);
            bulk_g2s(st + 65536, pBl0 + (size_t)cn * 16384, 16384, mb);
            bulk_g2s(st + 81920, pBl1 + (size_t)cn * 16384, 16384, mb);
        }
    }

    const int lr = l >> 2;
    const int lc = (l & 3) * 2;

    if constexpr (MODE == 0) {
#pragma unroll
        for (int m16 = 0; m16 < 4; m16++) {
            const size_t r0 = (size_t)(mt * 128 + mrow + m16 * 16 + lr);
            float* c0p = C + r0 * N;
            float* c1p = c0p + (size_t)8 * N;
#pragma unroll
            for (int n8 = 0; n8 < 8; n8++) {
                const int col = nt * 256 + ncol + n8 * 8 + lc;
                const float bx = bias[col], by = bias[col + 1];
                float2 v0 = make_float2(acc[m16][n8][0] + bx, acc[m16][n8][1] + by);
                float2 v1 = make_float2(acc[m16][n8][2] + bx, acc[m16][n8][3] + by);
                *(float2*)(c0p + col) = v0;
                *(float2*)(c1p + col) = v1;
            }
        }
    } else {
        const int b_ = mt >> 4;
        const int qt_ = mt & 15;
        if (nt < 8) {
            const bool isQ = (nt < 4);
            __nv_bfloat16* oh = isQ ? oQh : oKh;
            __nv_bfloat16* ol = isQ ? oQl : oKl;
            const float scale = isQ ? (0.125f * LOG2E) : 1.0f;
            const int base0 = nt * 256 - (isQ ? 0 : 1024);
#pragma unroll
            for (int m16 = 0; m16 < 4; m16++) {
                const int rl0 = mrow + m16 * 16 + lr;
#pragma unroll
                for (int n8 = 0; n8 < 8; n8++) {
                    const int cl = ncol + n8 * 8 + lc;
                    const int base = base0 + cl;
                    const int head = base >> 6;
                    const int d = base & 63;
                    const float bx = bias[nt * 256 + cl];
                    const float by = bias[nt * 256 + cl + 1];
                    const size_t tb = ((size_t)(b_ * HH + head) * 16 + qt_) * 8192;
                    char* th = (char*)(oh + tb);
                    char* tl = (char*)(ol + tb);
                    float r0, r1;
                    const uint32_t h0 = packres((acc[m16][n8][0] + bx) * scale,
                                                (acc[m16][n8][1] + by) * scale, r0, r1);
                    const uint32_t l0 = packlo(r0, r1);
                    const uint32_t off0 = SWZ128((uint32_t)(rl0 * 128 + d * 2));
                    *(uint32_t*)(th + off0) = h0;
                    *(uint32_t*)(tl + off0) = l0;
                    const uint32_t h1 = packres((acc[m16][n8][2] + bx) * scale,
                                                (acc[m16][n8][3] + by) * scale, r0, r1);
                    const uint32_t l1 = packlo(r0, r1);
                    const uint32_t off1 = SWZ128((uint32_t)((rl0 + 8) * 128 + d * 2));
                    *(uint32_t*)(th + off1) = h1;
                    *(uint32_t*)(tl + off1) = l1;
                }
            }
        } else {
            float* sf = (float*)(smem + 1024);
            __syncthreads();
#pragma unroll
            for (int m16 = 0; m16 < 4; m16++) {
                const int rl0 = mrow + m16 * 16 + lr;
#pragma unroll
                for (int n8 = 0; n8 < 8; n8++) {
                    const int cl = ncol + n8 * 8 + lc;
                    const float bx = bias[nt * 256 + cl];
                    const float by = bias[nt * 256 + cl + 1];
                    sf[rl0 * 260 + cl]           = acc[m16][n8][0] + bx;
                    sf[rl0 * 260 + cl + 1]       = acc[m16][n8][1] + by;
                    sf[(rl0 + 8) * 260 + cl]     = acc[m16][n8][2] + bx;
                    sf[(rl0 + 8) * 260 + cl + 1] = acc[m16][n8][3] + by;
                }
            }
            __syncthreads();
            const int ntv = nt - 8;
            for (int ch = tid; ch < 4096; ch += 256) {
                const int hh2 = ch >> 10;
                const int rem = ch & 1023;
                const int kt2loc = rem >> 9;
                const int d = (rem >> 3) & 63;
                const int oct = rem & 7;
                __align__(16) __nv_bfloat16 h8[8], l8[8];
#pragma unroll
                for (int e = 0; e < 8; e++) {
                    const int key = kt2loc * 64 + oct * 8 + e;
                    split_bf16(sf[key * 260 + hh2 * 64 + d], h8[e], l8[e]);
                }
                const size_t tb =
                    ((size_t)(b_ * HH + ntv * 4 + hh2) * 32 + qt_ * 2 + kt2loc) * 4096;
                const uint32_t off = SWZ128((uint32_t)(d * 128 + oct * 16));
                *(uint4*)((char*)(oVh + tb) + off) = *(const uint4*)h8;
                *(uint4*)((char*)(oVl + tb) + off) = *(const uint4*)l8;
            }
        }
    }
}

// ---------------------------------------------------------------------------
// PERSISTENT flash attention: NWORK CTAs, static snake-balanced job schedule.
// Job rank r (cost-descending): qt = 15-(r>>6), bh = r&63. Worker w takes
// rank p*NWORK + (p even ? w : NWORK-1-w) per pass p.
// ---------------------------------------------------------------------------
#define ATT_STAGE 65536u
#define A_NSTAGE 3
#define ATT_SMEM  (1024u + 32768u + A_NSTAGE * ATT_STAGE)
#define NJOBS 1024

__global__ __launch_bounds__(256) void flash_mma_kernel(
    const __nv_bfloat16* __restrict__ Qh_, const __nv_bfloat16* __restrict__ Ql_,
    const __nv_bfloat16* __restrict__ Kh_, const __nv_bfloat16* __restrict__ Kl_,
    const __nv_bfloat16* __restrict__ Vh_, const __nv_bfloat16* __restrict__ Vl_,
    __nv_bfloat16* __restrict__ oYh, __nv_bfloat16* __restrict__ oYl)
{
    extern __shared__ __align__(1024) char smem[];
    const uint32_t sbase = smem_u32(smem);
    const int tid = threadIdx.x;
    const int worker = (int)blockIdx.x;

    const uint32_t mbq = sbase + 8;
    const uint32_t sQh = sbase + 1024;
    const uint32_t sQl = sQh + 16384;
    const uint32_t stage0 = sQl + 16384;

    const int w = tid >> 5, l = tid & 31;
    const int mat = l >> 3, rin = l & 7;
    const int a_row_off = rin + ((mat & 1) << 3);
    const int a_kb_off  = (mat >> 1) << 4;
    const int b_row_off = rin + ((mat >> 1) << 3);
    const int b_kb_off  = (mat & 1) << 4;
    const int lr = l >> 2, qp = l & 3;

    for (int p = 0;; p++) {
        const int rank = p * NWORK + ((p & 1) ? (NWORK - 1 - worker) : worker);
        if (rank >= NJOBS) break;
        const int qt = 15 - (rank >> 6);
        const int bh_idx = rank & 63;
        const int b = bh_idx >> 4;
        const int h = bh_idx & 15;

        // per-job barrier (re)init — all prior async ops are drained at this point
        if (tid == 0) {
            MBAR_INIT(mbq, 1);
#pragma unroll
            for (int s = 0; s < A_NSTAGE; s++) {
                MBAR_INIT(sbase + 16 + 8 * s, 1);
                MBAR_INIT(sbase + 40 + 8 * s, 256);
            }
        }
        __syncthreads();

        const char* pQh = (const char*)(Qh_ + ((size_t)bh_idx * 16 + qt) * 8192);
        const char* pQl = (const char*)(Ql_ + ((size_t)bh_idx * 16 + qt) * 8192);
        const char* pKh = (const char*)(Kh_ + (size_t)bh_idx * 16 * 8192);
        const char* pKl = (const char*)(Kl_ + (size_t)bh_idx * 16 * 8192);
        const char* pVh = (const char*)(Vh_ + (size_t)bh_idx * 32 * 4096);
        const char* pVl = (const char*)(Vl_ + (size_t)bh_idx * 32 * 4096);

        const int ntiles = qt + 1;

        if (tid == 0) {
            MBAR_EXPECT_TX(mbq, 32768);
            bulk_g2s(sQh, pQh, 16384, mbq);
            bulk_g2s(sQl, pQl, 16384, mbq);
            const int npro = ntiles < A_NSTAGE ? ntiles : A_NSTAGE;
            for (int c = 0; c < npro; c++) {
                uint32_t st = stage0 + c * ATT_STAGE;
                uint32_t mb = sbase + 16 + 8 * c;
                MBAR_EXPECT_TX(mb, ATT_STAGE);
                bulk_g2s(st + 0,     pKh + (size_t)c * 16384, 16384, mb);
                bulk_g2s(st + 16384, pKl + (size_t)c * 16384, 16384, mb);
                bulk_g2s(st + 32768, pVh + (size_t)c * 16384, 16384, mb);
                bulk_g2s(st + 49152, pVl + (size_t)c * 16384, 16384, mb);
            }
        }

        // Q fragments (persist for the job)
        mbar_wait(mbq, 0);
        uint32_t qh[4][4], ql[4][4];
#pragma unroll
        for (int ks = 0; ks < 4; ks++) {
            int row = w * 16 + a_row_off;
            uint32_t off = (uint32_t)(row * 128) +
                           (uint32_t)((ks * 32 + a_kb_off) ^ ((row & 7) << 4));
            ldsm_x4(qh[ks][0], qh[ks][1], qh[ks][2], qh[ks][3], sQh + off);
            ldsm_x4(ql[ks][0], ql[ks][1], ql[ks][2], ql[ks][3], sQl + off);
        }

        float acc_o[8][4];
#pragma unroll
        for (int j = 0; j < 8; j++)
#pragma unroll
            for (int e = 0; e < 4; e++) acc_o[j][e] = 0.f;
        float m0 = -1e30f, m1 = -1e30f, l0 = 0.f, l1 = 0.f;

        for (int kt = 0; kt < ntiles; kt++) {
            const int s = kt % A_NSTAGE;
            const uint32_t phs = (uint32_t)((kt / A_NSTAGE) & 1);
            mbar_wait(sbase + 16 + 8 * s, phs);
            const uint32_t stKh = stage0 + s * ATT_STAGE;
            const uint32_t stKl = stKh + 16384;
            const uint32_t stVh = stKh + 32768;
            const uint32_t stVl = stKh + 49152;

            // --- S = Q K^T (3-term compensated), log2 units
            float acc_s[16][4];
#pragma unroll
            for (int j = 0; j < 16; j++)
#pragma unroll
                for (int e = 0; e < 4; e++) acc_s[j][e] = 0.f;

#pragma unroll
            for (int ks = 0; ks < 4; ks++) {
                const uint32_t kb = (uint32_t)(ks * 32 + b_kb_off);
#pragma unroll
                for (int g = 0; g < 8; g++) {
                    int row = g * 16 + b_row_off;
                    uint32_t off = (uint32_t)(row * 128) + (kb ^ (uint32_t)((row & 7) << 4));
                    uint32_t kfh[4], kfl[4];
                    ldsm_x4(kfh[0], kfh[1], kfh[2], kfh[3], stKh + off);
                    ldsm_x4(kfl[0], kfl[1], kfl[2], kfl[3], stKl + off);
                    mma_bf16(acc_s[2 * g],     qh[ks], kfh);
                    mma_bf16(acc_s[2 * g],     qh[ks], kfl);
                    mma_bf16(acc_s[2 * g],     ql[ks], kfh);
                    mma_bf16(acc_s[2 * g + 1], qh[ks], kfh + 2);
                    mma_bf16(acc_s[2 * g + 1], qh[ks], kfl + 2);
                    mma_bf16(acc_s[2 * g + 1], ql[ks], kfh + 2);
                }
            }

            // --- causal mask on the diagonal tile
            if (kt == qt) {
                const int rr0 = w * 16 + lr, rr1 = rr0 + 8;
#pragma unroll
                for (int j = 0; j < 16; j++) {
                    const int c0 = j * 8 + qp * 2;
                    if (c0     > rr0) acc_s[j][0] = -1e30f;
                    if (c0 + 1 > rr0) acc_s[j][1] = -1e30f;
                    if (c0     > rr1) acc_s[j][2] = -1e30f;
                    if (c0 + 1 > rr1) acc_s[j][3] = -1e30f;
                }
            }

            // --- online softmax (base-2)
            float t0 = -1e30f, t1 = -1e30f;
#pragma unroll
            for (int j = 0; j < 16; j++) {
                t0 = fmaxf(t0, fmaxf(acc_s[j][0], acc_s[j][1]));
                t1 = fmaxf(t1, fmaxf(acc_s[j][2], acc_s[j][3]));
            }
            t0 = fmaxf(t0, __shfl_xor_sync(0xffffffffu, t0, 1));
            t0 = fmaxf(t0, __shfl_xor_sync(0xffffffffu, t0, 2));
            t1 = fmaxf(t1, __shfl_xor_sync(0xffffffffu, t1, 1));
            t1 = fmaxf(t1, __shfl_xor_sync(0xffffffffu, t1, 2));

            const float mn0 = fmaxf(m0, t0);
            const float mn1 = fmaxf(m1, t1);
            const float cr0 = ex2(m0 - mn0);
            const float cr1 = ex2(m1 - mn1);
            m0 = mn0; m1 = mn1;
            l0 *= cr0; l1 *= cr1;
#pragma unroll
            for (int j = 0; j < 8; j++) {
                acc_o[j][0] *= cr0; acc_o[j][1] *= cr0;
                acc_o[j][2] *= cr1; acc_o[j][3] *= cr1;
            }

            // --- interleaved exp/pack + PV MMAs
#pragma unroll
            for (int kc = 0; kc < 8; kc++) {
                uint32_t ph[4], pl[4];
#pragma unroll
                for (int jj = 0; jj < 2; jj++) {
                    const int j = 2 * kc + jj;
                    const float p0 = ex2(acc_s[j][0] - mn0);
                    const float p1 = ex2(acc_s[j][1] - mn0);
                    const float p2 = ex2(acc_s[j][2] - mn1);
                    const float p3 = ex2(acc_s[j][3] - mn1);
                    l0 += p0 + p1; l1 += p2 + p3;
                    float r0, r1, r2, r3;
                    ph[jj * 2 + 0] = packres(p0, p1, r0, r1);
                    ph[jj * 2 + 1] = packres(p2, p3, r2, r3);
                    pl[jj * 2 + 0] = packlo(r0, r1);
                    pl[jj * 2 + 1] = packlo(r2, r3);
                }
                const uint32_t vhb = stVh + ((kc < 4) ? 0u : 8192u);
                const uint32_t vlb = stVl + ((kc < 4) ? 0u : 8192u);
                const uint32_t kb = (uint32_t)((kc & 3) * 32 + b_kb_off);
#pragma unroll
                for (int g = 0; g < 4; g++) {
                    int row = g * 16 + b_row_off;
                    uint32_t off = (uint32_t)(row * 128) + (kb ^ (uint32_t)((row & 7) << 4));
                    uint32_t vfh[4], vfl[4];
                    ldsm_x4(vfh[0], vfh[1], vfh[2], vfh[3], vhb + off);
                    ldsm_x4(vfl[0], vfl[1], vfl[2], vfl[3], vlb + off);
                    mma_bf16(acc_o[2 * g],     ph, vfh);
                    mma_bf16(acc_o[2 * g],     ph, vfl);
                    mma_bf16(acc_o[2 * g],     pl, vfh);
                    mma_bf16(acc_o[2 * g + 1], ph, vfh + 2);
                    mma_bf16(acc_o[2 * g + 1], ph, vfl + 2);
                    mma_bf16(acc_o[2 * g + 1], pl, vfh + 2);
                }
            }

            MBAR_ARRIVE(sbase + 40 + 8 * s);

            if (tid == 0 && kt + A_NSTAGE < ntiles) {
                mbar_wait(sbase + 40 + 8 * s, phs);
                FENCE_ASYNC();
                const int cn = kt + A_NSTAGE;
                const uint32_t mb = sbase + 16 + 8 * s;
                const uint32_t st = stage0 + s * ATT_STAGE;
                MBAR_EXPECT_TX(mb, ATT_STAGE);
                bulk_g2s(st + 0,     pKh + (size_t)cn * 16384, 16384, mb);
                bulk_g2s(st + 16384, pKl + (size_t)cn * 16384, 16384, mb);
                bulk_g2s(st + 32768, pVh + (size_t)cn * 16384, 16384, mb);
                bulk_g2s(st + 49152, pVl + (size_t)cn * 16384, 16384, mb);
            }
        }

        // --- epilogue: normalize, split hi/lo, write y as proj A-tiles
        l0 += __shfl_xor_sync(0xffffffffu, l0, 1);
        l0 += __shfl_xor_sync(0xffffffffu, l0, 2);
        l1 += __shfl_xor_sync(0xffffffffu, l1, 1);
        l1 += __shfl_xor_sync(0xffffffffu, l1, 2);
        const float inv0 = 1.f / l0;
        const float inv1 = 1.f / l1;

        const size_t tb = ((size_t)(b * 16 + qt) * NKC + h) * 8192;
        char* th = (char*)(oYh + tb);
        char* tl = (char*)(oYl + tb);
        const int rl0 = w * 16 + lr;
#pragma unroll
        for (int j = 0; j < 8; j++) {
            const int dc = j * 8 + qp * 2;
            float r0, r1;
            const uint32_t h0 = packres(acc_o[j][0] * inv0, acc_o[j][1] * inv0, r0, r1);
            const uint32_t lo0 = packlo(r0, r1);
            const uint32_t off0 = SWZ128((uint32_t)(rl0 * 128 + dc * 2));
            *(uint32_t*)(th + off0) = h0;
            *(uint32_t*)(tl + off0) = lo0;
            const uint32_t h1 = packres(acc_o[j][2] * inv1, acc_o[j][3] * inv1, r0, r1);
            const uint32_t lo1 = packlo(r0, r1);
            const uint32_t off1 = SWZ128((uint32_t)((rl0 + 8) * 128 + dc * 2));
            *(uint32_t*)(th + off1) = h1;
            *(uint32_t*)(tl + off1) = lo1;
        }

        __syncthreads();   // all threads done with smem/barriers before next job's reinit
    }
}

// ---------------------------------------------------------------------------
// Launch
// ---------------------------------------------------------------------------
extern "C" void kernel_launch(void* const* d_in, const int* in_sizes, int n_in,
                              void* d_out, int out_size)
{
    const float* x     = (const float*)d_in[0];
    const float* Wqkv  = (const float*)d_in[1];
    const float* bqkv  = (const float*)d_in[2];
    const float* Wproj = (const float*)d_in[3];
    const float* bproj = (const float*)d_in[4];
    float* out = (float*)d_out;

    __nv_bfloat16 *xh, *xl, *yh, *yl, *wqh, *wql, *wph, *wpl;
    __nv_bfloat16 *aqh, *aql, *akh, *akl, *avh, *avl;
    cudaGetSymbolAddress((void**)&xh, g_xh);
    cudaGetSymbolAddress((void**)&xl, g_xl);
    cudaGetSymbolAddress((void**)&yh, g_yh);
    cudaGetSymbolAddress((void**)&yl, g_yl);
    cudaGetSymbolAddress((void**)&wqh, g_wqkvh);
    cudaGetSymbolAddress((void**)&wql, g_wqkvl);
    cudaGetSymbolAddress((void**)&wph, g_wprojh);
    cudaGetSymbolAddress((void**)&wpl, g_wprojl);
    cudaGetSymbolAddress((void**)&aqh, g_qh);
    cudaGetSymbolAddress((void**)&aql, g_ql);
    cudaGetSymbolAddress((void**)&akh, g_kh);
    cudaGetSymbolAddress((void**)&akl, g_kl);
    cudaGetSymbolAddress((void**)&avh, g_vh);
    cudaGetSymbolAddress((void**)&avl, g_vl);

    cudaFuncSetAttribute(gemm_mma_kernel<0>,
                         cudaFuncAttributeMaxDynamicSharedMemorySize, GEMM_SMEM);
    cudaFuncSetAttribute(gemm_mma_kernel<1>,
                         cudaFuncAttributeMaxDynamicSharedMemorySize, GEMM_SMEM);
    cudaFuncSetAttribute(flash_mma_kernel,
                         cudaFuncAttributeMaxDynamicSharedMemorySize, ATT_SMEM);

    // Combined prep (x split + both weight transposes)
    prep_all_kernel<<<1536, 256>>>(x, xh, xl, Wqkv, wqh, wql, Wproj, wph, wpl);

    // QKV GEMM with fused Q/K/V-tile epilogue (Q pre-scaled for exp2 softmax)
    gemm_mma_kernel<1><<<dim3(N_QKV / 256, MTOK / 128), 256, GEMM_SMEM>>>(
        xh, xl, wqh, wql, bqkv, nullptr, N_QKV,
        aqh, aql, akh, akl, avh, avl);

    // Persistent flash attention (static snake-balanced schedule)
    flash_mma_kernel<<<NWORK, 256, ATT_SMEM>>>(
        aqh, aql, akh, akl, avh, avl, yh, yl);

    // Proj GEMM: out = y @ Wproj + bproj (fp32 epilogue)
    gemm_mma_kernel<0><<<dim3(CC / 256, MTOK / 128), 256, GEMM_SMEM>>>(
        yh, yl, wph, wpl, bproj, out, CC,
        nullptr, nullptr, nullptr, nullptr, nullptr, nullptr);
}

// round 9
// speedup vs baseline: 10.6503x; 2.4011x over previous
#include <cuda_runtime.h>
#include <cuda_fp16.h>
#include <math.h>
#include <stdint.h>

// Problem constants
#define BB 4
#define TT 2048
#define CC 1024
#define HH 16
#define DD 64
#define MTOK (BB * TT)          // 8192 tokens
#define N_QKV (3 * CC)          // 3072
#define NKC 16                  // K chunks: 1024 / 64

#define LOG2E 1.4426950408889634f
#define NWORK 152               // persistent attention workers (GB300: 152 SMs)

// ---------------------------------------------------------------------------
// Scratch (allocation-free rule: __device__ globals) — fp16 single precision
// ---------------------------------------------------------------------------
__device__ __half g_x16[(size_t)MTOK * CC];
__device__ __half g_y16[(size_t)MTOK * CC];
__device__ __half g_wqkv16[(size_t)N_QKV * CC];
__device__ __half g_wproj16[(size_t)CC * CC];
// attention operand tiles (per (b,h), SW128 swizzled fp16)
__device__ __half g_q16[(size_t)BB * HH * 16 * 8192];
__device__ __half g_k16[(size_t)BB * HH * 16 * 8192];
__device__ __half g_v16[(size_t)BB * HH * 32 * 4096];

// ---------------------------------------------------------------------------
// PTX helpers (base sm_103 target — NO tcgen05)
// ---------------------------------------------------------------------------
__device__ __forceinline__ uint32_t smem_u32(const void* p) {
    uint32_t a;
    asm("{ .reg .u64 t; cvta.to.shared.u64 t, %1; cvt.u32.u64 %0, t; }" : "=r"(a) : "l"(p));
    return a;
}

#define SWZ128(off) ((off) ^ (((off) >> 3) & 0x70))

#define MBAR_INIT(addr, cnt) \
    asm volatile("mbarrier.init.shared.b64 [%0], %1;" :: "r"(addr), "r"(cnt) : "memory")

#define MBAR_EXPECT_TX(addr, bytes) \
    asm volatile("mbarrier.arrive.expect_tx.shared.b64 _, [%0], %1;" :: "r"(addr), "r"(bytes) : "memory")

#define MBAR_ARRIVE(addr) \
    asm volatile("mbarrier.arrive.shared.b64 _, [%0];" :: "r"(addr) : "memory")

__device__ __forceinline__ void mbar_wait(uint32_t mbar, uint32_t parity) {
    uint32_t done;
    asm volatile(
        "{\n\t.reg .pred p;\n\t"
        "mbarrier.try_wait.parity.acquire.cta.shared::cta.b64 p, [%1], %2;\n\t"
        "selp.b32 %0, 1, 0, p;\n\t}"
        : "=r"(done) : "r"(mbar), "r"(parity) : "memory");
    if (!done) {
        asm volatile(
            "{\n\t.reg .pred P1;\n\t"
            "WL_%=:\n\t"
            "mbarrier.try_wait.parity.acquire.cta.shared::cta.b64 P1, [%0], %1, 0x989680;\n\t"
            "@P1 bra.uni WD_%=;\n\t"
            "bra.uni WL_%=;\n\t"
            "WD_%=:\n\t}"
            :: "r"(mbar), "r"(parity) : "memory");
    }
}

__device__ __forceinline__ void bulk_g2s(uint32_t dst, const void* src, uint32_t bytes, uint32_t mbar) {
    asm volatile(
        "cp.async.bulk.shared::cluster.global.mbarrier::complete_tx::bytes [%0], [%1], %2, [%3];"
        :: "r"(dst), "l"(src), "r"(bytes), "r"(mbar) : "memory");
}

#define FENCE_ASYNC() asm volatile("fence.proxy.async.shared::cta;" ::: "memory")

__device__ __forceinline__ void ldsm_x4(uint32_t& r0, uint32_t& r1, uint32_t& r2, uint32_t& r3,
                                        uint32_t addr) {
    asm volatile("ldmatrix.sync.aligned.m8n8.x4.shared.b16 {%0,%1,%2,%3}, [%4];"
                 : "=r"(r0), "=r"(r1), "=r"(r2), "=r"(r3) : "r"(addr));
}

__device__ __forceinline__ void mma_f16(float* d, const uint32_t* a, const uint32_t* b) {
    asm volatile(
        "mma.sync.aligned.m16n8k16.row.col.f32.f16.f16.f32 "
        "{%0,%1,%2,%3}, {%4,%5,%6,%7}, {%8,%9}, {%0,%1,%2,%3};"
        : "+f"(d[0]), "+f"(d[1]), "+f"(d[2]), "+f"(d[3])
        : "r"(a[0]), "r"(a[1]), "r"(a[2]), "r"(a[3]), "r"(b[0]), "r"(b[1]));
}

__device__ __forceinline__ float ex2(float x) {
    float r;
    asm("ex2.approx.f32 %0, %1;" : "=f"(r) : "f"(x));
    return r;
}

// pack two floats into fp16x2 (low = a, high = b)
__device__ __forceinline__ uint32_t packh2(float a, float b) {
    __half2 h = __floats2half2_rn(a, b);
    return *(uint32_t*)&h;
}

// ---------------------------------------------------------------------------
// Combined prep kernel: [0,1024) split x; [1024,1408) Wqkv^T; [1408,1536) Wproj^T
// ---------------------------------------------------------------------------
__global__ __launch_bounds__(256) void prep_all_kernel(
    const float* __restrict__ x, __half* __restrict__ x16,
    const float* __restrict__ Wq, __half* __restrict__ wq16,
    const float* __restrict__ Wp, __half* __restrict__ wp16)
{
    __shared__ float s[64][128];
    const int id = blockIdx.x;
    const int t = threadIdx.x;

    if (id < 1024) {
        const int kc = id & 15;
        const int mt = id >> 4;
        const int r = t >> 1;
        const int hh = t & 1;
        const float* src = x + (size_t)(mt * 128 + r) * CC + kc * 64 + hh * 32;
        char* bh = (char*)(x16 + ((size_t)mt * NKC + kc) * 8192);
#pragma unroll
        for (int j = 0; j < 4; j++) {
            float4 v0 = ((const float4*)src)[j * 2 + 0];
            float4 v1 = ((const float4*)src)[j * 2 + 1];
            __align__(16) __half h8[8];
            h8[0] = __float2half_rn(v0.x); h8[1] = __float2half_rn(v0.y);
            h8[2] = __float2half_rn(v0.z); h8[3] = __float2half_rn(v0.w);
            h8[4] = __float2half_rn(v1.x); h8[5] = __float2half_rn(v1.y);
            h8[6] = __float2half_rn(v1.z); h8[7] = __float2half_rn(v1.w);
            uint32_t off = SWZ128((uint32_t)(r * 128 + hh * 64 + j * 16));
            *(uint4*)(bh + off) = *(const uint4*)h8;
        }
        return;
    }

    const bool isQ = (id < 1408);
    const int v = isQ ? (id - 1024) : (id - 1408);
    const int kc = v & 15;
    const int nt = v >> 4;
    const float* W = isQ ? Wq : Wp;
    __half* oh = isQ ? wq16 : wp16;
    const int N = isQ ? N_QKV : CC;

    for (int idx = t; idx < 64 * 128; idx += 256) {
        int r = idx >> 7, n = idx & 127;
        s[r][n] = W[(size_t)(kc * 64 + r) * N + nt * 128 + n];
    }
    __syncthreads();

    const int np = t & 127;
    const int c0 = (t >> 7) * 4;
    char* bh = (char*)(oh + ((size_t)nt * NKC + kc) * 8192);

#pragma unroll
    for (int c = c0; c < c0 + 4; c++) {
        __align__(16) __half h8[8];
#pragma unroll
        for (int j = 0; j < 8; j++) h8[j] = __float2half_rn(s[c * 8 + j][np]);
        uint32_t off = SWZ128((uint32_t)(np * 128 + c * 16));
        *(uint4*)(bh + off) = *(const uint4*)h8;
    }
}

// ---------------------------------------------------------------------------
// mma.sync fp16 GEMM, CTA 128x256, warps 64x64, BK=64, 4-stage pipeline.
// MODE 0: C = A@W + bias (fp32).  MODE 1: QKV fused epilogue.
// ---------------------------------------------------------------------------
#define G_STAGE 49152u      // A 16K | B0 16K | B1 16K
#define G_NSTAGE 4
#define GEMM_SMEM (1024u + G_NSTAGE * G_STAGE)

template <int MODE>
__global__ __launch_bounds__(256) void gemm_mma_kernel(
    const __half* __restrict__ A_, const __half* __restrict__ B_,
    const float* __restrict__ bias, float* __restrict__ C, int N,
    __half* __restrict__ oQ, __half* __restrict__ oK, __half* __restrict__ oV)
{
    extern __shared__ __align__(1024) char smem[];
    const uint32_t sbase = smem_u32(smem);
    const int tid = threadIdx.x;
    const int nt = blockIdx.x;
    const int mt = blockIdx.y;

    const uint32_t stage0 = sbase + 1024;

    if (tid == 0) {
#pragma unroll
        for (int s = 0; s < G_NSTAGE; s++) {
            MBAR_INIT(sbase + 8 + 8 * s, 1);       // full
            MBAR_INIT(sbase + 64 + 8 * s, 256);    // empty
        }
    }
    __syncthreads();

    const char* pA  = (const char*)(A_ + (size_t)mt * NKC * 8192);
    const char* pB0 = (const char*)(B_ + (size_t)(2 * nt) * NKC * 8192);
    const char* pB1 = (const char*)(B_ + (size_t)(2 * nt + 1) * NKC * 8192);

    if (tid == 0) {
#pragma unroll
        for (int c = 0; c < G_NSTAGE; c++) {
            uint32_t st = stage0 + c * G_STAGE;
            uint32_t mb = sbase + 8 + 8 * c;
            MBAR_EXPECT_TX(mb, G_STAGE);
            bulk_g2s(st + 0,     pA  + (size_t)c * 16384, 16384, mb);
            bulk_g2s(st + 16384, pB0 + (size_t)c * 16384, 16384, mb);
            bulk_g2s(st + 32768, pB1 + (size_t)c * 16384, 16384, mb);
        }
    }

    const int w = tid >> 5, l = tid & 31;
    const int mrow = (w >> 2) * 64;
    const int ncol = (w & 3) * 64;
    const int mat = l >> 3;
    const int rin = l & 7;

    const int a_row_off = rin + ((mat & 1) << 3);
    const int a_kb_off  = (mat >> 1) << 4;
    const int b_row_off = rin + ((mat >> 1) << 3);
    const int b_kb_off  = (mat & 1) << 4;

    float acc[4][8][4];
#pragma unroll
    for (int i = 0; i < 4; i++)
#pragma unroll
        for (int j = 0; j < 8; j++)
#pragma unroll
            for (int k = 0; k < 4; k++) acc[i][j][k] = 0.f;

    for (int c = 0; c < NKC; c++) {
        const int s = c & (G_NSTAGE - 1);
        const uint32_t ph = (uint32_t)((c / G_NSTAGE) & 1);
        mbar_wait(sbase + 8 + 8 * s, ph);

        const uint32_t stA = stage0 + s * G_STAGE;
        const uint32_t stB = stA + 16384;   // 256 rows x 64 cols contiguous

#pragma unroll
        for (int ks = 0; ks < 4; ks++) {
            const int kb = ks * 32;
            uint32_t bf[8][2];
#pragma unroll
            for (int n16 = 0; n16 < 4; n16++) {
                int row = ncol + n16 * 16 + b_row_off;
                uint32_t off = (uint32_t)(row * 128) +
                               (uint32_t)((kb + b_kb_off) ^ ((row & 7) << 4));
                ldsm_x4(bf[n16 * 2][0], bf[n16 * 2][1],
                        bf[n16 * 2 + 1][0], bf[n16 * 2 + 1][1], stB + off);
            }
#pragma unroll
            for (int m16 = 0; m16 < 4; m16++) {
                int row = mrow + m16 * 16 + a_row_off;
                uint32_t off = (uint32_t)(row * 128) +
                               (uint32_t)((kb + a_kb_off) ^ ((row & 7) << 4));
                uint32_t a[4];
                ldsm_x4(a[0], a[1], a[2], a[3], stA + off);
#pragma unroll
                for (int n8 = 0; n8 < 8; n8++) mma_f16(acc[m16][n8], a, bf[n8]);
            }
        }

        MBAR_ARRIVE(sbase + 64 + 8 * s);

        if (tid == 0 && c + G_NSTAGE < NKC) {
            mbar_wait(sbase + 64 + 8 * s, ph);
            FENCE_ASYNC();
            const int cn = c + G_NSTAGE;
            const uint32_t mb = sbase + 8 + 8 * s;
            const uint32_t st = stage0 + s * G_STAGE;
            MBAR_EXPECT_TX(mb, G_STAGE);
            bulk_g2s(st + 0,     pA  + (size_t)cn * 16384, 16384, mb);
            bulk_g2s(st + 16384, pB0 + (size_t)cn * 16384, 16384, mb);
            bulk_g2s(st + 32768, pB1 + (size_t)cn * 16384, 16384, mb);
        }
    }

    const int lr = l >> 2;
    const int lc = (l & 3) * 2;

    if constexpr (MODE == 0) {
#pragma unroll
        for (int m16 = 0; m16 < 4; m16++) {
            const size_t r0 = (size_t)(mt * 128 + mrow + m16 * 16 + lr);
            float* c0p = C + r0 * N;
            float* c1p = c0p + (size_t)8 * N;
#pragma unroll
            for (int n8 = 0; n8 < 8; n8++) {
                const int col = nt * 256 + ncol + n8 * 8 + lc;
                const float bx = bias[col], by = bias[col + 1];
                float2 v0 = make_float2(acc[m16][n8][0] + bx, acc[m16][n8][1] + by);
                float2 v1 = make_float2(acc[m16][n8][2] + bx, acc[m16][n8][3] + by);
                *(float2*)(c0p + col) = v0;
                *(float2*)(c1p + col) = v1;
            }
        }
    } else {
        const int b_ = mt >> 4;
        const int qt_ = mt & 15;
        if (nt < 8) {
            const bool isQ = (nt < 4);
            __half* oh = isQ ? oQ : oK;
            const float scale = isQ ? (0.125f * LOG2E) : 1.0f;
            const int base0 = nt * 256 - (isQ ? 0 : 1024);
#pragma unroll
            for (int m16 = 0; m16 < 4; m16++) {
                const int rl0 = mrow + m16 * 16 + lr;
#pragma unroll
                for (int n8 = 0; n8 < 8; n8++) {
                    const int cl = ncol + n8 * 8 + lc;
                    const int base = base0 + cl;
                    const int head = base >> 6;
                    const int d = base & 63;
                    const float bx = bias[nt * 256 + cl];
                    const float by = bias[nt * 256 + cl + 1];
                    const size_t tb = ((size_t)(b_ * HH + head) * 16 + qt_) * 8192;
                    char* th = (char*)(oh + tb);
                    const uint32_t h0 = packh2((acc[m16][n8][0] + bx) * scale,
                                               (acc[m16][n8][1] + by) * scale);
                    const uint32_t off0 = SWZ128((uint32_t)(rl0 * 128 + d * 2));
                    *(uint32_t*)(th + off0) = h0;
                    const uint32_t h1 = packh2((acc[m16][n8][2] + bx) * scale,
                                               (acc[m16][n8][3] + by) * scale);
                    const uint32_t off1 = SWZ128((uint32_t)((rl0 + 8) * 128 + d * 2));
                    *(uint32_t*)(th + off1) = h1;
                }
            }
        } else {
            // V: transpose through smem (stage buffers free), write V^T fp16
            float* sf = (float*)(smem + 1024);   // [128][260] fp32 = 133 KB < 192 KB
            __syncthreads();
#pragma unroll
            for (int m16 = 0; m16 < 4; m16++) {
                const int rl0 = mrow + m16 * 16 + lr;
#pragma unroll
                for (int n8 = 0; n8 < 8; n8++) {
                    const int cl = ncol + n8 * 8 + lc;
                    const float bx = bias[nt * 256 + cl];
                    const float by = bias[nt * 256 + cl + 1];
                    sf[rl0 * 260 + cl]           = acc[m16][n8][0] + bx;
                    sf[rl0 * 260 + cl + 1]       = acc[m16][n8][1] + by;
                    sf[(rl0 + 8) * 260 + cl]     = acc[m16][n8][2] + bx;
                    sf[(rl0 + 8) * 260 + cl + 1] = acc[m16][n8][3] + by;
                }
            }
            __syncthreads();
            const int ntv = nt - 8;
            for (int ch = tid; ch < 4096; ch += 256) {
                const int hh2 = ch >> 10;
                const int rem = ch & 1023;
                const int kt2loc = rem >> 9;
                const int d = (rem >> 3) & 63;
                const int oct = rem & 7;
                __align__(16) __half h8[8];
#pragma unroll
                for (int e = 0; e < 8; e++) {
                    const int key = kt2loc * 64 + oct * 8 + e;
                    h8[e] = __float2half_rn(sf[key * 260 + hh2 * 64 + d]);
                }
                const size_t tb =
                    ((size_t)(b_ * HH + ntv * 4 + hh2) * 32 + qt_ * 2 + kt2loc) * 4096;
                const uint32_t off = SWZ128((uint32_t)(d * 128 + oct * 16));
                *(uint4*)((char*)(oV + tb) + off) = *(const uint4*)h8;
            }
        }
    }
}

// ---------------------------------------------------------------------------
// PERSISTENT flash attention (fp16 single), 6-stage K/V pipeline,
// static snake-balanced job schedule.
// ---------------------------------------------------------------------------
#define ATT_STAGE 32768u        // K 16K | V 16K
#define A_NSTAGE 6
#define ATT_SMEM  (1024u + 16384u + A_NSTAGE * ATT_STAGE)
#define NJOBS 1024

__global__ __launch_bounds__(256) void flash_mma_kernel(
    const __half* __restrict__ Q_, const __half* __restrict__ K_,
    const __half* __restrict__ V_, __half* __restrict__ oY)
{
    extern __shared__ __align__(1024) char smem[];
    const uint32_t sbase = smem_u32(smem);
    const int tid = threadIdx.x;
    const int worker = (int)blockIdx.x;

    const uint32_t mbq = sbase + 8;
    const uint32_t sQ = sbase + 1024;
    const uint32_t stage0 = sQ + 16384;

    const int w = tid >> 5, l = tid & 31;
    const int mat = l >> 3, rin = l & 7;
    const int a_row_off = rin + ((mat & 1) << 3);
    const int a_kb_off  = (mat >> 1) << 4;
    const int b_row_off = rin + ((mat >> 1) << 3);
    const int b_kb_off  = (mat & 1) << 4;
    const int lr = l >> 2, qp = l & 3;

    for (int p = 0;; p++) {
        const int rank = p * NWORK + ((p & 1) ? (NWORK - 1 - worker) : worker);
        if (rank >= NJOBS) break;
        const int qt = 15 - (rank >> 6);
        const int bh_idx = rank & 63;
        const int b = bh_idx >> 4;
        const int h = bh_idx & 15;

        if (tid == 0) {
            MBAR_INIT(mbq, 1);
#pragma unroll
            for (int s = 0; s < A_NSTAGE; s++) {
                MBAR_INIT(sbase + 16 + 8 * s, 1);
                MBAR_INIT(sbase + 80 + 8 * s, 256);
            }
        }
        __syncthreads();

        const char* pQ = (const char*)(Q_ + ((size_t)bh_idx * 16 + qt) * 8192);
        const char* pK = (const char*)(K_ + (size_t)bh_idx * 16 * 8192);
        const char* pV = (const char*)(V_ + (size_t)bh_idx * 32 * 4096);

        const int ntiles = qt + 1;

        if (tid == 0) {
            MBAR_EXPECT_TX(mbq, 16384);
            bulk_g2s(sQ, pQ, 16384, mbq);
            const int npro = ntiles < A_NSTAGE ? ntiles : A_NSTAGE;
            for (int c = 0; c < npro; c++) {
                uint32_t st = stage0 + c * ATT_STAGE;
                uint32_t mb = sbase + 16 + 8 * c;
                MBAR_EXPECT_TX(mb, ATT_STAGE);
                bulk_g2s(st + 0,     pK + (size_t)c * 16384, 16384, mb);
                bulk_g2s(st + 16384, pV + (size_t)c * 16384, 16384, mb);
            }
        }

        // Q fragments (persist for the job)
        mbar_wait(mbq, 0);
        uint32_t qf[4][4];
#pragma unroll
        for (int ks = 0; ks < 4; ks++) {
            int row = w * 16 + a_row_off;
            uint32_t off = (uint32_t)(row * 128) +
                           (uint32_t)((ks * 32 + a_kb_off) ^ ((row & 7) << 4));
            ldsm_x4(qf[ks][0], qf[ks][1], qf[ks][2], qf[ks][3], sQ + off);
        }

        float acc_o[8][4];
#pragma unroll
        for (int j = 0; j < 8; j++)
#pragma unroll
            for (int e = 0; e < 4; e++) acc_o[j][e] = 0.f;
        float m0 = -1e30f, m1 = -1e30f, l0 = 0.f, l1 = 0.f;

        for (int kt = 0; kt < ntiles; kt++) {
            const int s = kt % A_NSTAGE;
            const uint32_t phs = (uint32_t)((kt / A_NSTAGE) & 1);
            mbar_wait(sbase + 16 + 8 * s, phs);
            const uint32_t stK = stage0 + s * ATT_STAGE;
            const uint32_t stV = stK + 16384;

            // --- S = Q K^T (fp16 single), log2 units
            float acc_s[16][4];
#pragma unroll
            for (int j = 0; j < 16; j++)
#pragma unroll
                for (int e = 0; e < 4; e++) acc_s[j][e] = 0.f;

#pragma unroll
            for (int ks = 0; ks < 4; ks++) {
                const uint32_t kb = (uint32_t)(ks * 32 + b_kb_off);
#pragma unroll
                for (int g = 0; g < 8; g++) {
                    int row = g * 16 + b_row_off;
                    uint32_t off = (uint32_t)(row * 128) + (kb ^ (uint32_t)((row & 7) << 4));
                    uint32_t kf[4];
                    ldsm_x4(kf[0], kf[1], kf[2], kf[3], stK + off);
                    mma_f16(acc_s[2 * g],     qf[ks], kf);
                    mma_f16(acc_s[2 * g + 1], qf[ks], kf + 2);
                }
            }

            // --- causal mask on the diagonal tile
            if (kt == qt) {
                const int rr0 = w * 16 + lr, rr1 = rr0 + 8;
#pragma unroll
                for (int j = 0; j < 16; j++) {
                    const int c0 = j * 8 + qp * 2;
                    if (c0     > rr0) acc_s[j][0] = -1e30f;
                    if (c0 + 1 > rr0) acc_s[j][1] = -1e30f;
                    if (c0     > rr1) acc_s[j][2] = -1e30f;
                    if (c0 + 1 > rr1) acc_s[j][3] = -1e30f;
                }
            }

            // --- online softmax (base-2)
            float t0 = -1e30f, t1 = -1e30f;
#pragma unroll
            for (int j = 0; j < 16; j++) {
                t0 = fmaxf(t0, fmaxf(acc_s[j][0], acc_s[j][1]));
                t1 = fmaxf(t1, fmaxf(acc_s[j][2], acc_s[j][3]));
            }
            t0 = fmaxf(t0, __shfl_xor_sync(0xffffffffu, t0, 1));
            t0 = fmaxf(t0, __shfl_xor_sync(0xffffffffu, t0, 2));
            t1 = fmaxf(t1, __shfl_xor_sync(0xffffffffu, t1, 1));
            t1 = fmaxf(t1, __shfl_xor_sync(0xffffffffu, t1, 2));

            const float mn0 = fmaxf(m0, t0);
            const float mn1 = fmaxf(m1, t1);
            const float cr0 = ex2(m0 - mn0);
            const float cr1 = ex2(m1 - mn1);
            m0 = mn0; m1 = mn1;
            l0 *= cr0; l1 *= cr1;
#pragma unroll
            for (int j = 0; j < 8; j++) {
                acc_o[j][0] *= cr0; acc_o[j][1] *= cr0;
                acc_o[j][2] *= cr1; acc_o[j][3] *= cr1;
            }

            // --- interleaved exp/pack + PV MMAs
#pragma unroll
            for (int kc = 0; kc < 8; kc++) {
                uint32_t pf[4];
#pragma unroll
                for (int jj = 0; jj < 2; jj++) {
                    const int j = 2 * kc + jj;
                    const float p0 = ex2(acc_s[j][0] - mn0);
                    const float p1 = ex2(acc_s[j][1] - mn0);
                    const float p2 = ex2(acc_s[j][2] - mn1);
                    const float p3 = ex2(acc_s[j][3] - mn1);
                    l0 += p0 + p1; l1 += p2 + p3;
                    pf[jj * 2 + 0] = packh2(p0, p1);
                    pf[jj * 2 + 1] = packh2(p2, p3);
                }
                const uint32_t vb = stV + ((kc < 4) ? 0u : 8192u);
                const uint32_t kb = (uint32_t)((kc & 3) * 32 + b_kb_off);
#pragma unroll
                for (int g = 0; g < 4; g++) {
                    int row = g * 16 + b_row_off;
                    uint32_t off = (uint32_t)(row * 128) + (kb ^ (uint32_t)((row & 7) << 4));
                    uint32_t vf[4];
                    ldsm_x4(vf[0], vf[1], vf[2], vf[3], vb + off);
                    mma_f16(acc_o[2 * g],     pf, vf);
                    mma_f16(acc_o[2 * g + 1], pf, vf + 2);
                }
            }

            MBAR_ARRIVE(sbase + 80 + 8 * s);

            if (tid == 0 && kt + A_NSTAGE < ntiles) {
                mbar_wait(sbase + 80 + 8 * s, phs);
                FENCE_ASYNC();
                const int cn = kt + A_NSTAGE;
                const uint32_t mb = sbase + 16 + 8 * s;
                const uint32_t st = stage0 + s * ATT_STAGE;
                MBAR_EXPECT_TX(mb, ATT_STAGE);
                bulk_g2s(st + 0,     pK + (size_t)cn * 16384, 16384, mb);
                bulk_g2s(st + 16384, pV + (size_t)cn * 16384, 16384, mb);
            }
        }

        // --- epilogue: normalize, write y as proj A-tiles (fp16)
        l0 += __shfl_xor_sync(0xffffffffu, l0, 1);
        l0 += __shfl_xor_sync(0xffffffffu, l0, 2);
        l1 += __shfl_xor_sync(0xffffffffu, l1, 1);
        l1 += __shfl_xor_sync(0xffffffffu, l1, 2);
        const float inv0 = 1.f / l0;
        const float inv1 = 1.f / l1;

        const size_t tb = ((size_t)(b * 16 + qt) * NKC + h) * 8192;
        char* th = (char*)(oY + tb);
        const int rl0 = w * 16 + lr;
#pragma unroll
        for (int j = 0; j < 8; j++) {
            const int dc = j * 8 + qp * 2;
            const uint32_t h0 = packh2(acc_o[j][0] * inv0, acc_o[j][1] * inv0);
            const uint32_t off0 = SWZ128((uint32_t)(rl0 * 128 + dc * 2));
            *(uint32_t*)(th + off0) = h0;
            const uint32_t h1 = packh2(acc_o[j][2] * inv1, acc_o[j][3] * inv1);
            const uint32_t off1 = SWZ128((uint32_t)((rl0 + 8) * 128 + dc * 2));
            *(uint32_t*)(th + off1) = h1;
        }

        __syncthreads();   // all threads done with smem/barriers before next job
    }
}

// ---------------------------------------------------------------------------
// Launch
// ---------------------------------------------------------------------------
extern "C" void kernel_launch(void* const* d_in, const int* in_sizes, int n_in,
                              void* d_out, int out_size)
{
    const float* x     = (const float*)d_in[0];
    const float* Wqkv  = (const float*)d_in[1];
    const float* bqkv  = (const float*)d_in[2];
    const float* Wproj = (const float*)d_in[3];
    const float* bproj = (const float*)d_in[4];
    float* out = (float*)d_out;

    __half *x16, *y16, *wq16, *wp16, *q16, *k16, *v16;
    cudaGetSymbolAddress((void**)&x16, g_x16);
    cudaGetSymbolAddress((void**)&y16, g_y16);
    cudaGetSymbolAddress((void**)&wq16, g_wqkv16);
    cudaGetSymbolAddress((void**)&wp16, g_wproj16);
    cudaGetSymbolAddress((void**)&q16, g_q16);
    cudaGetSymbolAddress((void**)&k16, g_k16);
    cudaGetSymbolAddress((void**)&v16, g_v16);

    cudaFuncSetAttribute(gemm_mma_kernel<0>,
                         cudaFuncAttributeMaxDynamicSharedMemorySize, GEMM_SMEM);
    cudaFuncSetAttribute(gemm_mma_kernel<1>,
                         cudaFuncAttributeMaxDynamicSharedMemorySize, GEMM_SMEM);
    cudaFuncSetAttribute(flash_mma_kernel,
                         cudaFuncAttributeMaxDynamicSharedMemorySize, ATT_SMEM);

    // Combined prep (x + both weight transposes, fp16)
    prep_all_kernel<<<1536, 256>>>(x, x16, Wqkv, wq16, Wproj, wp16);

    // QKV GEMM with fused Q/K/V-tile epilogue (Q pre-scaled for exp2 softmax)
    gemm_mma_kernel<1><<<dim3(N_QKV / 256, MTOK / 128), 256, GEMM_SMEM>>>(
        x16, wq16, bqkv, nullptr, N_QKV, q16, k16, v16);

    // Persistent flash attention (static snake-balanced schedule)
    flash_mma_kernel<<<NWORK, 256, ATT_SMEM>>>(q16, k16, v16, y16);

    // Proj GEMM: out = y @ Wproj + bproj (fp32 epilogue)
    gemm_mma_kernel<0><<<dim3(CC / 256, MTOK / 128), 256, GEMM_SMEM>>>(
        y16, wp16, bproj, out, CC, nullptr, nullptr, nullptr);
}

// round 10
// speedup vs baseline: 11.4458x; 1.0747x over previous
#include <cuda_runtime.h>
#include <cuda_fp16.h>
#include <math.h>
#include <stdint.h>

// Problem constants
#define BB 4
#define TT 2048
#define CC 1024
#define HH 16
#define DD 64
#define MTOK (BB * TT)          // 8192 tokens
#define N_QKV (3 * CC)          // 3072
#define NKC 16                  // K chunks: 1024 / 64

#define LOG2E 1.4426950408889634f
#define NWORK 152               // persistent attention workers (GB300: 152 SMs)

// ---------------------------------------------------------------------------
// Scratch (allocation-free rule: __device__ globals) — fp16 single precision
// ---------------------------------------------------------------------------
__device__ __half g_x16[(size_t)MTOK * CC];
__device__ __half g_y16[(size_t)MTOK * CC];
__device__ __half g_wqkv16[(size_t)N_QKV * CC];
__device__ __half g_wproj16[(size_t)CC * CC];
// attention operand tiles (per (b,h), SW128 swizzled fp16)
__device__ __half g_q16[(size_t)BB * HH * 16 * 8192];
__device__ __half g_k16[(size_t)BB * HH * 16 * 8192];
__device__ __half g_v16[(size_t)BB * HH * 32 * 4096];

// ---------------------------------------------------------------------------
// PTX helpers (base sm_103 target — NO tcgen05)
// ---------------------------------------------------------------------------
__device__ __forceinline__ uint32_t smem_u32(const void* p) {
    uint32_t a;
    asm("{ .reg .u64 t; cvta.to.shared.u64 t, %1; cvt.u32.u64 %0, t; }" : "=r"(a) : "l"(p));
    return a;
}

#define SWZ128(off) ((off) ^ (((off) >> 3) & 0x70))

#define MBAR_INIT(addr, cnt) \
    asm volatile("mbarrier.init.shared.b64 [%0], %1;" :: "r"(addr), "r"(cnt) : "memory")

#define MBAR_EXPECT_TX(addr, bytes) \
    asm volatile("mbarrier.arrive.expect_tx.shared.b64 _, [%0], %1;" :: "r"(addr), "r"(bytes) : "memory")

#define MBAR_ARRIVE(addr) \
    asm volatile("mbarrier.arrive.shared.b64 _, [%0];" :: "r"(addr) : "memory")

__device__ __forceinline__ void mbar_wait(uint32_t mbar, uint32_t parity) {
    uint32_t done;
    asm volatile(
        "{\n\t.reg .pred p;\n\t"
        "mbarrier.try_wait.parity.acquire.cta.shared::cta.b64 p, [%1], %2;\n\t"
        "selp.b32 %0, 1, 0, p;\n\t}"
        : "=r"(done) : "r"(mbar), "r"(parity) : "memory");
    if (!done) {
        asm volatile(
            "{\n\t.reg .pred P1;\n\t"
            "WL_%=:\n\t"
            "mbarrier.try_wait.parity.acquire.cta.shared::cta.b64 P1, [%0], %1, 0x989680;\n\t"
            "@P1 bra.uni WD_%=;\n\t"
            "bra.uni WL_%=;\n\t"
            "WD_%=:\n\t}"
            :: "r"(mbar), "r"(parity) : "memory");
    }
}

__device__ __forceinline__ void bulk_g2s(uint32_t dst, const void* src, uint32_t bytes, uint32_t mbar) {
    asm volatile(
        "cp.async.bulk.shared::cluster.global.mbarrier::complete_tx::bytes [%0], [%1], %2, [%3];"
        :: "r"(dst), "l"(src), "r"(bytes), "r"(mbar) : "memory");
}

#define FENCE_ASYNC() asm volatile("fence.proxy.async.shared::cta;" ::: "memory")

__device__ __forceinline__ void ldsm_x4(uint32_t& r0, uint32_t& r1, uint32_t& r2, uint32_t& r3,
                                        uint32_t addr) {
    asm volatile("ldmatrix.sync.aligned.m8n8.x4.shared.b16 {%0,%1,%2,%3}, [%4];"
                 : "=r"(r0), "=r"(r1), "=r"(r2), "=r"(r3) : "r"(addr));
}

__device__ __forceinline__ void mma_f16(float* d, const uint32_t* a, const uint32_t* b) {
    asm volatile(
        "mma.sync.aligned.m16n8k16.row.col.f32.f16.f16.f32 "
        "{%0,%1,%2,%3}, {%4,%5,%6,%7}, {%8,%9}, {%0,%1,%2,%3};"
        : "+f"(d[0]), "+f"(d[1]), "+f"(d[2]), "+f"(d[3])
        : "r"(a[0]), "r"(a[1]), "r"(a[2]), "r"(a[3]), "r"(b[0]), "r"(b[1]));
}

__device__ __forceinline__ float ex2(float x) {
    float r;
    asm("ex2.approx.f32 %0, %1;" : "=f"(r) : "f"(x));
    return r;
}
__device__ __forceinline__ uint32_t ex2h2(uint32_t x) {
    uint32_t r;
    asm("ex2.approx.f16x2 %0, %1;" : "=r"(r) : "r"(x));
    return r;
}

// pack two floats into fp16x2 (low = a, high = b)
__device__ __forceinline__ uint32_t packh2(float a, float b) {
    __half2 h = __floats2half2_rn(a, b);
    return *(uint32_t*)&h;
}

// ---------------------------------------------------------------------------
// Combined prep kernel: [0,1024) split x; [1024,1408) Wqkv^T; [1408,1536) Wproj^T
// ---------------------------------------------------------------------------
__global__ __launch_bounds__(256) void prep_all_kernel(
    const float* __restrict__ x, __half* __restrict__ x16,
    const float* __restrict__ Wq, __half* __restrict__ wq16,
    const float* __restrict__ Wp, __half* __restrict__ wp16)
{
    __shared__ float s[64][128];
    const int id = blockIdx.x;
    const int t = threadIdx.x;

    if (id < 1024) {
        const int kc = id & 15;
        const int mt = id >> 4;
        const int r = t >> 1;
        const int hh = t & 1;
        const float* src = x + (size_t)(mt * 128 + r) * CC + kc * 64 + hh * 32;
        char* bh = (char*)(x16 + ((size_t)mt * NKC + kc) * 8192);
#pragma unroll
        for (int j = 0; j < 4; j++) {
            float4 v0 = ((const float4*)src)[j * 2 + 0];
            float4 v1 = ((const float4*)src)[j * 2 + 1];
            __align__(16) __half h8[8];
            h8[0] = __float2half_rn(v0.x); h8[1] = __float2half_rn(v0.y);
            h8[2] = __float2half_rn(v0.z); h8[3] = __float2half_rn(v0.w);
            h8[4] = __float2half_rn(v1.x); h8[5] = __float2half_rn(v1.y);
            h8[6] = __float2half_rn(v1.z); h8[7] = __float2half_rn(v1.w);
            uint32_t off = SWZ128((uint32_t)(r * 128 + hh * 64 + j * 16));
            *(uint4*)(bh + off) = *(const uint4*)h8;
        }
        return;
    }

    const bool isQ = (id < 1408);
    const int v = isQ ? (id - 1024) : (id - 1408);
    const int kc = v & 15;
    const int nt = v >> 4;
    const float* W = isQ ? Wq : Wp;
    __half* oh = isQ ? wq16 : wp16;
    const int N = isQ ? N_QKV : CC;

    for (int idx = t; idx < 64 * 128; idx += 256) {
        int r = idx >> 7, n = idx & 127;
        s[r][n] = W[(size_t)(kc * 64 + r) * N + nt * 128 + n];
    }
    __syncthreads();

    const int np = t & 127;
    const int c0 = (t >> 7) * 4;
    char* bh = (char*)(oh + ((size_t)nt * NKC + kc) * 8192);

#pragma unroll
    for (int c = c0; c < c0 + 4; c++) {
        __align__(16) __half h8[8];
#pragma unroll
        for (int j = 0; j < 8; j++) h8[j] = __float2half_rn(s[c * 8 + j][np]);
        uint32_t off = SWZ128((uint32_t)(np * 128 + c * 16));
        *(uint4*)(bh + off) = *(const uint4*)h8;
    }
}

// ---------------------------------------------------------------------------
// mma.sync fp16 GEMM, CTA 128x128 (warps 64x32), BK=64, 3-stage pipeline,
// 2 CTAs/SM (regs<=128 via launch_bounds). MODE 0: fp32+bias. MODE 1: QKV
// fused epilogue (Q scaled by 0.125*log2e; K tiles; V transposed tiles).
// ---------------------------------------------------------------------------
#define G_STAGE 32768u      // A 16K | B 16K
#define G_NSTAGE 3
#define GEMM_SMEM (1024u + G_NSTAGE * G_STAGE)

template <int MODE>
__global__ __launch_bounds__(256, 2) void gemm_mma_kernel(
    const __half* __restrict__ A_, const __half* __restrict__ B_,
    const float* __restrict__ bias, float* __restrict__ C, int N,
    __half* __restrict__ oQ, __half* __restrict__ oK, __half* __restrict__ oV)
{
    extern __shared__ __align__(1024) char smem[];
    const uint32_t sbase = smem_u32(smem);
    const int tid = threadIdx.x;
    const int nt = blockIdx.x;
    const int mt = blockIdx.y;

    const uint32_t stage0 = sbase + 1024;

    if (tid == 0) {
#pragma unroll
        for (int s = 0; s < G_NSTAGE; s++) {
            MBAR_INIT(sbase + 8 + 8 * s, 1);       // full
            MBAR_INIT(sbase + 40 + 8 * s, 256);    // empty
        }
    }
    __syncthreads();

    const char* pA = (const char*)(A_ + (size_t)mt * NKC * 8192);
    const char* pB = (const char*)(B_ + (size_t)nt * NKC * 8192);

    if (tid == 0) {
#pragma unroll
        for (int c = 0; c < G_NSTAGE; c++) {
            uint32_t st = stage0 + c * G_STAGE;
            uint32_t mb = sbase + 8 + 8 * c;
            MBAR_EXPECT_TX(mb, G_STAGE);
            bulk_g2s(st + 0,     pA + (size_t)c * 16384, 16384, mb);
            bulk_g2s(st + 16384, pB + (size_t)c * 16384, 16384, mb);
        }
    }

    const int w = tid >> 5, l = tid & 31;
    const int mrow = (w >> 2) * 64;      // 0 or 64
    const int ncol = (w & 3) * 32;       // 0,32,64,96
    const int mat = l >> 3;
    const int rin = l & 7;

    const int a_row_off = rin + ((mat & 1) << 3);
    const int a_kb_off  = (mat >> 1) << 4;
    const int b_row_off = rin + ((mat >> 1) << 3);
    const int b_kb_off  = (mat & 1) << 4;

    float acc[4][4][4];
#pragma unroll
    for (int i = 0; i < 4; i++)
#pragma unroll
        for (int j = 0; j < 4; j++)
#pragma unroll
            for (int k = 0; k < 4; k++) acc[i][j][k] = 0.f;

    for (int c = 0; c < NKC; c++) {
        const int s = c % G_NSTAGE;
        const uint32_t ph = (uint32_t)((c / G_NSTAGE) & 1);
        mbar_wait(sbase + 8 + 8 * s, ph);

        const uint32_t stA = stage0 + s * G_STAGE;
        const uint32_t stB = stA + 16384;

#pragma unroll
        for (int ks = 0; ks < 4; ks++) {
            const int kb = ks * 32;
            uint32_t bf[4][2];
#pragma unroll
            for (int n16 = 0; n16 < 2; n16++) {
                int row = ncol + n16 * 16 + b_row_off;
                uint32_t off = (uint32_t)(row * 128) +
                               (uint32_t)((kb + b_kb_off) ^ ((row & 7) << 4));
                ldsm_x4(bf[n16 * 2][0], bf[n16 * 2][1],
                        bf[n16 * 2 + 1][0], bf[n16 * 2 + 1][1], stB + off);
            }
#pragma unroll
            for (int m16 = 0; m16 < 4; m16++) {
                int row = mrow + m16 * 16 + a_row_off;
                uint32_t off = (uint32_t)(row * 128) +
                               (uint32_t)((kb + a_kb_off) ^ ((row & 7) << 4));
                uint32_t a[4];
                ldsm_x4(a[0], a[1], a[2], a[3], stA + off);
#pragma unroll
                for (int n8 = 0; n8 < 4; n8++) mma_f16(acc[m16][n8], a, bf[n8]);
            }
        }

        MBAR_ARRIVE(sbase + 40 + 8 * s);

        if (tid == 0 && c + G_NSTAGE < NKC) {
            mbar_wait(sbase + 40 + 8 * s, ph);
            FENCE_ASYNC();
            const int cn = c + G_NSTAGE;
            const uint32_t mb = sbase + 8 + 8 * s;
            const uint32_t st = stage0 + s * G_STAGE;
            MBAR_EXPECT_TX(mb, G_STAGE);
            bulk_g2s(st + 0,     pA + (size_t)cn * 16384, 16384, mb);
            bulk_g2s(st + 16384, pB + (size_t)cn * 16384, 16384, mb);
        }
    }

    const int lr = l >> 2;
    const int lc = (l & 3) * 2;

    if constexpr (MODE == 0) {
#pragma unroll
        for (int m16 = 0; m16 < 4; m16++) {
            const size_t r0 = (size_t)(mt * 128 + mrow + m16 * 16 + lr);
            float* c0p = C + r0 * N;
            float* c1p = c0p + (size_t)8 * N;
#pragma unroll
            for (int n8 = 0; n8 < 4; n8++) {
                const int col = nt * 128 + ncol + n8 * 8 + lc;
                const float bx = bias[col], by = bias[col + 1];
                float2 v0 = make_float2(acc[m16][n8][0] + bx, acc[m16][n8][1] + by);
                float2 v1 = make_float2(acc[m16][n8][2] + bx, acc[m16][n8][3] + by);
                *(float2*)(c0p + col) = v0;
                *(float2*)(c1p + col) = v1;
            }
        }
    } else {
        const int b_ = mt >> 4;
        const int qt_ = mt & 15;
        if (nt < 16) {
            // Q (nt<8, scaled) or K (nt in [8,16)): two heads per 128-col tile
            const bool isQ = (nt < 8);
            __half* oh = isQ ? oQ : oK;
            const float scale = isQ ? (0.125f * LOG2E) : 1.0f;
            const int nth = isQ ? nt : nt - 8;
#pragma unroll
            for (int m16 = 0; m16 < 4; m16++) {
                const int rl0 = mrow + m16 * 16 + lr;
#pragma unroll
                for (int n8 = 0; n8 < 4; n8++) {
                    const int cl = ncol + n8 * 8 + lc;
                    const int hh2 = cl >> 6;
                    const int d = cl & 63;
                    const float bx = bias[nt * 128 + cl];
                    const float by = bias[nt * 128 + cl + 1];
                    const size_t tb = ((size_t)(b_ * HH + 2 * nth + hh2) * 16 + qt_) * 8192;
                    char* th = (char*)(oh + tb);
                    const uint32_t h0 = packh2((acc[m16][n8][0] + bx) * scale,
                                               (acc[m16][n8][1] + by) * scale);
                    const uint32_t off0 = SWZ128((uint32_t)(rl0 * 128 + d * 2));
                    *(uint32_t*)(th + off0) = h0;
                    const uint32_t h1 = packh2((acc[m16][n8][2] + bx) * scale,
                                               (acc[m16][n8][3] + by) * scale);
                    const uint32_t off1 = SWZ128((uint32_t)((rl0 + 8) * 128 + d * 2));
                    *(uint32_t*)(th + off1) = h1;
                }
            }
        } else {
            // V: transpose through smem (stages free: 97 KB >= 66 KB), write V^T
            float* sf = (float*)(smem + 1024);   // [128][129] fp32
            __syncthreads();
#pragma unroll
            for (int m16 = 0; m16 < 4; m16++) {
                const int rl0 = mrow + m16 * 16 + lr;
#pragma unroll
                for (int n8 = 0; n8 < 4; n8++) {
                    const int cl = ncol + n8 * 8 + lc;
                    const float bx = bias[nt * 128 + cl];
                    const float by = bias[nt * 128 + cl + 1];
                    sf[rl0 * 129 + cl]           = acc[m16][n8][0] + bx;
                    sf[rl0 * 129 + cl + 1]       = acc[m16][n8][1] + by;
                    sf[(rl0 + 8) * 129 + cl]     = acc[m16][n8][2] + bx;
                    sf[(rl0 + 8) * 129 + cl + 1] = acc[m16][n8][3] + by;
                }
            }
            __syncthreads();
            const int ntv = nt - 16;   // 0..7, two heads each
            for (int it = tid; it < 2048; it += 256) {
                const int hh2 = it >> 10;
                const int rem = it & 1023;
                const int kt2loc = rem >> 9;
                const int d = (rem >> 3) & 63;
                const int oct = rem & 7;
                __align__(16) __half h8[8];
#pragma unroll
                for (int e = 0; e < 8; e++) {
                    const int key = kt2loc * 64 + oct * 8 + e;
                    h8[e] = __float2half_rn(sf[key * 129 + hh2 * 64 + d]);
                }
                const size_t tb =
                    ((size_t)(b_ * HH + 2 * ntv + hh2) * 32 + qt_ * 2 + kt2loc) * 4096;
                const uint32_t off = SWZ128((uint32_t)(d * 128 + oct * 16));
                *(uint4*)((char*)(oV + tb) + off) = *(const uint4*)h8;
            }
        }
    }
}

// ---------------------------------------------------------------------------
// PERSISTENT flash attention (fp16), 6-stage K/V pipeline, snake schedule.
// Softmax: ex2.approx.f16x2 (half MUFU count); l via ones-vector MMA.
// ---------------------------------------------------------------------------
#define ATT_STAGE 32768u        // K 16K | V 16K
#define A_NSTAGE 6
#define ATT_SMEM  (1024u + 16384u + A_NSTAGE * ATT_STAGE)
#define NJOBS 1024
#define ONESH2 0x3C003C00u      // half2(1.0, 1.0)

__global__ __launch_bounds__(256) void flash_mma_kernel(
    const __half* __restrict__ Q_, const __half* __restrict__ K_,
    const __half* __restrict__ V_, __half* __restrict__ oY)
{
    extern __shared__ __align__(1024) char smem[];
    const uint32_t sbase = smem_u32(smem);
    const int tid = threadIdx.x;
    const int worker = (int)blockIdx.x;

    const uint32_t mbq = sbase + 8;
    const uint32_t sQ = sbase + 1024;
    const uint32_t stage0 = sQ + 16384;

    const int w = tid >> 5, l = tid & 31;
    const int mat = l >> 3, rin = l & 7;
    const int a_row_off = rin + ((mat & 1) << 3);
    const int a_kb_off  = (mat >> 1) << 4;
    const int b_row_off = rin + ((mat >> 1) << 3);
    const int b_kb_off  = (mat & 1) << 4;
    const int lr = l >> 2, qp = l & 3;

    const uint32_t ones[2] = {ONESH2, ONESH2};

    for (int p = 0;; p++) {
        const int rank = p * NWORK + ((p & 1) ? (NWORK - 1 - worker) : worker);
        if (rank >= NJOBS) break;
        const int qt = 15 - (rank >> 6);
        const int bh_idx = rank & 63;
        const int b = bh_idx >> 4;
        const int h = bh_idx & 15;

        if (tid == 0) {
            MBAR_INIT(mbq, 1);
#pragma unroll
            for (int s = 0; s < A_NSTAGE; s++) {
                MBAR_INIT(sbase + 16 + 8 * s, 1);
                MBAR_INIT(sbase + 80 + 8 * s, 256);
            }
        }
        __syncthreads();

        const char* pQ = (const char*)(Q_ + ((size_t)bh_idx * 16 + qt) * 8192);
        const char* pK = (const char*)(K_ + (size_t)bh_idx * 16 * 8192);
        const char* pV = (const char*)(V_ + (size_t)bh_idx * 32 * 4096);

        const int ntiles = qt + 1;

        if (tid == 0) {
            MBAR_EXPECT_TX(mbq, 16384);
            bulk_g2s(sQ, pQ, 16384, mbq);
            const int npro = ntiles < A_NSTAGE ? ntiles : A_NSTAGE;
            for (int c = 0; c < npro; c++) {
                uint32_t st = stage0 + c * ATT_STAGE;
                uint32_t mb = sbase + 16 + 8 * c;
                MBAR_EXPECT_TX(mb, ATT_STAGE);
                bulk_g2s(st + 0,     pK + (size_t)c * 16384, 16384, mb);
                bulk_g2s(st + 16384, pV + (size_t)c * 16384, 16384, mb);
            }
        }

        // Q fragments (persist for the job)
        mbar_wait(mbq, 0);
        uint32_t qf[4][4];
#pragma unroll
        for (int ks = 0; ks < 4; ks++) {
            int row = w * 16 + a_row_off;
            uint32_t off = (uint32_t)(row * 128) +
                           (uint32_t)((ks * 32 + a_kb_off) ^ ((row & 7) << 4));
            ldsm_x4(qf[ks][0], qf[ks][1], qf[ks][2], qf[ks][3], sQ + off);
        }

        float acc_o[8][4];
#pragma unroll
        for (int j = 0; j < 8; j++)
#pragma unroll
            for (int e = 0; e < 4; e++) acc_o[j][e] = 0.f;
        float acc_l[4] = {0.f, 0.f, 0.f, 0.f};
        float m0 = -1e30f, m1 = -1e30f;

        for (int kt = 0; kt < ntiles; kt++) {
            const int s = kt % A_NSTAGE;
            const uint32_t phs = (uint32_t)((kt / A_NSTAGE) & 1);
            mbar_wait(sbase + 16 + 8 * s, phs);
            const uint32_t stK = stage0 + s * ATT_STAGE;
            const uint32_t stV = stK + 16384;

            // --- S = Q K^T (fp16), log2 units
            float acc_s[16][4];
#pragma unroll
            for (int j = 0; j < 16; j++)
#pragma unroll
                for (int e = 0; e < 4; e++) acc_s[j][e] = 0.f;

#pragma unroll
            for (int ks = 0; ks < 4; ks++) {
                const uint32_t kb = (uint32_t)(ks * 32 + b_kb_off);
#pragma unroll
                for (int g = 0; g < 8; g++) {
                    int row = g * 16 + b_row_off;
                    uint32_t off = (uint32_t)(row * 128) + (kb ^ (uint32_t)((row & 7) << 4));
                    uint32_t kf[4];
                    ldsm_x4(kf[0], kf[1], kf[2], kf[3], stK + off);
                    mma_f16(acc_s[2 * g],     qf[ks], kf);
                    mma_f16(acc_s[2 * g + 1], qf[ks], kf + 2);
                }
            }

            // --- causal mask on the diagonal tile
            if (kt == qt) {
                const int rr0 = w * 16 + lr, rr1 = rr0 + 8;
#pragma unroll
                for (int j = 0; j < 16; j++) {
                    const int c0 = j * 8 + qp * 2;
                    if (c0     > rr0) acc_s[j][0] = -1e30f;
                    if (c0 + 1 > rr0) acc_s[j][1] = -1e30f;
                    if (c0     > rr1) acc_s[j][2] = -1e30f;
                    if (c0 + 1 > rr1) acc_s[j][3] = -1e30f;
                }
            }

            // --- online softmax (base-2)
            float t0 = -1e30f, t1 = -1e30f;
#pragma unroll
            for (int j = 0; j < 16; j++) {
                t0 = fmaxf(t0, fmaxf(acc_s[j][0], acc_s[j][1]));
                t1 = fmaxf(t1, fmaxf(acc_s[j][2], acc_s[j][3]));
            }
            t0 = fmaxf(t0, __shfl_xor_sync(0xffffffffu, t0, 1));
            t0 = fmaxf(t0, __shfl_xor_sync(0xffffffffu, t0, 2));
            t1 = fmaxf(t1, __shfl_xor_sync(0xffffffffu, t1, 1));
            t1 = fmaxf(t1, __shfl_xor_sync(0xffffffffu, t1, 2));

            const float mn0 = fmaxf(m0, t0);
            const float mn1 = fmaxf(m1, t1);
            const float cr0 = ex2(m0 - mn0);
            const float cr1 = ex2(m1 - mn1);
            m0 = mn0; m1 = mn1;
            acc_l[0] *= cr0; acc_l[1] *= cr0;
            acc_l[2] *= cr1; acc_l[3] *= cr1;
#pragma unroll
            for (int j = 0; j < 8; j++) {
                acc_o[j][0] *= cr0; acc_o[j][1] *= cr0;
                acc_o[j][2] *= cr1; acc_o[j][3] *= cr1;
            }

            // --- interleaved: f16x2 exp -> P frag; l += P@1 (ones MMA); PV MMAs
#pragma unroll
            for (int kc = 0; kc < 8; kc++) {
                uint32_t pf[4];
#pragma unroll
                for (int jj = 0; jj < 2; jj++) {
                    const int j = 2 * kc + jj;
                    pf[jj * 2 + 0] = ex2h2(packh2(acc_s[j][0] - mn0, acc_s[j][1] - mn0));
                    pf[jj * 2 + 1] = ex2h2(packh2(acc_s[j][2] - mn1, acc_s[j][3] - mn1));
                }
                mma_f16(acc_l, pf, ones);   // row-sum of P -> l accum

                const uint32_t vb = stV + ((kc < 4) ? 0u : 8192u);
                const uint32_t kb = (uint32_t)((kc & 3) * 32 + b_kb_off);
#pragma unroll
                for (int g = 0; g < 4; g++) {
                    int row = g * 16 + b_row_off;
                    uint32_t off = (uint32_t)(row * 128) + (kb ^ (uint32_t)((row & 7) << 4));
                    uint32_t vf[4];
                    ldsm_x4(vf[0], vf[1], vf[2], vf[3], vb + off);
                    mma_f16(acc_o[2 * g],     pf, vf);
                    mma_f16(acc_o[2 * g + 1], pf, vf + 2);
                }
            }

            MBAR_ARRIVE(sbase + 80 + 8 * s);

            if (tid == 0 && kt + A_NSTAGE < ntiles) {
                mbar_wait(sbase + 80 + 8 * s, phs);
                FENCE_ASYNC();
                const int cn = kt + A_NSTAGE;
                const uint32_t mb = sbase + 16 + 8 * s;
                const uint32_t st = stage0 + s * ATT_STAGE;
                MBAR_EXPECT_TX(mb, ATT_STAGE);
                bulk_g2s(st + 0,     pK + (size_t)cn * 16384, 16384, mb);
                bulk_g2s(st + 16384, pV + (size_t)cn * 16384, 16384, mb);
            }
        }

        // --- epilogue: l comes straight from the ones-MMA accumulator
        const float inv0 = 1.f / acc_l[0];
        const float inv1 = 1.f / acc_l[2];

        const size_t tb = ((size_t)(b * 16 + qt) * NKC + h) * 8192;
        char* th = (char*)(oY + tb);
        const int rl0 = w * 16 + lr;
#pragma unroll
        for (int j = 0; j < 8; j++) {
            const int dc = j * 8 + qp * 2;
            const uint32_t h0 = packh2(acc_o[j][0] * inv0, acc_o[j][1] * inv0);
            const uint32_t off0 = SWZ128((uint32_t)(rl0 * 128 + dc * 2));
            *(uint32_t*)(th + off0) = h0;
            const uint32_t h1 = packh2(acc_o[j][2] * inv1, acc_o[j][3] * inv1);
            const uint32_t off1 = SWZ128((uint32_t)((rl0 + 8) * 128 + dc * 2));
            *(uint32_t*)(th + off1) = h1;
        }

        __syncthreads();   // all threads done with smem/barriers before next job
    }
}

// ---------------------------------------------------------------------------
// Launch
// ---------------------------------------------------------------------------
extern "C" void kernel_launch(void* const* d_in, const int* in_sizes, int n_in,
                              void* d_out, int out_size)
{
    const float* x     = (const float*)d_in[0];
    const float* Wqkv  = (const float*)d_in[1];
    const float* bqkv  = (const float*)d_in[2];
    const float* Wproj = (const float*)d_in[3];
    const float* bproj = (const float*)d_in[4];
    float* out = (float*)d_out;

    __half *x16, *y16, *wq16, *wp16, *q16, *k16, *v16;
    cudaGetSymbolAddress((void**)&x16, g_x16);
    cudaGetSymbolAddress((void**)&y16, g_y16);
    cudaGetSymbolAddress((void**)&wq16, g_wqkv16);
    cudaGetSymbolAddress((void**)&wp16, g_wproj16);
    cudaGetSymbolAddress((void**)&q16, g_q16);
    cudaGetSymbolAddress((void**)&k16, g_k16);
    cudaGetSymbolAddress((void**)&v16, g_v16);

    cudaFuncSetAttribute(gemm_mma_kernel<0>,
                         cudaFuncAttributeMaxDynamicSharedMemorySize, GEMM_SMEM);
    cudaFuncSetAttribute(gemm_mma_kernel<1>,
                         cudaFuncAttributeMaxDynamicSharedMemorySize, GEMM_SMEM);
    cudaFuncSetAttribute(flash_mma_kernel,
                         cudaFuncAttributeMaxDynamicSharedMemorySize, ATT_SMEM);

    // Combined prep (x + both weight transposes, fp16)
    prep_all_kernel<<<1536, 256>>>(x, x16, Wqkv, wq16, Wproj, wp16);

    // QKV GEMM with fused Q/K/V-tile epilogue (Q pre-scaled for exp2 softmax)
    gemm_mma_kernel<1><<<dim3(N_QKV / 128, MTOK / 128), 256, GEMM_SMEM>>>(
        x16, wq16, bqkv, nullptr, N_QKV, q16, k16, v16);

    // Persistent flash attention (static snake-balanced schedule)
    flash_mma_kernel<<<NWORK, 256, ATT_SMEM>>>(q16, k16, v16, y16);

    // Proj GEMM: out = y @ Wproj + bproj (fp32 epilogue)
    gemm_mma_kernel<0><<<dim3(CC / 128, MTOK / 128), 256, GEMM_SMEM>>>(
        y16, wp16, bproj, out, CC, nullptr, nullptr, nullptr);
}